// round 1
// baseline (speedup 1.0000x reference)
#include <cuda_runtime.h>

// Problem constants
#define BB 2
#define TT 2048
#define DD 1024
#define HH 16
#define DH 64
#define MROWS (BB * TT)          // 4096
#define KQV_LD (3 * DD)          // 3072

// Scratch (device globals — no allocation allowed)
__device__ float g_kqv[(size_t)MROWS * 3 * DD];   // [4096, 3072]
__device__ float g_ao [(size_t)MROWS * DD];       // [4096, 1024]

// ---------------------------------------------------------------------------
// Tiled SGEMM with bias: C[M,N] = A[M,K] @ B[K,N] + bias[N]
// BM=BN=128, BK=8, 256 threads, 8x8 per-thread tile.
// ---------------------------------------------------------------------------
__global__ __launch_bounds__(256) void sgemm_bias_kernel(
    const float* __restrict__ A, const float* __restrict__ B,
    const float* __restrict__ bias, float* __restrict__ C,
    int M, int N, int K)
{
    const int BM = 128, BN = 128, BK = 8;
    __shared__ float As[BK][BM];   // A stored transposed: As[k][m]
    __shared__ float Bs[BK][BN];

    const int tid = threadIdx.x;
    const int m0 = blockIdx.y * BM;
    const int n0 = blockIdx.x * BN;

    const int tx = tid % 16;
    const int ty = tid / 16;
    const int tr = ty * 8;   // row offset within tile
    const int tc = tx * 8;   // col offset within tile

    // Load mapping
    const int a_row = tid / 2;            // 0..127
    const int a_col = (tid % 2) * 4;      // 0 or 4
    const int b_row = tid / 32;           // 0..7
    const int b_col = (tid % 32) * 4;     // 0..124

    const float* Aptr = A + (size_t)(m0 + a_row) * K + a_col;
    const float* Bptr = B + (size_t)b_row * N + n0 + b_col;

    float acc[8][8];
#pragma unroll
    for (int i = 0; i < 8; i++)
#pragma unroll
        for (int j = 0; j < 8; j++) acc[i][j] = 0.f;

    for (int k0 = 0; k0 < K; k0 += BK) {
        float4 av = *(const float4*)(Aptr + k0);
        float4 bv = *(const float4*)(Bptr + (size_t)k0 * N);
        As[a_col + 0][a_row] = av.x;
        As[a_col + 1][a_row] = av.y;
        As[a_col + 2][a_row] = av.z;
        As[a_col + 3][a_row] = av.w;
        *(float4*)&Bs[b_row][b_col] = bv;
        __syncthreads();

        float ra[8], rb[8];
#pragma unroll
        for (int kk = 0; kk < BK; kk++) {
            *(float4*)&ra[0] = *(const float4*)&As[kk][tr];
            *(float4*)&ra[4] = *(const float4*)&As[kk][tr + 4];
            *(float4*)&rb[0] = *(const float4*)&Bs[kk][tc];
            *(float4*)&rb[4] = *(const float4*)&Bs[kk][tc + 4];
#pragma unroll
            for (int i = 0; i < 8; i++)
#pragma unroll
                for (int j = 0; j < 8; j++)
                    acc[i][j] += ra[i] * rb[j];
        }
        __syncthreads();
    }

#pragma unroll
    for (int i = 0; i < 8; i++) {
        const size_t m = m0 + tr + i;
#pragma unroll
        for (int j = 0; j < 8; j += 4) {
            const int n = n0 + tc + j;
            float4 o;
            o.x = acc[i][j + 0] + bias[n + 0];
            o.y = acc[i][j + 1] + bias[n + 1];
            o.z = acc[i][j + 2] + bias[n + 2];
            o.w = acc[i][j + 3] + bias[n + 3];
            *(float4*)&C[m * N + n] = o;
        }
    }
}

// ---------------------------------------------------------------------------
// Causal retention attention (no softmax):
//   per (b, h): O = tril(Q @ K^T) @ V
// Q/K/V live inside g_kqv at [b, t, {K:0 | Q:1024 | V:2048} + h*64 .. +64).
// Each block: 64 q-rows x 64 dh-cols of O, loops over k-tiles <= q-tile.
// Shared tiles stored transposed (d-major) so the hot loops use float4 LDS.
// ---------------------------------------------------------------------------
#define PITCH 68
#define ATT_SMEM (3 * 64 * PITCH * 4)

__global__ __launch_bounds__(256) void attn_kernel(
    const float* __restrict__ kqv, float* __restrict__ ao)
{
    extern __shared__ float smem[];
    float (*QsT)[PITCH] = (float(*)[PITCH])(smem);                 // QsT[d][r]
    float (*KVs)[PITCH] = (float(*)[PITCH])(smem + 64 * PITCH);    // KsT[d][c] then Vs[k][d]
    float (*SsT)[PITCH] = (float(*)[PITCH])(smem + 2 * 64 * PITCH);// SsT[k][r]

    const int tid = threadIdx.x;
    const int qb = blockIdx.x;
    const int h  = blockIdx.y;
    const int b  = blockIdx.z;
    const int q0 = qb * 64;

    const float* base = kqv + (size_t)b * TT * KQV_LD;
    const float* Kg = base + 0      + h * DH;
    const float* Qg = base + DD     + h * DH;
    const float* Vg = base + 2 * DD + h * DH;

    // Load Q tile transposed: QsT[d][r] = Q[q0+r][d]
    for (int e = tid; e < 1024; e += 256) {
        const int r = e / 16, c4 = (e % 16) * 4;
        float4 v = *(const float4*)(Qg + (size_t)(q0 + r) * KQV_LD + c4);
        QsT[c4 + 0][r] = v.x; QsT[c4 + 1][r] = v.y;
        QsT[c4 + 2][r] = v.z; QsT[c4 + 3][r] = v.w;
    }

    const int tx = tid % 16, ty = tid / 16;
    const int r0 = ty * 4, c0 = tx * 4;

    float acc[4][4];
#pragma unroll
    for (int i = 0; i < 4; i++)
#pragma unroll
        for (int j = 0; j < 4; j++) acc[i][j] = 0.f;

    for (int kb = 0; kb <= qb; kb++) {
        const int k0 = kb * 64;
        __syncthreads();   // prior V reads done (and Q load on first iter)

        // Load K tile transposed: KVs[d][c] = K[k0+c][d]
        for (int e = tid; e < 1024; e += 256) {
            const int r = e / 16, c4 = (e % 16) * 4;
            float4 v = *(const float4*)(Kg + (size_t)(k0 + r) * KQV_LD + c4);
            KVs[c4 + 0][r] = v.x; KVs[c4 + 1][r] = v.y;
            KVs[c4 + 2][r] = v.z; KVs[c4 + 3][r] = v.w;
        }
        __syncthreads();

        // S[r][c] = sum_d Q[r][d] * K[c][d]
        float s[4][4];
#pragma unroll
        for (int i = 0; i < 4; i++)
#pragma unroll
            for (int j = 0; j < 4; j++) s[i][j] = 0.f;

#pragma unroll 8
        for (int d = 0; d < 64; d++) {
            float4 q = *(const float4*)&QsT[d][r0];
            float4 k = *(const float4*)&KVs[d][c0];
            s[0][0] += q.x * k.x; s[0][1] += q.x * k.y; s[0][2] += q.x * k.z; s[0][3] += q.x * k.w;
            s[1][0] += q.y * k.x; s[1][1] += q.y * k.y; s[1][2] += q.y * k.z; s[1][3] += q.y * k.w;
            s[2][0] += q.z * k.x; s[2][1] += q.z * k.y; s[2][2] += q.z * k.z; s[2][3] += q.z * k.w;
            s[3][0] += q.w * k.x; s[3][1] += q.w * k.y; s[3][2] += q.w * k.z; s[3][3] += q.w * k.w;
        }

        // Causal mask on the diagonal block
        if (kb == qb) {
#pragma unroll
            for (int i = 0; i < 4; i++)
#pragma unroll
                for (int j = 0; j < 4; j++)
                    if (c0 + j > r0 + i) s[i][j] = 0.f;
        }

        // Store S transposed: SsT[c][r]
#pragma unroll
        for (int i = 0; i < 4; i++)
#pragma unroll
            for (int j = 0; j < 4; j++)
                SsT[c0 + j][r0 + i] = s[i][j];
        __syncthreads();   // S visible; K reads done before overwrite

        // Load V tile natural: KVs[k][d] = V[k0+k][d]
        for (int e = tid; e < 1024; e += 256) {
            const int r = e / 16, c4 = (e % 16) * 4;
            float4 v = *(const float4*)(Vg + (size_t)(k0 + r) * KQV_LD + c4);
            *(float4*)&KVs[r][c4] = v;
        }
        __syncthreads();

        // O[r][c] += sum_k S[r][k] * V[k][c]
#pragma unroll 8
        for (int kk = 0; kk < 64; kk++) {
            float4 sv = *(const float4*)&SsT[kk][r0];
            float4 vv = *(const float4*)&KVs[kk][c0];
            acc[0][0] += sv.x * vv.x; acc[0][1] += sv.x * vv.y; acc[0][2] += sv.x * vv.z; acc[0][3] += sv.x * vv.w;
            acc[1][0] += sv.y * vv.x; acc[1][1] += sv.y * vv.y; acc[1][2] += sv.y * vv.z; acc[1][3] += sv.y * vv.w;
            acc[2][0] += sv.z * vv.x; acc[2][1] += sv.z * vv.y; acc[2][2] += sv.z * vv.z; acc[2][3] += sv.z * vv.w;
            acc[3][0] += sv.w * vv.x; acc[3][1] += sv.w * vv.y; acc[3][2] += sv.w * vv.z; acc[3][3] += sv.w * vv.w;
        }
    }

    // Write O to [b, t, h*64 + c]
#pragma unroll
    for (int i = 0; i < 4; i++) {
        const size_t t = (size_t)b * TT + q0 + r0 + i;
        float4 o;
        o.x = acc[i][0]; o.y = acc[i][1]; o.z = acc[i][2]; o.w = acc[i][3];
        *(float4*)&ao[t * DD + h * DH + c0] = o;
    }
}

// ---------------------------------------------------------------------------
extern "C" void kernel_launch(void* const* d_in, const int* in_sizes, int n_in,
                              void* d_out, int out_size)
{
    const float* x  = (const float*)d_in[0];
    const float* W1 = (const float*)d_in[1];
    const float* b1 = (const float*)d_in[2];
    const float* W2 = (const float*)d_in[3];
    const float* b2 = (const float*)d_in[4];
    float* out = (float*)d_out;

    float* kqv; cudaGetSymbolAddress((void**)&kqv, g_kqv);
    float* ao;  cudaGetSymbolAddress((void**)&ao,  g_ao);

    cudaFuncSetAttribute(attn_kernel,
                         cudaFuncAttributeMaxDynamicSharedMemorySize, ATT_SMEM);

    // 1) kqv = x @ W1 + b1      [4096,1024]@[1024,3072]
    {
        dim3 grid(3 * DD / 128, MROWS / 128);
        sgemm_bias_kernel<<<grid, 256>>>(x, W1, b1, kqv, MROWS, 3 * DD, DD);
    }
    // 2) causal retention attention
    {
        dim3 grid(TT / 64, HH, BB);
        attn_kernel<<<grid, 256, ATT_SMEM>>>(kqv, ao);
    }
    // 3) out = ao @ W2 + b2     [4096,1024]@[1024,1024]
    {
        dim3 grid(DD / 128, MROWS / 128);
        sgemm_bias_kernel<<<grid, 256>>>(ao, W2, b2, out, MROWS, DD, DD);
    }
}

// round 2
// speedup vs baseline: 1.2375x; 1.2375x over previous
#include <cuda_runtime.h>
#include <cuda_bf16.h>

#define BB 2
#define TT 2048
#define DD 1024
#define HH 16
#define DH 64
#define MROWS (BB*TT)
#define KQV_LD (3*DD)

__device__ float g_kqv[(size_t)MROWS * KQV_LD];
__device__ float g_ao [(size_t)MROWS * DD];

// ---------------------------------------------------------------------------
// helpers
// ---------------------------------------------------------------------------
__device__ __forceinline__ unsigned bf2_pack(__nv_bfloat16 a, __nv_bfloat16 b) {
    __nv_bfloat162 t = __halves2bfloat162(a, b);
    return *reinterpret_cast<unsigned*>(&t);
}
// split two floats into packed hi / packed lo bf16x2
__device__ __forceinline__ void split_pack2(float x, float y, unsigned &hi, unsigned &lo) {
    __nv_bfloat16 hx = __float2bfloat16_rn(x), hy = __float2bfloat16_rn(y);
    __nv_bfloat16 lx = __float2bfloat16_rn(x - __bfloat162float(hx));
    __nv_bfloat16 ly = __float2bfloat16_rn(y - __bfloat162float(hy));
    hi = bf2_pack(hx, hy);
    lo = bf2_pack(lx, ly);
}
__device__ __forceinline__ void mma16816(float* c,
    unsigned a0, unsigned a1, unsigned a2, unsigned a3,
    unsigned b0, unsigned b1)
{
    asm volatile(
        "mma.sync.aligned.m16n8k16.row.col.f32.bf16.bf16.f32 "
        "{%0,%1,%2,%3},{%4,%5,%6,%7},{%8,%9},{%0,%1,%2,%3};\n"
        : "+f"(c[0]), "+f"(c[1]), "+f"(c[2]), "+f"(c[3])
        : "r"(a0), "r"(a1), "r"(a2), "r"(a3), "r"(b0), "r"(b1));
}
#define U32(arr, idx) (*reinterpret_cast<const unsigned*>(&(arr)[idx]))

// ---------------------------------------------------------------------------
// GEMM: C[M,N] = A[M,K] @ B[K,N] + bias, bf16-split (3 MMA) tensor-core path.
// Block 128x128, BK=32, 256 threads (8 warps as 2x4), warp tile 64x32.
// ---------------------------------------------------------------------------
#define GP 40   // smem pitch (bf16 elems) for 32-wide k — conflict-free

__global__ __launch_bounds__(256, 1) void gemm_mma(
    const float* __restrict__ A, const float* __restrict__ Bm,
    const float* __restrict__ bias, float* __restrict__ C,
    int M, int N, int K)
{
    __shared__ __nv_bfloat16 Ah[128 * GP], Al[128 * GP];
    __shared__ __nv_bfloat16 Bh[128 * GP], Bl[128 * GP];

    const int tid = threadIdx.x, warp = tid >> 5, lane = tid & 31;
    const int g = lane >> 2, tg = lane & 3;
    const int m0 = blockIdx.y * 128, n0 = blockIdx.x * 128;
    const int wm = (warp & 1) * 64, wn = (warp >> 1) * 32;

    // global load mapping
    const int ar = tid >> 3, ac = (tid & 7) * 4;     // A tile: rows ar+32i, cols ac..ac+3
    const int br = tid >> 5, bc = (tid & 31) * 4;    // B tile: rows br+8i,  cols bc..bc+3

    float acc[4][4][4];
#pragma unroll
    for (int i = 0; i < 4; i++)
#pragma unroll
        for (int j = 0; j < 4; j++)
#pragma unroll
            for (int l = 0; l < 4; l++) acc[i][j][l] = 0.f;

    float4 pa[4], pb[4];
#pragma unroll
    for (int i = 0; i < 4; i++) {
        pa[i] = *reinterpret_cast<const float4*>(&A[(size_t)(m0 + ar + 32 * i) * K + ac]);
        pb[i] = *reinterpret_cast<const float4*>(&Bm[(size_t)(br + 8 * i) * N + n0 + bc]);
    }

    for (int k0 = 0; k0 < K; k0 += 32) {
        // store current tiles to smem (split hi/lo)
#pragma unroll
        for (int i = 0; i < 4; i++) {
            unsigned h0, h1, l0, l1;
            split_pack2(pa[i].x, pa[i].y, h0, l0);
            split_pack2(pa[i].z, pa[i].w, h1, l1);
            const int aidx = (ar + 32 * i) * GP + ac;
            *reinterpret_cast<uint2*>(&Ah[aidx]) = make_uint2(h0, h1);
            *reinterpret_cast<uint2*>(&Al[aidx]) = make_uint2(l0, l1);

            const int krow = br + 8 * i;
            float b4[4] = {pb[i].x, pb[i].y, pb[i].z, pb[i].w};
#pragma unroll
            for (int j = 0; j < 4; j++) {
                __nv_bfloat16 hh = __float2bfloat16_rn(b4[j]);
                __nv_bfloat16 ll = __float2bfloat16_rn(b4[j] - __bfloat162float(hh));
                Bh[(bc + j) * GP + krow] = hh;   // B stored transposed: [n][k]
                Bl[(bc + j) * GP + krow] = ll;
            }
        }
        __syncthreads();

        // prefetch next tiles (hidden under MMA work)
        if (k0 + 32 < K) {
#pragma unroll
            for (int i = 0; i < 4; i++) {
                pa[i] = *reinterpret_cast<const float4*>(&A[(size_t)(m0 + ar + 32 * i) * K + k0 + 32 + ac]);
                pb[i] = *reinterpret_cast<const float4*>(&Bm[(size_t)(k0 + 32 + br + 8 * i) * N + n0 + bc]);
            }
        }

#pragma unroll
        for (int ks = 0; ks < 32; ks += 16) {
            unsigned bhf[4][2], blf[4][2];
#pragma unroll
            for (int nt = 0; nt < 4; nt++) {
                const int c = (wn + nt * 8 + g) * GP + ks + tg * 2;
                bhf[nt][0] = U32(Bh, c); bhf[nt][1] = U32(Bh, c + 8);
                blf[nt][0] = U32(Bl, c); blf[nt][1] = U32(Bl, c + 8);
            }
#pragma unroll
            for (int mt = 0; mt < 4; mt++) {
                const int r  = (wm + mt * 16 + g) * GP + ks + tg * 2;
                const int r8 = r + 8 * GP;
                const unsigned ah0 = U32(Ah, r),     ah1 = U32(Ah, r8);
                const unsigned ah2 = U32(Ah, r + 8), ah3 = U32(Ah, r8 + 8);
                const unsigned al0 = U32(Al, r),     al1 = U32(Al, r8);
                const unsigned al2 = U32(Al, r + 8), al3 = U32(Al, r8 + 8);
#pragma unroll
                for (int nt = 0; nt < 4; nt++) {
                    mma16816(acc[mt][nt], ah0, ah1, ah2, ah3, bhf[nt][0], bhf[nt][1]);
                    mma16816(acc[mt][nt], ah0, ah1, ah2, ah3, blf[nt][0], blf[nt][1]);
                    mma16816(acc[mt][nt], al0, al1, al2, al3, bhf[nt][0], bhf[nt][1]);
                }
            }
        }
        __syncthreads();
    }

    // epilogue: + bias
#pragma unroll
    for (int mt = 0; mt < 4; mt++) {
        const int r = m0 + wm + mt * 16 + g;
#pragma unroll
        for (int nt = 0; nt < 4; nt++) {
            const int c = n0 + wn + nt * 8 + tg * 2;
            const float bx = bias[c], by = bias[c + 1];
            float2 o0 = {acc[mt][nt][0] + bx, acc[mt][nt][1] + by};
            float2 o1 = {acc[mt][nt][2] + bx, acc[mt][nt][3] + by};
            *reinterpret_cast<float2*>(&C[(size_t)r * N + c])       = o0;
            *reinterpret_cast<float2*>(&C[(size_t)(r + 8) * N + c]) = o1;
        }
    }
}

// ---------------------------------------------------------------------------
// Fused causal retention attention, bf16-split tensor cores.
// Per block: (b, h, 128 q-rows). Loop k-tiles of 64.
//   S = Q K^T (mask) -> smem bf16 hi/lo -> O += S V
// 8 warps as 2(q-half) x 4(16-wide n slice).
// ---------------------------------------------------------------------------
#define AP 72   // smem pitch (bf16 elems) for 64-wide rows — conflict-free
#define ATT_SMEM ((2*128*AP + 2*64*AP + 2*64*AP + 2*128*AP) * 2)  // 110592 B

__global__ __launch_bounds__(256, 1) void attn_mma(
    const float* __restrict__ kqv, float* __restrict__ ao)
{
    extern __shared__ __nv_bfloat16 sm[];
    __nv_bfloat16 *Qh = sm,            *Ql = Qh + 128 * AP;
    __nv_bfloat16 *Kh = Ql + 128 * AP, *Kl = Kh + 64 * AP;
    __nv_bfloat16 *Vh = Kl + 64 * AP,  *Vl = Vh + 64 * AP;
    __nv_bfloat16 *Sh = Vl + 64 * AP,  *Sl = Sh + 128 * AP;

    const int tid = threadIdx.x, warp = tid >> 5, lane = tid & 31;
    const int g = lane >> 2, tg = lane & 3;
    const int qb = gridDim.x - 1 - blockIdx.x;   // heavy tiles first
    const int h = blockIdx.y, b = blockIdx.z;
    const int q0 = qb * 128;

    const float* base = kqv + (size_t)b * TT * KQV_LD + h * DH;
    const float* Kg = base;
    const float* Qg = base + DD;
    const float* Vg = base + 2 * DD;

    // load Q tile 128x64 -> Qh/Ql [q][d]
    {
        const int qr = tid >> 4, qc = (tid & 15) * 4;
#pragma unroll
        for (int i = 0; i < 8; i++) {
            const int row = qr + 16 * i;
            float4 v = *reinterpret_cast<const float4*>(&Qg[(size_t)(q0 + row) * KQV_LD + qc]);
            unsigned h0, h1, l0, l1;
            split_pack2(v.x, v.y, h0, l0);
            split_pack2(v.z, v.w, h1, l1);
            const int idx = row * AP + qc;
            *reinterpret_cast<uint2*>(&Qh[idx]) = make_uint2(h0, h1);
            *reinterpret_cast<uint2*>(&Ql[idx]) = make_uint2(l0, l1);
        }
    }

    const int wq = (warp & 1) * 64;      // q offset of warp
    const int wk = (warp >> 1) * 16;     // k (S phase) / d (O phase) offset

    float oacc[4][2][4];
#pragma unroll
    for (int i = 0; i < 4; i++)
#pragma unroll
        for (int j = 0; j < 2; j++)
#pragma unroll
            for (int l = 0; l < 4; l++) oacc[i][j][l] = 0.f;

    const int kvr = tid >> 4, kvc = (tid & 15) * 4;
    const int nkb = 2 * qb + 2;

    for (int kb = 0; kb < nkb; kb++) {
        const int k0 = kb * 64;

        // prefetch K/V tile (overlaps previous iteration's O-mma)
        float4 kf[4], vf[4];
#pragma unroll
        for (int i = 0; i < 4; i++) {
            const int row = kvr + 16 * i;
            kf[i] = *reinterpret_cast<const float4*>(&Kg[(size_t)(k0 + row) * KQV_LD + kvc]);
            vf[i] = *reinterpret_cast<const float4*>(&Vg[(size_t)(k0 + row) * KQV_LD + kvc]);
        }
        __syncthreads();   // previous O-mma done reading Ss/Vs; Q ready (iter 0)

#pragma unroll
        for (int i = 0; i < 4; i++) {
            const int row = kvr + 16 * i;
            unsigned h0, h1, l0, l1;
            split_pack2(kf[i].x, kf[i].y, h0, l0);
            split_pack2(kf[i].z, kf[i].w, h1, l1);
            const int idx = row * AP + kvc;
            *reinterpret_cast<uint2*>(&Kh[idx]) = make_uint2(h0, h1);  // K: [k][d]
            *reinterpret_cast<uint2*>(&Kl[idx]) = make_uint2(l0, l1);
            float v4[4] = {vf[i].x, vf[i].y, vf[i].z, vf[i].w};
#pragma unroll
            for (int j = 0; j < 4; j++) {
                __nv_bfloat16 hh = __float2bfloat16_rn(v4[j]);
                __nv_bfloat16 ll = __float2bfloat16_rn(v4[j] - __bfloat162float(hh));
                Vh[(kvc + j) * AP + row] = hh;    // V transposed: [d][k]
                Vl[(kvc + j) * AP + row] = ll;
            }
        }
        __syncthreads();

        // ---- S = Q K^T (warp: 64q x 16k), accumulate fp32 ----
        float sacc[4][2][4];
#pragma unroll
        for (int i = 0; i < 4; i++)
#pragma unroll
            for (int j = 0; j < 2; j++)
#pragma unroll
                for (int l = 0; l < 4; l++) sacc[i][j][l] = 0.f;

#pragma unroll
        for (int ks = 0; ks < 64; ks += 16) {
            unsigned bhf[2][2], blf[2][2];
#pragma unroll
            for (int nt = 0; nt < 2; nt++) {
                const int c = (wk + nt * 8 + g) * AP + ks + tg * 2;
                bhf[nt][0] = U32(Kh, c); bhf[nt][1] = U32(Kh, c + 8);
                blf[nt][0] = U32(Kl, c); blf[nt][1] = U32(Kl, c + 8);
            }
#pragma unroll
            for (int mt = 0; mt < 4; mt++) {
                const int r  = (wq + mt * 16 + g) * AP + ks + tg * 2;
                const int r8 = r + 8 * AP;
                const unsigned ah0 = U32(Qh, r),     ah1 = U32(Qh, r8);
                const unsigned ah2 = U32(Qh, r + 8), ah3 = U32(Qh, r8 + 8);
                const unsigned al0 = U32(Ql, r),     al1 = U32(Ql, r8);
                const unsigned al2 = U32(Ql, r + 8), al3 = U32(Ql, r8 + 8);
#pragma unroll
                for (int nt = 0; nt < 2; nt++) {
                    mma16816(sacc[mt][nt], ah0, ah1, ah2, ah3, bhf[nt][0], bhf[nt][1]);
                    mma16816(sacc[mt][nt], ah0, ah1, ah2, ah3, blf[nt][0], blf[nt][1]);
                    mma16816(sacc[mt][nt], al0, al1, al2, al3, bhf[nt][0], bhf[nt][1]);
                }
            }
        }

        // mask (diagonal tiles only) + split-store S -> smem
        const bool diag = (kb >= 2 * qb);
#pragma unroll
        for (int mt = 0; mt < 4; mt++) {
            const int qr = wq + mt * 16 + g;       // local q row
#pragma unroll
            for (int nt = 0; nt < 2; nt++) {
                const int kc = wk + nt * 8 + tg * 2;  // local k col
                float s0 = sacc[mt][nt][0], s1 = sacc[mt][nt][1];
                float s2 = sacc[mt][nt][2], s3 = sacc[mt][nt][3];
                if (diag) {
                    const int qg0 = q0 + qr, qg8 = qg0 + 8, kg = k0 + kc;
                    if (kg     > qg0) s0 = 0.f;
                    if (kg + 1 > qg0) s1 = 0.f;
                    if (kg     > qg8) s2 = 0.f;
                    if (kg + 1 > qg8) s3 = 0.f;
                }
                unsigned h0, l0, h1, l1;
                split_pack2(s0, s1, h0, l0);
                split_pack2(s2, s3, h1, l1);
                const int idx = qr * AP + kc;
                *reinterpret_cast<unsigned*>(&Sh[idx])           = h0;
                *reinterpret_cast<unsigned*>(&Sl[idx])           = l0;
                *reinterpret_cast<unsigned*>(&Sh[idx + 8 * AP])  = h1;
                *reinterpret_cast<unsigned*>(&Sl[idx + 8 * AP])  = l1;
            }
        }
        __syncthreads();

        // ---- O += S V (warp: 64q x 16d) ----
#pragma unroll
        for (int ks = 0; ks < 64; ks += 16) {
            unsigned bhf[2][2], blf[2][2];
#pragma unroll
            for (int nt = 0; nt < 2; nt++) {
                const int c = (wk + nt * 8 + g) * AP + ks + tg * 2;
                bhf[nt][0] = U32(Vh, c); bhf[nt][1] = U32(Vh, c + 8);
                blf[nt][0] = U32(Vl, c); blf[nt][1] = U32(Vl, c + 8);
            }
#pragma unroll
            for (int mt = 0; mt < 4; mt++) {
                const int r  = (wq + mt * 16 + g) * AP + ks + tg * 2;
                const int r8 = r + 8 * AP;
                const unsigned ah0 = U32(Sh, r),     ah1 = U32(Sh, r8);
                const unsigned ah2 = U32(Sh, r + 8), ah3 = U32(Sh, r8 + 8);
                const unsigned al0 = U32(Sl, r),     al1 = U32(Sl, r8);
                const unsigned al2 = U32(Sl, r + 8), al3 = U32(Sl, r8 + 8);
#pragma unroll
                for (int nt = 0; nt < 2; nt++) {
                    mma16816(oacc[mt][nt], ah0, ah1, ah2, ah3, bhf[nt][0], bhf[nt][1]);
                    mma16816(oacc[mt][nt], ah0, ah1, ah2, ah3, blf[nt][0], blf[nt][1]);
                    mma16816(oacc[mt][nt], al0, al1, al2, al3, bhf[nt][0], bhf[nt][1]);
                }
            }
        }
    }

    // write O -> ao[b, t, h*64 + d]
#pragma unroll
    for (int mt = 0; mt < 4; mt++) {
        const int r = q0 + wq + mt * 16 + g;
        const size_t t = (size_t)b * TT + r;
#pragma unroll
        for (int nt = 0; nt < 2; nt++) {
            const int c = h * DH + wk + nt * 8 + tg * 2;
            float2 o0 = {oacc[mt][nt][0], oacc[mt][nt][1]};
            float2 o1 = {oacc[mt][nt][2], oacc[mt][nt][3]};
            *reinterpret_cast<float2*>(&ao[t * DD + c])       = o0;
            *reinterpret_cast<float2*>(&ao[(t + 8) * DD + c]) = o1;
        }
    }
}

// ---------------------------------------------------------------------------
extern "C" void kernel_launch(void* const* d_in, const int* in_sizes, int n_in,
                              void* d_out, int out_size)
{
    const float* x  = (const float*)d_in[0];
    const float* W1 = (const float*)d_in[1];
    const float* b1 = (const float*)d_in[2];
    const float* W2 = (const float*)d_in[3];
    const float* b2 = (const float*)d_in[4];
    float* out = (float*)d_out;

    float* kqv; cudaGetSymbolAddress((void**)&kqv, g_kqv);
    float* ao;  cudaGetSymbolAddress((void**)&ao,  g_ao);

    cudaFuncSetAttribute(attn_mma,
                         cudaFuncAttributeMaxDynamicSharedMemorySize, ATT_SMEM);

    // 1) kqv = x @ W1 + b1
    {
        dim3 grid(3 * DD / 128, MROWS / 128);
        gemm_mma<<<grid, 256>>>(x, W1, b1, kqv, MROWS, 3 * DD, DD);
    }
    // 2) causal retention attention
    {
        dim3 grid(TT / 128, HH, BB);
        attn_mma<<<grid, 256, ATT_SMEM>>>(kqv, ao);
    }
    // 3) out = ao @ W2 + b2
    {
        dim3 grid(DD / 128, MROWS / 128);
        gemm_mma<<<grid, 256>>>(ao, W2, b2, out, MROWS, DD, DD);
    }
}

// round 3
// speedup vs baseline: 2.2611x; 1.8271x over previous
#include <cuda_runtime.h>
#include <cuda_bf16.h>

#define BB 2
#define TT 2048
#define DD 1024
#define HH 16
#define DH 64
#define MROWS (BB*TT)
#define KQV_LD (3*DD)

// pre-split bf16 operands (device globals; allocation is forbidden)
__device__ __nv_bfloat16 g_xh [(size_t)MROWS*DD],    g_xl [(size_t)MROWS*DD];
__device__ __nv_bfloat16 g_w1h[(size_t)DD*3*DD],     g_w1l[(size_t)DD*3*DD];
__device__ __nv_bfloat16 g_w2h[(size_t)DD*DD],       g_w2l[(size_t)DD*DD];
__device__ __nv_bfloat16 g_kqvh[(size_t)MROWS*3*DD], g_kqvl[(size_t)MROWS*3*DD];
__device__ __nv_bfloat16 g_aoh[(size_t)MROWS*DD],    g_aol[(size_t)MROWS*DD];

// ---------------------------------------------------------------------------
// helpers
// ---------------------------------------------------------------------------
__device__ __forceinline__ unsigned bf2_pack(__nv_bfloat16 a, __nv_bfloat16 b) {
    __nv_bfloat162 t = __halves2bfloat162(a, b);
    return *reinterpret_cast<unsigned*>(&t);
}
__device__ __forceinline__ void split_pack2(float x, float y, unsigned &hi, unsigned &lo) {
    __nv_bfloat16 hx = __float2bfloat16_rn(x), hy = __float2bfloat16_rn(y);
    __nv_bfloat16 lx = __float2bfloat16_rn(x - __bfloat162float(hx));
    __nv_bfloat16 ly = __float2bfloat16_rn(y - __bfloat162float(hy));
    hi = bf2_pack(hx, hy);
    lo = bf2_pack(lx, ly);
}
__device__ __forceinline__ void mma16816(float* c,
    unsigned a0, unsigned a1, unsigned a2, unsigned a3,
    unsigned b0, unsigned b1)
{
    asm volatile(
        "mma.sync.aligned.m16n8k16.row.col.f32.bf16.bf16.f32 "
        "{%0,%1,%2,%3},{%4,%5,%6,%7},{%8,%9},{%0,%1,%2,%3};\n"
        : "+f"(c[0]), "+f"(c[1]), "+f"(c[2]), "+f"(c[3])
        : "r"(a0), "r"(a1), "r"(a2), "r"(a3), "r"(b0), "r"(b1));
}
__device__ __forceinline__ void ldsm4(unsigned* r, const void* p) {
    unsigned a = (unsigned)__cvta_generic_to_shared(p);
    asm volatile("ldmatrix.sync.aligned.m8n8.x4.shared.b16 {%0,%1,%2,%3}, [%4];\n"
        : "=r"(r[0]), "=r"(r[1]), "=r"(r[2]), "=r"(r[3]) : "r"(a));
}
__device__ __forceinline__ void ldsm4t(unsigned* r, const void* p) {
    unsigned a = (unsigned)__cvta_generic_to_shared(p);
    asm volatile("ldmatrix.sync.aligned.m8n8.x4.trans.shared.b16 {%0,%1,%2,%3}, [%4];\n"
        : "=r"(r[0]), "=r"(r[1]), "=r"(r[2]), "=r"(r[3]) : "r"(a));
}
__device__ __forceinline__ void cp16(void* sp, const void* gp) {
    unsigned s = (unsigned)__cvta_generic_to_shared(sp);
    asm volatile("cp.async.cg.shared.global [%0], [%1], 16;\n" :: "r"(s), "l"(gp));
}
#define CP_COMMIT() asm volatile("cp.async.commit_group;\n")
#define CP_WAIT0()  asm volatile("cp.async.wait_group 0;\n")

// ---------------------------------------------------------------------------
// split fp32 -> bf16 hi/lo (elementwise, n multiple of 4)
// ---------------------------------------------------------------------------
__global__ void split_kernel(const float* __restrict__ in,
                             __nv_bfloat16* __restrict__ hi,
                             __nv_bfloat16* __restrict__ lo, int n4)
{
    int i = blockIdx.x * blockDim.x + threadIdx.x;
    if (i >= n4) return;
    float4 v = reinterpret_cast<const float4*>(in)[i];
    unsigned h0, l0, h1, l1;
    split_pack2(v.x, v.y, h0, l0);
    split_pack2(v.z, v.w, h1, l1);
    reinterpret_cast<uint2*>(hi)[i] = make_uint2(h0, h1);
    reinterpret_cast<uint2*>(lo)[i] = make_uint2(l0, l1);
}

// ---------------------------------------------------------------------------
// bf16-split GEMM: C = A @ B + bias. Pre-split inputs, cp.async 2-stage,
// ldmatrix-fed HMMA. Block 128x128, BK=32, 8 warps (2m x 4n), warp 64x32.
// ---------------------------------------------------------------------------
#define APG 40
#define BPG 136
#define GEMM_SMEM ((2*2*128*APG + 2*2*32*BPG) * 2)

#define GEMM_LOAD(s, k0)                                                        \
    {                                                                           \
        _Pragma("unroll")                                                       \
        for (int j = 0; j < 2; j++) {                                           \
            const int id = tid * 2 + j;                                         \
            const int arow = id >> 2, ac = (id & 3) * 8;                        \
            const size_t ga = (size_t)(m0 + arow) * K + (k0) + ac;              \
            cp16(sA + ((s)*2+0)*128*APG + arow*APG + ac, Ah_g + ga);            \
            cp16(sA + ((s)*2+1)*128*APG + arow*APG + ac, Al_g + ga);            \
            const int brow = id >> 4, bc = (id & 15) * 8;                       \
            const size_t gb = (size_t)((k0) + brow) * N + n0 + bc;              \
            cp16(sB + ((s)*2+0)*32*BPG + brow*BPG + bc, Bh_g + gb);             \
            cp16(sB + ((s)*2+1)*32*BPG + brow*BPG + bc, Bl_g + gb);             \
        }                                                                       \
        CP_COMMIT();                                                            \
    }

template<bool SPLIT_OUT>
__global__ __launch_bounds__(256, 1) void gemm_bf16(
    const __nv_bfloat16* __restrict__ Ah_g, const __nv_bfloat16* __restrict__ Al_g,
    const __nv_bfloat16* __restrict__ Bh_g, const __nv_bfloat16* __restrict__ Bl_g,
    const float* __restrict__ bias,
    float* __restrict__ C, __nv_bfloat16* __restrict__ Ch, __nv_bfloat16* __restrict__ Cl,
    int M, int N, int K)
{
    extern __shared__ __nv_bfloat16 smg[];
    __nv_bfloat16* sA = smg;                       // [stage][half][128*APG]
    __nv_bfloat16* sB = smg + 2*2*128*APG;         // [stage][half][32*BPG] natural [k][n]

    const int tid = threadIdx.x, warp = tid >> 5, lane = tid & 31;
    const int m0 = blockIdx.y * 128, n0 = blockIdx.x * 128;
    const int wm = (warp & 1) * 64, wn = (warp >> 1) * 32;

    float acc[4][4][4];
#pragma unroll
    for (int i = 0; i < 4; i++)
#pragma unroll
        for (int j = 0; j < 4; j++)
#pragma unroll
            for (int l = 0; l < 4; l++) acc[i][j][l] = 0.f;

    GEMM_LOAD(0, 0);

    const int ntiles = K / 32;
    for (int t = 0; t < ntiles; t++) {
        CP_WAIT0();
        __syncthreads();
        if (t + 1 < ntiles) GEMM_LOAD((t + 1) & 1, (t + 1) * 32);

        const int s = t & 1;
        const __nv_bfloat16* Ahs = sA + (s*2+0)*128*APG;
        const __nv_bfloat16* Als = sA + (s*2+1)*128*APG;
        const __nv_bfloat16* Bhs = sB + (s*2+0)*32*BPG;
        const __nv_bfloat16* Bls = sB + (s*2+1)*32*BPG;

#pragma unroll
        for (int ks = 0; ks < 32; ks += 16) {
            unsigned bh[2][4], bl[2][4];
            const int brr = ks + (lane & 8) + (lane & 7);
#pragma unroll
            for (int np = 0; np < 2; np++) {
                const int bcc = wn + np * 16 + ((lane >> 1) & 8);
                ldsm4t(bh[np], Bhs + brr * BPG + bcc);
                ldsm4t(bl[np], Bls + brr * BPG + bcc);
            }
#pragma unroll
            for (int mt = 0; mt < 4; mt++) {
                unsigned ah[4], al[4];
                const int r = (wm + mt * 16 + (lane & 15)) * APG + ks + ((lane & 16) >> 1);
                ldsm4(ah, Ahs + r);
                ldsm4(al, Als + r);
#pragma unroll
                for (int nt = 0; nt < 4; nt++) {
                    const unsigned b0h = bh[nt >> 1][(nt & 1) * 2], b1h = bh[nt >> 1][(nt & 1) * 2 + 1];
                    const unsigned b0l = bl[nt >> 1][(nt & 1) * 2], b1l = bl[nt >> 1][(nt & 1) * 2 + 1];
                    mma16816(acc[mt][nt], ah[0], ah[1], ah[2], ah[3], b0h, b1h);
                    mma16816(acc[mt][nt], ah[0], ah[1], ah[2], ah[3], b0l, b1l);
                    mma16816(acc[mt][nt], al[0], al[1], al[2], al[3], b0h, b1h);
                }
            }
        }
        __syncthreads();
    }

    // epilogue
    const int g = lane >> 2, tg = lane & 3;
#pragma unroll
    for (int mt = 0; mt < 4; mt++) {
        const int r = m0 + wm + mt * 16 + g;
#pragma unroll
        for (int nt = 0; nt < 4; nt++) {
            const int c = n0 + wn + nt * 8 + tg * 2;
            const float bx = bias[c], by = bias[c + 1];
            const float v0 = acc[mt][nt][0] + bx, v1 = acc[mt][nt][1] + by;
            const float v2 = acc[mt][nt][2] + bx, v3 = acc[mt][nt][3] + by;
            if (SPLIT_OUT) {
                unsigned h0, l0, h1, l1;
                split_pack2(v0, v1, h0, l0);
                split_pack2(v2, v3, h1, l1);
                *reinterpret_cast<unsigned*>(&Ch[(size_t)r * N + c])       = h0;
                *reinterpret_cast<unsigned*>(&Cl[(size_t)r * N + c])       = l0;
                *reinterpret_cast<unsigned*>(&Ch[(size_t)(r + 8) * N + c]) = h1;
                *reinterpret_cast<unsigned*>(&Cl[(size_t)(r + 8) * N + c]) = l1;
            } else {
                float2 o0 = {v0, v1}, o1 = {v2, v3};
                *reinterpret_cast<float2*>(&C[(size_t)r * N + c])       = o0;
                *reinterpret_cast<float2*>(&C[(size_t)(r + 8) * N + c]) = o1;
            }
        }
    }
}

// ---------------------------------------------------------------------------
// Fused causal retention attention on pre-split bf16 Q/K/V.
// Block: (b, h, 128 q-rows); k-tiles of 64. 8 warps = 2(q:64) x 4(16-wide).
// K stored natural [k][d] (regular ldsm = B-frag), V natural (trans ldsm).
// ---------------------------------------------------------------------------
#define AP 72
#define ATT_SMEM ((2*128*AP + 4*64*AP + 2*128*AP) * 2)   // 110592 B

__global__ __launch_bounds__(256, 1) void attn_mma(
    const __nv_bfloat16* __restrict__ kqvh, const __nv_bfloat16* __restrict__ kqvl,
    __nv_bfloat16* __restrict__ aoh, __nv_bfloat16* __restrict__ aol)
{
    extern __shared__ __nv_bfloat16 sma[];
    __nv_bfloat16 *Qh = sma,           *Ql = Qh + 128 * AP;
    __nv_bfloat16 *Kh = Ql + 128 * AP, *Kl = Kh + 64 * AP;
    __nv_bfloat16 *Vh = Kl + 64 * AP,  *Vl = Vh + 64 * AP;
    __nv_bfloat16 *Sh = Vl + 64 * AP,  *Sl = Sh + 128 * AP;

    const int tid = threadIdx.x, warp = tid >> 5, lane = tid & 31;
    const int g = lane >> 2, tg = lane & 3;
    const int qb = gridDim.x - 1 - blockIdx.x;    // heavy tiles first
    const int h = blockIdx.y, b = blockIdx.z;
    const int q0 = qb * 128;

    const size_t hoff = (size_t)b * TT * KQV_LD + h * DH;
    const __nv_bfloat16 *Khg = kqvh + hoff,          *Klg = kqvl + hoff;
    const __nv_bfloat16 *Qhg = Khg + DD,             *Qlg = Klg + DD;
    const __nv_bfloat16 *Vhg = Khg + 2 * DD,         *Vlg = Klg + 2 * DD;

    // load Q tile 128x64 (hi/lo), 16B vectors
#pragma unroll
    for (int j = 0; j < 4; j++) {
        const int id = tid * 4 + j;
        const int row = id >> 3, c8 = (id & 7) * 8;
        const size_t gq = (size_t)(q0 + row) * KQV_LD + c8;
        *reinterpret_cast<uint4*>(&Qh[row * AP + c8]) = *reinterpret_cast<const uint4*>(&Qhg[gq]);
        *reinterpret_cast<uint4*>(&Ql[row * AP + c8]) = *reinterpret_cast<const uint4*>(&Qlg[gq]);
    }

    const int wq = (warp & 1) * 64;
    const int wk = (warp >> 1) * 16;

    float oacc[4][2][4];
#pragma unroll
    for (int i = 0; i < 4; i++)
#pragma unroll
        for (int j = 0; j < 2; j++)
#pragma unroll
            for (int l = 0; l < 4; l++) oacc[i][j][l] = 0.f;

    const int nkb = 2 * qb + 2;
    for (int kb = 0; kb < nkb; kb++) {
        const int k0 = kb * 64;

        // prefetch K/V (hi/lo) into registers — overlaps previous O-mma
        uint4 pkh[2], pkl[2], pvh[2], pvl[2];
#pragma unroll
        for (int j = 0; j < 2; j++) {
            const int id = tid * 2 + j;
            const int row = id >> 3, c8 = (id & 7) * 8;
            const size_t gk = (size_t)(k0 + row) * KQV_LD + c8;
            pkh[j] = *reinterpret_cast<const uint4*>(&Khg[gk]);
            pkl[j] = *reinterpret_cast<const uint4*>(&Klg[gk]);
            pvh[j] = *reinterpret_cast<const uint4*>(&Vhg[gk]);
            pvl[j] = *reinterpret_cast<const uint4*>(&Vlg[gk]);
        }
        __syncthreads();   // prev O-mma done with K/V/S (and Q load, iter 0)

#pragma unroll
        for (int j = 0; j < 2; j++) {
            const int id = tid * 2 + j;
            const int row = id >> 3, c8 = (id & 7) * 8;
            *reinterpret_cast<uint4*>(&Kh[row * AP + c8]) = pkh[j];
            *reinterpret_cast<uint4*>(&Kl[row * AP + c8]) = pkl[j];
            *reinterpret_cast<uint4*>(&Vh[row * AP + c8]) = pvh[j];
            *reinterpret_cast<uint4*>(&Vl[row * AP + c8]) = pvl[j];
        }
        __syncthreads();

        // ---- S = Q K^T (warp: 64q x 16k) ----
        float sacc[4][2][4];
#pragma unroll
        for (int i = 0; i < 4; i++)
#pragma unroll
            for (int j = 0; j < 2; j++)
#pragma unroll
                for (int l = 0; l < 4; l++) sacc[i][j][l] = 0.f;

#pragma unroll
        for (int ds = 0; ds < 64; ds += 16) {
            unsigned bh[4], bl[4];
            const int kr = wk + ((lane >> 1) & 8) + (lane & 7);
            const int kc = ds + (lane & 8);
            ldsm4(bh, Kh + kr * AP + kc);
            ldsm4(bl, Kl + kr * AP + kc);
#pragma unroll
            for (int mt = 0; mt < 4; mt++) {
                unsigned qh[4], ql[4];
                const int r = (wq + mt * 16 + (lane & 15)) * AP + ds + ((lane & 16) >> 1);
                ldsm4(qh, Qh + r);
                ldsm4(ql, Ql + r);
#pragma unroll
                for (int nt = 0; nt < 2; nt++) {
                    mma16816(sacc[mt][nt], qh[0], qh[1], qh[2], qh[3], bh[nt*2], bh[nt*2+1]);
                    mma16816(sacc[mt][nt], qh[0], qh[1], qh[2], qh[3], bl[nt*2], bl[nt*2+1]);
                    mma16816(sacc[mt][nt], ql[0], ql[1], ql[2], ql[3], bh[nt*2], bh[nt*2+1]);
                }
            }
        }

        // mask (diagonal) + split-store S
        const bool diag = (kb >= 2 * qb);
#pragma unroll
        for (int mt = 0; mt < 4; mt++) {
            const int qr = wq + mt * 16 + g;
#pragma unroll
            for (int nt = 0; nt < 2; nt++) {
                const int kc = wk + nt * 8 + tg * 2;
                float s0 = sacc[mt][nt][0], s1 = sacc[mt][nt][1];
                float s2 = sacc[mt][nt][2], s3 = sacc[mt][nt][3];
                if (diag) {
                    const int qg0 = q0 + qr, qg8 = qg0 + 8, kg = k0 + kc;
                    if (kg     > qg0) s0 = 0.f;
                    if (kg + 1 > qg0) s1 = 0.f;
                    if (kg     > qg8) s2 = 0.f;
                    if (kg + 1 > qg8) s3 = 0.f;
                }
                unsigned h0, l0, h1, l1;
                split_pack2(s0, s1, h0, l0);
                split_pack2(s2, s3, h1, l1);
                const int idx = qr * AP + kc;
                *reinterpret_cast<unsigned*>(&Sh[idx])          = h0;
                *reinterpret_cast<unsigned*>(&Sl[idx])          = l0;
                *reinterpret_cast<unsigned*>(&Sh[idx + 8 * AP]) = h1;
                *reinterpret_cast<unsigned*>(&Sl[idx + 8 * AP]) = l1;
            }
        }
        __syncthreads();

        // ---- O += S V (warp: 64q x 16d) ----
#pragma unroll
        for (int ks = 0; ks < 64; ks += 16) {
            unsigned vh4[4], vl4[4];
            const int vr = ks + (lane & 8) + (lane & 7);
            const int vc = wk + ((lane >> 1) & 8);
            ldsm4t(vh4, Vh + vr * AP + vc);
            ldsm4t(vl4, Vl + vr * AP + vc);
#pragma unroll
            for (int mt = 0; mt < 4; mt++) {
                unsigned sh4[4], sl4[4];
                const int r = (wq + mt * 16 + (lane & 15)) * AP + ks + ((lane & 16) >> 1);
                ldsm4(sh4, Sh + r);
                ldsm4(sl4, Sl + r);
#pragma unroll
                for (int nt = 0; nt < 2; nt++) {
                    mma16816(oacc[mt][nt], sh4[0], sh4[1], sh4[2], sh4[3], vh4[nt*2], vh4[nt*2+1]);
                    mma16816(oacc[mt][nt], sh4[0], sh4[1], sh4[2], sh4[3], vl4[nt*2], vl4[nt*2+1]);
                    mma16816(oacc[mt][nt], sl4[0], sl4[1], sl4[2], sl4[3], vh4[nt*2], vh4[nt*2+1]);
                }
            }
        }
    }

    // write O split -> aoh/aol [b*TT + q, h*64 + d]
#pragma unroll
    for (int mt = 0; mt < 4; mt++) {
        const size_t t = (size_t)b * TT + q0 + wq + mt * 16 + g;
#pragma unroll
        for (int nt = 0; nt < 2; nt++) {
            const int c = h * DH + wk + nt * 8 + tg * 2;
            unsigned h0, l0, h1, l1;
            split_pack2(oacc[mt][nt][0], oacc[mt][nt][1], h0, l0);
            split_pack2(oacc[mt][nt][2], oacc[mt][nt][3], h1, l1);
            *reinterpret_cast<unsigned*>(&aoh[t * DD + c])       = h0;
            *reinterpret_cast<unsigned*>(&aol[t * DD + c])       = l0;
            *reinterpret_cast<unsigned*>(&aoh[(t + 8) * DD + c]) = h1;
            *reinterpret_cast<unsigned*>(&aol[(t + 8) * DD + c]) = l1;
        }
    }
}

// ---------------------------------------------------------------------------
extern "C" void kernel_launch(void* const* d_in, const int* in_sizes, int n_in,
                              void* d_out, int out_size)
{
    const float* x  = (const float*)d_in[0];
    const float* W1 = (const float*)d_in[1];
    const float* b1 = (const float*)d_in[2];
    const float* W2 = (const float*)d_in[3];
    const float* b2 = (const float*)d_in[4];
    float* out = (float*)d_out;

    __nv_bfloat16 *xh, *xl, *w1h, *w1l, *w2h, *w2l, *kqvh, *kqvl, *aoh, *aol;
    cudaGetSymbolAddress((void**)&xh,  g_xh);   cudaGetSymbolAddress((void**)&xl,  g_xl);
    cudaGetSymbolAddress((void**)&w1h, g_w1h);  cudaGetSymbolAddress((void**)&w1l, g_w1l);
    cudaGetSymbolAddress((void**)&w2h, g_w2h);  cudaGetSymbolAddress((void**)&w2l, g_w2l);
    cudaGetSymbolAddress((void**)&kqvh, g_kqvh); cudaGetSymbolAddress((void**)&kqvl, g_kqvl);
    cudaGetSymbolAddress((void**)&aoh, g_aoh);  cudaGetSymbolAddress((void**)&aol, g_aol);

    cudaFuncSetAttribute(gemm_bf16<true>,
                         cudaFuncAttributeMaxDynamicSharedMemorySize, GEMM_SMEM);
    cudaFuncSetAttribute(gemm_bf16<false>,
                         cudaFuncAttributeMaxDynamicSharedMemorySize, GEMM_SMEM);
    cudaFuncSetAttribute(attn_mma,
                         cudaFuncAttributeMaxDynamicSharedMemorySize, ATT_SMEM);

    // 0) pre-split inputs to bf16 hi/lo
    {
        int n4;
        n4 = MROWS * DD / 4;      split_kernel<<<(n4 + 255) / 256, 256>>>(x,  xh,  xl,  n4);
        n4 = DD * 3 * DD / 4;     split_kernel<<<(n4 + 255) / 256, 256>>>(W1, w1h, w1l, n4);
        n4 = DD * DD / 4;         split_kernel<<<(n4 + 255) / 256, 256>>>(W2, w2h, w2l, n4);
    }
    // 1) kqv = x @ W1 + b1  (split output)
    {
        dim3 grid(3 * DD / 128, MROWS / 128);
        gemm_bf16<true><<<grid, 256, GEMM_SMEM>>>(xh, xl, w1h, w1l, b1,
                                                  nullptr, kqvh, kqvl,
                                                  MROWS, 3 * DD, DD);
    }
    // 2) causal retention attention (split in, split out)
    {
        dim3 grid(TT / 128, HH, BB);
        attn_mma<<<grid, 256, ATT_SMEM>>>(kqvh, kqvl, aoh, aol);
    }
    // 3) out = ao @ W2 + b2  (fp32 output)
    {
        dim3 grid(DD / 128, MROWS / 128);
        gemm_bf16<false><<<grid, 256, GEMM_SMEM>>>(aoh, aol, w2h, w2l, b2,
                                                   out, nullptr, nullptr,
                                                   MROWS, DD, DD);
    }
}

// round 5
// speedup vs baseline: 3.6236x; 1.6025x over previous
#include <cuda_runtime.h>
#include <cuda_fp16.h>

#define BB 2
#define TT 2048
#define DD 1024
#define HH 16
#define DH 64
#define MROWS (BB*TT)
#define KQV_LD (3*DD)

// fp16 operands (device globals; allocation is forbidden)
__device__ __half g_xh [(size_t)MROWS*DD];
__device__ __half g_w1h[(size_t)DD*3*DD], g_w1l[(size_t)DD*3*DD];   // natural [K][N]
__device__ __half g_w2h[(size_t)DD*DD],   g_w2l[(size_t)DD*DD];
__device__ __half g_kqvh[(size_t)MROWS*3*DD], g_kqvl[(size_t)MROWS*3*DD];
__device__ __half g_aoh[(size_t)MROWS*DD];

// ---------------------------------------------------------------------------
// helpers
// ---------------------------------------------------------------------------
__device__ __forceinline__ unsigned h2_pack(__half a, __half b) {
    __half2 t = __halves2half2(a, b);
    return *reinterpret_cast<unsigned*>(&t);
}
__device__ __forceinline__ void hsplit2(float x, float y, unsigned &hi, unsigned &lo) {
    __half hx = __float2half_rn(x), hy = __float2half_rn(y);
    __half lx = __float2half_rn(x - __half2float(hx));
    __half ly = __float2half_rn(y - __half2float(hy));
    hi = h2_pack(hx, hy);
    lo = h2_pack(lx, ly);
}
__device__ __forceinline__ unsigned hpack2(float x, float y) {
    return h2_pack(__float2half_rn(x), __float2half_rn(y));
}
__device__ __forceinline__ void mma16816(float* c,
    unsigned a0, unsigned a1, unsigned a2, unsigned a3,
    unsigned b0, unsigned b1)
{
    asm volatile(
        "mma.sync.aligned.m16n8k16.row.col.f32.f16.f16.f32 "
        "{%0,%1,%2,%3},{%4,%5,%6,%7},{%8,%9},{%0,%1,%2,%3};\n"
        : "+f"(c[0]), "+f"(c[1]), "+f"(c[2]), "+f"(c[3])
        : "r"(a0), "r"(a1), "r"(a2), "r"(a3), "r"(b0), "r"(b1));
}
__device__ __forceinline__ void ldsm4(unsigned* r, const void* p) {
    unsigned a = (unsigned)__cvta_generic_to_shared(p);
    asm volatile("ldmatrix.sync.aligned.m8n8.x4.shared.b16 {%0,%1,%2,%3}, [%4];\n"
        : "=r"(r[0]), "=r"(r[1]), "=r"(r[2]), "=r"(r[3]) : "r"(a));
}
__device__ __forceinline__ void ldsm4t(unsigned* r, const void* p) {
    unsigned a = (unsigned)__cvta_generic_to_shared(p);
    asm volatile("ldmatrix.sync.aligned.m8n8.x4.trans.shared.b16 {%0,%1,%2,%3}, [%4];\n"
        : "=r"(r[0]), "=r"(r[1]), "=r"(r[2]), "=r"(r[3]) : "r"(a));
}
__device__ __forceinline__ void cp16(void* sp, const void* gp) {
    unsigned s = (unsigned)__cvta_generic_to_shared(sp);
    asm volatile("cp.async.cg.shared.global [%0], [%1], 16;\n" :: "r"(s), "l"(gp));
}
#define CP_COMMIT() asm volatile("cp.async.commit_group;\n")
#define CP_WAIT(n)  asm volatile("cp.async.wait_group %0;\n" :: "n"(n))

// ---------------------------------------------------------------------------
// prep kernels
// ---------------------------------------------------------------------------
__global__ void round_kernel(const float* __restrict__ in,
                             __half* __restrict__ hi, int n4)
{
    int i = blockIdx.x * blockDim.x + threadIdx.x;
    if (i >= n4) return;
    float4 v = reinterpret_cast<const float4*>(in)[i];
    reinterpret_cast<uint2*>(hi)[i] = make_uint2(hpack2(v.x, v.y), hpack2(v.z, v.w));
}
__global__ void split_kernel(const float* __restrict__ in,
                             __half* __restrict__ hi, __half* __restrict__ lo, int n4)
{
    int i = blockIdx.x * blockDim.x + threadIdx.x;
    if (i >= n4) return;
    float4 v = reinterpret_cast<const float4*>(in)[i];
    unsigned h0, l0, h1, l1;
    hsplit2(v.x, v.y, h0, l0);
    hsplit2(v.z, v.w, h1, l1);
    reinterpret_cast<uint2*>(hi)[i] = make_uint2(h0, h1);
    reinterpret_cast<uint2*>(lo)[i] = make_uint2(l0, l1);
}

// ---------------------------------------------------------------------------
// fp16 2-product GEMM: C = A @ B + bias  (A hi-only, B split hi/lo)
// Block 128x128, BK=32, 2-stage cp.async, 8 warps (2m x 4n), warp 64x32.
// ---------------------------------------------------------------------------
#define APG 40
#define BPG 136
#define GEMM_SMEM ((2*128*APG + 2*2*32*BPG) * 2)   // 55296 B

#define GEMM_LOAD(s, k0)                                                        \
    {                                                                           \
        _Pragma("unroll")                                                       \
        for (int j = 0; j < 2; j++) {                                           \
            const int id = tid * 2 + j;                                         \
            const int arow = id >> 2, ac = (id & 3) * 8;                        \
            const size_t ga = (size_t)(m0 + arow) * K + (k0) + ac;              \
            cp16(sA + (s)*128*APG + arow*APG + ac, Ah_g + ga);                  \
            const int brow = id >> 4, bc = (id & 15) * 8;                       \
            const size_t gb = (size_t)((k0) + brow) * N + n0 + bc;              \
            cp16(sB + ((s)*2+0)*32*BPG + brow*BPG + bc, Bh_g + gb);             \
            cp16(sB + ((s)*2+1)*32*BPG + brow*BPG + bc, Bl_g + gb);             \
        }                                                                       \
        CP_COMMIT();                                                            \
    }

template<bool SPLIT_OUT>
__global__ __launch_bounds__(256, 2) void gemm_h(
    const __half* __restrict__ Ah_g,
    const __half* __restrict__ Bh_g, const __half* __restrict__ Bl_g,
    const float* __restrict__ bias,
    float* __restrict__ C, __half* __restrict__ Ch, __half* __restrict__ Cl,
    int M, int N, int K)
{
    extern __shared__ __half smg[];
    __half* sA = smg;                       // [stage][128*APG]
    __half* sB = smg + 2*128*APG;           // [stage][half][32*BPG] natural [k][n]

    const int tid = threadIdx.x, warp = tid >> 5, lane = tid & 31;
    const int m0 = blockIdx.y * 128, n0 = blockIdx.x * 128;
    const int wm = (warp & 1) * 64, wn = (warp >> 1) * 32;

    float acc[4][4][4];
#pragma unroll
    for (int i = 0; i < 4; i++)
#pragma unroll
        for (int j = 0; j < 4; j++)
#pragma unroll
            for (int l = 0; l < 4; l++) acc[i][j][l] = 0.f;

    GEMM_LOAD(0, 0);

    const int ntiles = K / 32;
    for (int t = 0; t < ntiles; t++) {
        CP_WAIT(0);
        __syncthreads();
        if (t + 1 < ntiles) GEMM_LOAD((t + 1) & 1, (t + 1) * 32);

        const int s = t & 1;
        const __half* Ahs = sA + s*128*APG;
        const __half* Bhs = sB + (s*2+0)*32*BPG;
        const __half* Bls = sB + (s*2+1)*32*BPG;

#pragma unroll
        for (int ks = 0; ks < 32; ks += 16) {
            unsigned bh[2][4], bl[2][4];
            const int brr = ks + (lane & 8) + (lane & 7);
#pragma unroll
            for (int np = 0; np < 2; np++) {
                const int bcc = wn + np * 16 + ((lane >> 1) & 8);
                ldsm4t(bh[np], Bhs + brr * BPG + bcc);
                ldsm4t(bl[np], Bls + brr * BPG + bcc);
            }
#pragma unroll
            for (int mt = 0; mt < 4; mt++) {
                unsigned ah[4];
                const int r = (wm + mt * 16 + (lane & 15)) * APG + ks + ((lane & 16) >> 1);
                ldsm4(ah, Ahs + r);
#pragma unroll
                for (int nt = 0; nt < 4; nt++) {
                    const unsigned b0h = bh[nt >> 1][(nt & 1) * 2], b1h = bh[nt >> 1][(nt & 1) * 2 + 1];
                    const unsigned b0l = bl[nt >> 1][(nt & 1) * 2], b1l = bl[nt >> 1][(nt & 1) * 2 + 1];
                    mma16816(acc[mt][nt], ah[0], ah[1], ah[2], ah[3], b0h, b1h);
                    mma16816(acc[mt][nt], ah[0], ah[1], ah[2], ah[3], b0l, b1l);
                }
            }
        }
        __syncthreads();
    }

    const int g = lane >> 2, tg = lane & 3;
#pragma unroll
    for (int mt = 0; mt < 4; mt++) {
        const int r = m0 + wm + mt * 16 + g;
#pragma unroll
        for (int nt = 0; nt < 4; nt++) {
            const int c = n0 + wn + nt * 8 + tg * 2;
            const float bx = bias[c], by = bias[c + 1];
            const float v0 = acc[mt][nt][0] + bx, v1 = acc[mt][nt][1] + by;
            const float v2 = acc[mt][nt][2] + bx, v3 = acc[mt][nt][3] + by;
            if (SPLIT_OUT) {
                unsigned h0, l0, h1, l1;
                hsplit2(v0, v1, h0, l0);
                hsplit2(v2, v3, h1, l1);
                *reinterpret_cast<unsigned*>(&Ch[(size_t)r * N + c])       = h0;
                *reinterpret_cast<unsigned*>(&Cl[(size_t)r * N + c])       = l0;
                *reinterpret_cast<unsigned*>(&Ch[(size_t)(r + 8) * N + c]) = h1;
                *reinterpret_cast<unsigned*>(&Cl[(size_t)(r + 8) * N + c]) = l1;
            } else {
                float2 o0 = {v0, v1}, o1 = {v2, v3};
                *reinterpret_cast<float2*>(&C[(size_t)r * N + c])       = o0;
                *reinterpret_cast<float2*>(&C[(size_t)(r + 8) * N + c]) = o1;
            }
        }
    }
}

// ---------------------------------------------------------------------------
// Fused causal retention attention, fp16 2-product.
// Q hi-only, K/V split, S hi-only. Block (b, h, 128 q-rows), k-tiles of 64.
// ---------------------------------------------------------------------------
#define AP 72
#define ATT_SMEM ((128*AP + 4*64*AP + 128*AP) * 2)   // 73728 B

__global__ __launch_bounds__(256, 2) void attn_mma(
    const __half* __restrict__ kqvh, const __half* __restrict__ kqvl,
    __half* __restrict__ aoh)
{
    extern __shared__ __half sma[];
    __half *Qh = sma;
    __half *Kh = Qh + 128 * AP, *Kl = Kh + 64 * AP;
    __half *Vh = Kl + 64 * AP,  *Vl = Vh + 64 * AP;
    __half *Sh = Vl + 64 * AP;

    const int tid = threadIdx.x, warp = tid >> 5, lane = tid & 31;
    const int g = lane >> 2, tg = lane & 3;
    const int qb = gridDim.x - 1 - blockIdx.x;    // heavy tiles first
    const int h = blockIdx.y, b = blockIdx.z;
    const int q0 = qb * 128;

    const size_t hoff = (size_t)b * TT * KQV_LD + h * DH;
    const __half *Khg = kqvh + hoff, *Klg = kqvl + hoff;
    const __half *Qhg = Khg + DD;
    const __half *Vhg = Khg + 2*DD, *Vlg = Klg + 2*DD;

    // load Q tile 128x64 (hi only)
#pragma unroll
    for (int j = 0; j < 4; j++) {
        const int id = tid * 4 + j;
        const int row = id >> 3, c8 = (id & 7) * 8;
        const size_t gq = (size_t)(q0 + row) * KQV_LD + c8;
        *reinterpret_cast<uint4*>(&Qh[row * AP + c8]) = *reinterpret_cast<const uint4*>(&Qhg[gq]);
    }

    const int wq = (warp & 1) * 64;
    const int wk = (warp >> 1) * 16;

    float oacc[4][2][4];
#pragma unroll
    for (int i = 0; i < 4; i++)
#pragma unroll
        for (int j = 0; j < 2; j++)
#pragma unroll
            for (int l = 0; l < 4; l++) oacc[i][j][l] = 0.f;

    const int nkb = 2 * qb + 2;
    for (int kb = 0; kb < nkb; kb++) {
        const int k0 = kb * 64;

        // prefetch K/V (hi/lo) into registers — overlaps previous O-mma
        uint4 pkh[2], pkl[2], pvh[2], pvl[2];
#pragma unroll
        for (int j = 0; j < 2; j++) {
            const int id = tid * 2 + j;
            const int row = id >> 3, c8 = (id & 7) * 8;
            const size_t gk = (size_t)(k0 + row) * KQV_LD + c8;
            pkh[j] = *reinterpret_cast<const uint4*>(&Khg[gk]);
            pkl[j] = *reinterpret_cast<const uint4*>(&Klg[gk]);
            pvh[j] = *reinterpret_cast<const uint4*>(&Vhg[gk]);
            pvl[j] = *reinterpret_cast<const uint4*>(&Vlg[gk]);
        }
        __syncthreads();   // prev O-mma done with K/V/S (and Q load, iter 0)

#pragma unroll
        for (int j = 0; j < 2; j++) {
            const int id = tid * 2 + j;
            const int row = id >> 3, c8 = (id & 7) * 8;
            *reinterpret_cast<uint4*>(&Kh[row * AP + c8]) = pkh[j];
            *reinterpret_cast<uint4*>(&Kl[row * AP + c8]) = pkl[j];
            *reinterpret_cast<uint4*>(&Vh[row * AP + c8]) = pvh[j];
            *reinterpret_cast<uint4*>(&Vl[row * AP + c8]) = pvl[j];
        }
        __syncthreads();

        // ---- S = Q K^T (warp: 64q x 16k) ----
        float sacc[4][2][4];
#pragma unroll
        for (int i = 0; i < 4; i++)
#pragma unroll
            for (int j = 0; j < 2; j++)
#pragma unroll
                for (int l = 0; l < 4; l++) sacc[i][j][l] = 0.f;

#pragma unroll
        for (int ds = 0; ds < 64; ds += 16) {
            unsigned bh[4], bl[4];
            const int kr = wk + ((lane >> 1) & 8) + (lane & 7);
            const int kc = ds + (lane & 8);
            ldsm4(bh, Kh + kr * AP + kc);
            ldsm4(bl, Kl + kr * AP + kc);
#pragma unroll
            for (int mt = 0; mt < 4; mt++) {
                unsigned qh[4];
                const int r = (wq + mt * 16 + (lane & 15)) * AP + ds + ((lane & 16) >> 1);
                ldsm4(qh, Qh + r);
#pragma unroll
                for (int nt = 0; nt < 2; nt++) {
                    mma16816(sacc[mt][nt], qh[0], qh[1], qh[2], qh[3], bh[nt*2], bh[nt*2+1]);
                    mma16816(sacc[mt][nt], qh[0], qh[1], qh[2], qh[3], bl[nt*2], bl[nt*2+1]);
                }
            }
        }

        // mask (diagonal) + store S (hi only)
        const bool diag = (kb >= 2 * qb);
#pragma unroll
        for (int mt = 0; mt < 4; mt++) {
            const int qr = wq + mt * 16 + g;
#pragma unroll
            for (int nt = 0; nt < 2; nt++) {
                const int kc = wk + nt * 8 + tg * 2;
                float s0 = sacc[mt][nt][0], s1 = sacc[mt][nt][1];
                float s2 = sacc[mt][nt][2], s3 = sacc[mt][nt][3];
                if (diag) {
                    const int qg0 = q0 + qr, qg8 = qg0 + 8, kg = k0 + kc;
                    if (kg     > qg0) s0 = 0.f;
                    if (kg + 1 > qg0) s1 = 0.f;
                    if (kg     > qg8) s2 = 0.f;
                    if (kg + 1 > qg8) s3 = 0.f;
                }
                const int idx = qr * AP + kc;
                *reinterpret_cast<unsigned*>(&Sh[idx])          = hpack2(s0, s1);
                *reinterpret_cast<unsigned*>(&Sh[idx + 8 * AP]) = hpack2(s2, s3);
            }
        }
        __syncthreads();

        // ---- O += S V (warp: 64q x 16d) ----
#pragma unroll
        for (int ks = 0; ks < 64; ks += 16) {
            unsigned vh4[4], vl4[4];
            const int vr = ks + (lane & 8) + (lane & 7);
            const int vc = wk + ((lane >> 1) & 8);
            ldsm4t(vh4, Vh + vr * AP + vc);
            ldsm4t(vl4, Vl + vr * AP + vc);
#pragma unroll
            for (int mt = 0; mt < 4; mt++) {
                unsigned sh4[4];
                const int r = (wq + mt * 16 + (lane & 15)) * AP + ks + ((lane & 16) >> 1);
                ldsm4(sh4, Sh + r);
#pragma unroll
                for (int nt = 0; nt < 2; nt++) {
                    mma16816(oacc[mt][nt], sh4[0], sh4[1], sh4[2], sh4[3], vh4[nt*2], vh4[nt*2+1]);
                    mma16816(oacc[mt][nt], sh4[0], sh4[1], sh4[2], sh4[3], vl4[nt*2], vl4[nt*2+1]);
                }
            }
        }
    }

    // write O (hi only) -> aoh[b*TT + q, h*64 + d]
#pragma unroll
    for (int mt = 0; mt < 4; mt++) {
        const size_t t = (size_t)b * TT + q0 + wq + mt * 16 + g;
#pragma unroll
        for (int nt = 0; nt < 2; nt++) {
            const int c = h * DH + wk + nt * 8 + tg * 2;
            *reinterpret_cast<unsigned*>(&aoh[t * DD + c])       = hpack2(oacc[mt][nt][0], oacc[mt][nt][1]);
            *reinterpret_cast<unsigned*>(&aoh[(t + 8) * DD + c]) = hpack2(oacc[mt][nt][2], oacc[mt][nt][3]);
        }
    }
}

// ---------------------------------------------------------------------------
extern "C" void kernel_launch(void* const* d_in, const int* in_sizes, int n_in,
                              void* d_out, int out_size)
{
    const float* x  = (const float*)d_in[0];
    const float* W1 = (const float*)d_in[1];
    const float* b1 = (const float*)d_in[2];
    const float* W2 = (const float*)d_in[3];
    const float* b2 = (const float*)d_in[4];
    float* out = (float*)d_out;

    __half *xh, *w1h, *w1l, *w2h, *w2l, *kqvh, *kqvl, *aoh;
    cudaGetSymbolAddress((void**)&xh,  g_xh);
    cudaGetSymbolAddress((void**)&w1h, g_w1h);  cudaGetSymbolAddress((void**)&w1l, g_w1l);
    cudaGetSymbolAddress((void**)&w2h, g_w2h);  cudaGetSymbolAddress((void**)&w2l, g_w2l);
    cudaGetSymbolAddress((void**)&kqvh, g_kqvh); cudaGetSymbolAddress((void**)&kqvl, g_kqvl);
    cudaGetSymbolAddress((void**)&aoh, g_aoh);

    cudaFuncSetAttribute(gemm_h<true>,
                         cudaFuncAttributeMaxDynamicSharedMemorySize, GEMM_SMEM);
    cudaFuncSetAttribute(gemm_h<false>,
                         cudaFuncAttributeMaxDynamicSharedMemorySize, GEMM_SMEM);
    cudaFuncSetAttribute(attn_mma,
                         cudaFuncAttributeMaxDynamicSharedMemorySize, ATT_SMEM);

    // 0) x -> fp16 hi; W1/W2 -> fp16 hi/lo
    {
        int n4;
        n4 = MROWS * DD / 4;   round_kernel<<<(n4 + 255) / 256, 256>>>(x, xh, n4);
        n4 = DD * 3 * DD / 4;  split_kernel<<<(n4 + 255) / 256, 256>>>(W1, w1h, w1l, n4);
        n4 = DD * DD / 4;      split_kernel<<<(n4 + 255) / 256, 256>>>(W2, w2h, w2l, n4);
    }
    // 1) kqv = x @ W1 + b1  (split fp16 output)
    {
        dim3 grid(3 * DD / 128, MROWS / 128);
        gemm_h<true><<<grid, 256, GEMM_SMEM>>>(xh, w1h, w1l, b1,
                                               nullptr, kqvh, kqvl,
                                               MROWS, 3 * DD, DD);
    }
    // 2) causal retention attention
    {
        dim3 grid(TT / 128, HH, BB);
        attn_mma<<<grid, 256, ATT_SMEM>>>(kqvh, kqvl, aoh);
    }
    // 3) out = ao @ W2 + b2  (fp32 output)
    {
        dim3 grid(DD / 128, MROWS / 128);
        gemm_h<false><<<grid, 256, GEMM_SMEM>>>(aoh, w2h, w2l, b2,
                                                out, nullptr, nullptr,
                                                MROWS, DD, DD);
    }
}

// round 6
// speedup vs baseline: 3.8541x; 1.0636x over previous
#include <cuda_runtime.h>
#include <cuda_fp16.h>

#define BB 2
#define TT 2048
#define DD 1024
#define HH 16
#define DH 64
#define MROWS (BB*TT)
#define KQV_LD (3*DD)

// fp16 operands (device globals; allocation is forbidden)
__device__ __half g_xh [(size_t)MROWS*DD];
__device__ __half g_w1h[(size_t)DD*3*DD], g_w1l[(size_t)DD*3*DD];   // natural [K][N]
__device__ __half g_w2h[(size_t)DD*DD],   g_w2l[(size_t)DD*DD];
__device__ __half g_kqvh[(size_t)MROWS*3*DD], g_kqvl[(size_t)MROWS*3*DD];
__device__ __half g_aoh[(size_t)MROWS*DD];

// ---------------------------------------------------------------------------
// helpers
// ---------------------------------------------------------------------------
__device__ __forceinline__ unsigned h2_pack(__half a, __half b) {
    __half2 t = __halves2half2(a, b);
    return *reinterpret_cast<unsigned*>(&t);
}
__device__ __forceinline__ void hsplit2(float x, float y, unsigned &hi, unsigned &lo) {
    __half hx = __float2half_rn(x), hy = __float2half_rn(y);
    __half lx = __float2half_rn(x - __half2float(hx));
    __half ly = __float2half_rn(y - __half2float(hy));
    hi = h2_pack(hx, hy);
    lo = h2_pack(lx, ly);
}
__device__ __forceinline__ unsigned hpack2(float x, float y) {
    return h2_pack(__float2half_rn(x), __float2half_rn(y));
}
__device__ __forceinline__ void mma16816(float* c,
    unsigned a0, unsigned a1, unsigned a2, unsigned a3,
    unsigned b0, unsigned b1)
{
    asm volatile(
        "mma.sync.aligned.m16n8k16.row.col.f32.f16.f16.f32 "
        "{%0,%1,%2,%3},{%4,%5,%6,%7},{%8,%9},{%0,%1,%2,%3};\n"
        : "+f"(c[0]), "+f"(c[1]), "+f"(c[2]), "+f"(c[3])
        : "r"(a0), "r"(a1), "r"(a2), "r"(a3), "r"(b0), "r"(b1));
}
__device__ __forceinline__ void ldsm4(unsigned* r, const void* p) {
    unsigned a = (unsigned)__cvta_generic_to_shared(p);
    asm volatile("ldmatrix.sync.aligned.m8n8.x4.shared.b16 {%0,%1,%2,%3}, [%4];\n"
        : "=r"(r[0]), "=r"(r[1]), "=r"(r[2]), "=r"(r[3]) : "r"(a));
}
__device__ __forceinline__ void ldsm4t(unsigned* r, const void* p) {
    unsigned a = (unsigned)__cvta_generic_to_shared(p);
    asm volatile("ldmatrix.sync.aligned.m8n8.x4.trans.shared.b16 {%0,%1,%2,%3}, [%4];\n"
        : "=r"(r[0]), "=r"(r[1]), "=r"(r[2]), "=r"(r[3]) : "r"(a));
}
__device__ __forceinline__ void cp16(void* sp, const void* gp) {
    unsigned s = (unsigned)__cvta_generic_to_shared(sp);
    asm volatile("cp.async.cg.shared.global [%0], [%1], 16;\n" :: "r"(s), "l"(gp));
}
#define CP_COMMIT() asm volatile("cp.async.commit_group;\n")
#define CP_WAIT(n)  asm volatile("cp.async.wait_group %0;\n" :: "n"(n))

// ---------------------------------------------------------------------------
// prep kernels
// ---------------------------------------------------------------------------
__global__ void round_kernel(const float* __restrict__ in,
                             __half* __restrict__ hi, int n4)
{
    int i = blockIdx.x * blockDim.x + threadIdx.x;
    if (i >= n4) return;
    float4 v = reinterpret_cast<const float4*>(in)[i];
    reinterpret_cast<uint2*>(hi)[i] = make_uint2(hpack2(v.x, v.y), hpack2(v.z, v.w));
}
__global__ void split_kernel(const float* __restrict__ in,
                             __half* __restrict__ hi, __half* __restrict__ lo, int n4)
{
    int i = blockIdx.x * blockDim.x + threadIdx.x;
    if (i >= n4) return;
    float4 v = reinterpret_cast<const float4*>(in)[i];
    unsigned h0, l0, h1, l1;
    hsplit2(v.x, v.y, h0, l0);
    hsplit2(v.z, v.w, h1, l1);
    reinterpret_cast<uint2*>(hi)[i] = make_uint2(h0, h1);
    reinterpret_cast<uint2*>(lo)[i] = make_uint2(l0, l1);
}

// ---------------------------------------------------------------------------
// fp16 2-product GEMM: C = A @ B + bias  (A hi-only, B split hi/lo)
// CTA 128x128, BK=32, 2-stage cp.async, 4 warps (2m x 2n), warp tile 64x64.
// ---------------------------------------------------------------------------
#define APG 40
#define BPG 136
#define SA_ST (128*APG)
#define SB_ST (32*BPG)
#define GEMM_SMEM ((2*SA_ST + 2*2*SB_ST) * 2)   // 55296 B

#define GEMM_LOAD(s, k0)                                                        \
    {                                                                           \
        _Pragma("unroll")                                                       \
        for (int j = 0; j < 4; j++) {                                           \
            const int id = tid + 128 * j;                                       \
            const int arow = id >> 2, ac = (id & 3) * 8;                        \
            const size_t ga = (size_t)(m0 + arow) * K + (k0) + ac;              \
            cp16(sA + (s)*SA_ST + arow*APG + ac, Ah_g + ga);                    \
            const int brow = id >> 4, bc = (id & 15) * 8;                       \
            const size_t gb = (size_t)((k0) + brow) * N + n0 + bc;              \
            cp16(sB + ((s)*2+0)*SB_ST + brow*BPG + bc, Bh_g + gb);              \
            cp16(sB + ((s)*2+1)*SB_ST + brow*BPG + bc, Bl_g + gb);              \
        }                                                                       \
        CP_COMMIT();                                                            \
    }

template<bool SPLIT_OUT>
__global__ __launch_bounds__(128, 2) void gemm_h(
    const __half* __restrict__ Ah_g,
    const __half* __restrict__ Bh_g, const __half* __restrict__ Bl_g,
    const float* __restrict__ bias,
    float* __restrict__ C, __half* __restrict__ Ch, __half* __restrict__ Cl,
    int M, int N, int K)
{
    extern __shared__ __half smg[];
    __half* sA = smg;                       // [stage][128*APG]
    __half* sB = smg + 2*SA_ST;             // [stage][half][32*BPG] natural [k][n]

    const int tid = threadIdx.x, warp = tid >> 5, lane = tid & 31;
    const int m0 = blockIdx.y * 128, n0 = blockIdx.x * 128;
    const int wm = (warp & 1) * 64, wn = (warp >> 1) * 64;

    float acc[4][8][4];
#pragma unroll
    for (int i = 0; i < 4; i++)
#pragma unroll
        for (int j = 0; j < 8; j++)
#pragma unroll
            for (int l = 0; l < 4; l++) acc[i][j][l] = 0.f;

    GEMM_LOAD(0, 0);

    const int ntiles = K / 32;
    for (int t = 0; t < ntiles; t++) {
        CP_WAIT(0);
        __syncthreads();
        if (t + 1 < ntiles) GEMM_LOAD((t + 1) & 1, (t + 1) * 32);

        const int s = t & 1;
        const __half* Ahs = sA + s*SA_ST;
        const __half* Bhs = sB + (s*2+0)*SB_ST;
        const __half* Bls = sB + (s*2+1)*SB_ST;

#pragma unroll
        for (int ks = 0; ks < 32; ks += 16) {
            unsigned bh[4][4], bl[4][4];
            const int brr = ks + (lane & 8) + (lane & 7);
#pragma unroll
            for (int np = 0; np < 4; np++) {
                const int bcc = wn + np * 16 + ((lane >> 1) & 8);
                ldsm4t(bh[np], Bhs + brr * BPG + bcc);
                ldsm4t(bl[np], Bls + brr * BPG + bcc);
            }
#pragma unroll
            for (int mt = 0; mt < 4; mt++) {
                unsigned ah[4];
                const int r = (wm + mt * 16 + (lane & 15)) * APG + ks + ((lane & 16) >> 1);
                ldsm4(ah, Ahs + r);
#pragma unroll
                for (int nt = 0; nt < 8; nt++) {
                    const unsigned b0h = bh[nt >> 1][(nt & 1) * 2], b1h = bh[nt >> 1][(nt & 1) * 2 + 1];
                    const unsigned b0l = bl[nt >> 1][(nt & 1) * 2], b1l = bl[nt >> 1][(nt & 1) * 2 + 1];
                    mma16816(acc[mt][nt], ah[0], ah[1], ah[2], ah[3], b0h, b1h);
                    mma16816(acc[mt][nt], ah[0], ah[1], ah[2], ah[3], b0l, b1l);
                }
            }
        }
        __syncthreads();
    }

    const int g = lane >> 2, tg = lane & 3;
#pragma unroll
    for (int mt = 0; mt < 4; mt++) {
        const int r = m0 + wm + mt * 16 + g;
#pragma unroll
        for (int nt = 0; nt < 8; nt++) {
            const int c = n0 + wn + nt * 8 + tg * 2;
            const float bx = bias[c], by = bias[c + 1];
            const float v0 = acc[mt][nt][0] + bx, v1 = acc[mt][nt][1] + by;
            const float v2 = acc[mt][nt][2] + bx, v3 = acc[mt][nt][3] + by;
            if (SPLIT_OUT) {
                unsigned h0, l0, h1, l1;
                hsplit2(v0, v1, h0, l0);
                hsplit2(v2, v3, h1, l1);
                *reinterpret_cast<unsigned*>(&Ch[(size_t)r * N + c])       = h0;
                *reinterpret_cast<unsigned*>(&Cl[(size_t)r * N + c])       = l0;
                *reinterpret_cast<unsigned*>(&Ch[(size_t)(r + 8) * N + c]) = h1;
                *reinterpret_cast<unsigned*>(&Cl[(size_t)(r + 8) * N + c]) = l1;
            } else {
                float2 o0 = {v0, v1}, o1 = {v2, v3};
                *reinterpret_cast<float2*>(&C[(size_t)r * N + c])       = o0;
                *reinterpret_cast<float2*>(&C[(size_t)(r + 8) * N + c]) = o1;
            }
        }
    }
}

// ---------------------------------------------------------------------------
// Fused causal retention attention, fp16 2-product (unchanged from R5).
// ---------------------------------------------------------------------------
#define AP 72
#define ATT_SMEM ((128*AP + 4*64*AP + 128*AP) * 2)   // 73728 B

__global__ __launch_bounds__(256, 2) void attn_mma(
    const __half* __restrict__ kqvh, const __half* __restrict__ kqvl,
    __half* __restrict__ aoh)
{
    extern __shared__ __half sma[];
    __half *Qh = sma;
    __half *Kh = Qh + 128 * AP, *Kl = Kh + 64 * AP;
    __half *Vh = Kl + 64 * AP,  *Vl = Vh + 64 * AP;
    __half *Sh = Vl + 64 * AP;

    const int tid = threadIdx.x, warp = tid >> 5, lane = tid & 31;
    const int g = lane >> 2, tg = lane & 3;
    const int qb = gridDim.x - 1 - blockIdx.x;    // heavy tiles first
    const int h = blockIdx.y, b = blockIdx.z;
    const int q0 = qb * 128;

    const size_t hoff = (size_t)b * TT * KQV_LD + h * DH;
    const __half *Khg = kqvh + hoff, *Klg = kqvl + hoff;
    const __half *Qhg = Khg + DD;
    const __half *Vhg = Khg + 2*DD, *Vlg = Klg + 2*DD;

    // load Q tile 128x64 (hi only)
#pragma unroll
    for (int j = 0; j < 4; j++) {
        const int id = tid * 4 + j;
        const int row = id >> 3, c8 = (id & 7) * 8;
        const size_t gq = (size_t)(q0 + row) * KQV_LD + c8;
        *reinterpret_cast<uint4*>(&Qh[row * AP + c8]) = *reinterpret_cast<const uint4*>(&Qhg[gq]);
    }

    const int wq = (warp & 1) * 64;
    const int wk = (warp >> 1) * 16;

    float oacc[4][2][4];
#pragma unroll
    for (int i = 0; i < 4; i++)
#pragma unroll
        for (int j = 0; j < 2; j++)
#pragma unroll
            for (int l = 0; l < 4; l++) oacc[i][j][l] = 0.f;

    const int nkb = 2 * qb + 2;
    for (int kb = 0; kb < nkb; kb++) {
        const int k0 = kb * 64;

        // prefetch K/V (hi/lo) into registers — overlaps previous O-mma
        uint4 pkh[2], pkl[2], pvh[2], pvl[2];
#pragma unroll
        for (int j = 0; j < 2; j++) {
            const int id = tid * 2 + j;
            const int row = id >> 3, c8 = (id & 7) * 8;
            const size_t gk = (size_t)(k0 + row) * KQV_LD + c8;
            pkh[j] = *reinterpret_cast<const uint4*>(&Khg[gk]);
            pkl[j] = *reinterpret_cast<const uint4*>(&Klg[gk]);
            pvh[j] = *reinterpret_cast<const uint4*>(&Vhg[gk]);
            pvl[j] = *reinterpret_cast<const uint4*>(&Vlg[gk]);
        }
        __syncthreads();   // prev O-mma done with K/V/S (and Q load, iter 0)

#pragma unroll
        for (int j = 0; j < 2; j++) {
            const int id = tid * 2 + j;
            const int row = id >> 3, c8 = (id & 7) * 8;
            *reinterpret_cast<uint4*>(&Kh[row * AP + c8]) = pkh[j];
            *reinterpret_cast<uint4*>(&Kl[row * AP + c8]) = pkl[j];
            *reinterpret_cast<uint4*>(&Vh[row * AP + c8]) = pvh[j];
            *reinterpret_cast<uint4*>(&Vl[row * AP + c8]) = pvl[j];
        }
        __syncthreads();

        // ---- S = Q K^T (warp: 64q x 16k) ----
        float sacc[4][2][4];
#pragma unroll
        for (int i = 0; i < 4; i++)
#pragma unroll
            for (int j = 0; j < 2; j++)
#pragma unroll
                for (int l = 0; l < 4; l++) sacc[i][j][l] = 0.f;

#pragma unroll
        for (int ds = 0; ds < 64; ds += 16) {
            unsigned bh[4], bl[4];
            const int kr = wk + ((lane >> 1) & 8) + (lane & 7);
            const int kc = ds + (lane & 8);
            ldsm4(bh, Kh + kr * AP + kc);
            ldsm4(bl, Kl + kr * AP + kc);
#pragma unroll
            for (int mt = 0; mt < 4; mt++) {
                unsigned qh[4];
                const int r = (wq + mt * 16 + (lane & 15)) * AP + ds + ((lane & 16) >> 1);
                ldsm4(qh, Qh + r);
#pragma unroll
                for (int nt = 0; nt < 2; nt++) {
                    mma16816(sacc[mt][nt], qh[0], qh[1], qh[2], qh[3], bh[nt*2], bh[nt*2+1]);
                    mma16816(sacc[mt][nt], qh[0], qh[1], qh[2], qh[3], bl[nt*2], bl[nt*2+1]);
                }
            }
        }

        // mask (diagonal) + store S (hi only)
        const bool diag = (kb >= 2 * qb);
#pragma unroll
        for (int mt = 0; mt < 4; mt++) {
            const int qr = wq + mt * 16 + g;
#pragma unroll
            for (int nt = 0; nt < 2; nt++) {
                const int kc = wk + nt * 8 + tg * 2;
                float s0 = sacc[mt][nt][0], s1 = sacc[mt][nt][1];
                float s2 = sacc[mt][nt][2], s3 = sacc[mt][nt][3];
                if (diag) {
                    const int qg0 = q0 + qr, qg8 = qg0 + 8, kg = k0 + kc;
                    if (kg     > qg0) s0 = 0.f;
                    if (kg + 1 > qg0) s1 = 0.f;
                    if (kg     > qg8) s2 = 0.f;
                    if (kg + 1 > qg8) s3 = 0.f;
                }
                const int idx = qr * AP + kc;
                *reinterpret_cast<unsigned*>(&Sh[idx])          = hpack2(s0, s1);
                *reinterpret_cast<unsigned*>(&Sh[idx + 8 * AP]) = hpack2(s2, s3);
            }
        }
        __syncthreads();

        // ---- O += S V (warp: 64q x 16d) ----
#pragma unroll
        for (int ks = 0; ks < 64; ks += 16) {
            unsigned vh4[4], vl4[4];
            const int vr = ks + (lane & 8) + (lane & 7);
            const int vc = wk + ((lane >> 1) & 8);
            ldsm4t(vh4, Vh + vr * AP + vc);
            ldsm4t(vl4, Vl + vr * AP + vc);
#pragma unroll
            for (int mt = 0; mt < 4; mt++) {
                unsigned sh4[4];
                const int r = (wq + mt * 16 + (lane & 15)) * AP + ks + ((lane & 16) >> 1);
                ldsm4(sh4, Sh + r);
#pragma unroll
                for (int nt = 0; nt < 2; nt++) {
                    mma16816(oacc[mt][nt], sh4[0], sh4[1], sh4[2], sh4[3], vh4[nt*2], vh4[nt*2+1]);
                    mma16816(oacc[mt][nt], sh4[0], sh4[1], sh4[2], sh4[3], vl4[nt*2], vl4[nt*2+1]);
                }
            }
        }
    }

    // write O (hi only) -> aoh[b*TT + q, h*64 + d]
#pragma unroll
    for (int mt = 0; mt < 4; mt++) {
        const size_t t = (size_t)b * TT + q0 + wq + mt * 16 + g;
#pragma unroll
        for (int nt = 0; nt < 2; nt++) {
            const int c = h * DH + wk + nt * 8 + tg * 2;
            *reinterpret_cast<unsigned*>(&aoh[t * DD + c])       = hpack2(oacc[mt][nt][0], oacc[mt][nt][1]);
            *reinterpret_cast<unsigned*>(&aoh[(t + 8) * DD + c]) = hpack2(oacc[mt][nt][2], oacc[mt][nt][3]);
        }
    }
}

// ---------------------------------------------------------------------------
extern "C" void kernel_launch(void* const* d_in, const int* in_sizes, int n_in,
                              void* d_out, int out_size)
{
    const float* x  = (const float*)d_in[0];
    const float* W1 = (const float*)d_in[1];
    const float* b1 = (const float*)d_in[2];
    const float* W2 = (const float*)d_in[3];
    const float* b2 = (const float*)d_in[4];
    float* out = (float*)d_out;

    __half *xh, *w1h, *w1l, *w2h, *w2l, *kqvh, *kqvl, *aoh;
    cudaGetSymbolAddress((void**)&xh,  g_xh);
    cudaGetSymbolAddress((void**)&w1h, g_w1h);  cudaGetSymbolAddress((void**)&w1l, g_w1l);
    cudaGetSymbolAddress((void**)&w2h, g_w2h);  cudaGetSymbolAddress((void**)&w2l, g_w2l);
    cudaGetSymbolAddress((void**)&kqvh, g_kqvh); cudaGetSymbolAddress((void**)&kqvl, g_kqvl);
    cudaGetSymbolAddress((void**)&aoh, g_aoh);

    cudaFuncSetAttribute(gemm_h<true>,
                         cudaFuncAttributeMaxDynamicSharedMemorySize, GEMM_SMEM);
    cudaFuncSetAttribute(gemm_h<false>,
                         cudaFuncAttributeMaxDynamicSharedMemorySize, GEMM_SMEM);
    cudaFuncSetAttribute(attn_mma,
                         cudaFuncAttributeMaxDynamicSharedMemorySize, ATT_SMEM);

    // 0) x -> fp16 hi; W1/W2 -> fp16 hi/lo
    {
        int n4;
        n4 = MROWS * DD / 4;   round_kernel<<<(n4 + 255) / 256, 256>>>(x, xh, n4);
        n4 = DD * 3 * DD / 4;  split_kernel<<<(n4 + 255) / 256, 256>>>(W1, w1h, w1l, n4);
        n4 = DD * DD / 4;      split_kernel<<<(n4 + 255) / 256, 256>>>(W2, w2h, w2l, n4);
    }
    // 1) kqv = x @ W1 + b1  (split fp16 output)
    {
        dim3 grid(3 * DD / 128, MROWS / 128);
        gemm_h<true><<<grid, 128, GEMM_SMEM>>>(xh, w1h, w1l, b1,
                                               nullptr, kqvh, kqvl,
                                               MROWS, 3 * DD, DD);
    }
    // 2) causal retention attention
    {
        dim3 grid(TT / 128, HH, BB);
        attn_mma<<<grid, 256, ATT_SMEM>>>(kqvh, kqvl, aoh);
    }
    // 3) out = ao @ W2 + b2  (fp32 output)
    {
        dim3 grid(DD / 128, MROWS / 128);
        gemm_h<false><<<grid, 128, GEMM_SMEM>>>(aoh, w2h, w2l, b2,
                                                out, nullptr, nullptr,
                                                MROWS, DD, DD);
    }
}

// round 7
// speedup vs baseline: 3.9162x; 1.0161x over previous
#include <cuda_runtime.h>
#include <cuda_fp16.h>

#define BB 2
#define TT 2048
#define DD 1024
#define HH 16
#define DH 64
#define MROWS (BB*TT)
#define KQV_LD (3*DD)

// fp16 operands (device globals; allocation is forbidden)
__device__ __half g_xh [(size_t)MROWS*DD];
__device__ __half g_w1h[(size_t)DD*3*DD], g_w1l[(size_t)DD*3*DD];   // natural [K][N]
__device__ __half g_w2h[(size_t)DD*DD],   g_w2l[(size_t)DD*DD];
__device__ __half g_kqvh[(size_t)MROWS*3*DD], g_kqvl[(size_t)MROWS*3*DD];
__device__ __half g_aoh[(size_t)MROWS*DD];

// ---------------------------------------------------------------------------
// helpers
// ---------------------------------------------------------------------------
__device__ __forceinline__ unsigned h2_pack(__half a, __half b) {
    __half2 t = __halves2half2(a, b);
    return *reinterpret_cast<unsigned*>(&t);
}
__device__ __forceinline__ void hsplit2(float x, float y, unsigned &hi, unsigned &lo) {
    __half hx = __float2half_rn(x), hy = __float2half_rn(y);
    __half lx = __float2half_rn(x - __half2float(hx));
    __half ly = __float2half_rn(y - __half2float(hy));
    hi = h2_pack(hx, hy);
    lo = h2_pack(lx, ly);
}
__device__ __forceinline__ unsigned hpack2(float x, float y) {
    return h2_pack(__float2half_rn(x), __float2half_rn(y));
}
__device__ __forceinline__ void mma16816(float* c,
    unsigned a0, unsigned a1, unsigned a2, unsigned a3,
    unsigned b0, unsigned b1)
{
    asm volatile(
        "mma.sync.aligned.m16n8k16.row.col.f32.f16.f16.f32 "
        "{%0,%1,%2,%3},{%4,%5,%6,%7},{%8,%9},{%0,%1,%2,%3};\n"
        : "+f"(c[0]), "+f"(c[1]), "+f"(c[2]), "+f"(c[3])
        : "r"(a0), "r"(a1), "r"(a2), "r"(a3), "r"(b0), "r"(b1));
}
__device__ __forceinline__ void ldsm4(unsigned* r, const void* p) {
    unsigned a = (unsigned)__cvta_generic_to_shared(p);
    asm volatile("ldmatrix.sync.aligned.m8n8.x4.shared.b16 {%0,%1,%2,%3}, [%4];\n"
        : "=r"(r[0]), "=r"(r[1]), "=r"(r[2]), "=r"(r[3]) : "r"(a));
}
__device__ __forceinline__ void ldsm4t(unsigned* r, const void* p) {
    unsigned a = (unsigned)__cvta_generic_to_shared(p);
    asm volatile("ldmatrix.sync.aligned.m8n8.x4.trans.shared.b16 {%0,%1,%2,%3}, [%4];\n"
        : "=r"(r[0]), "=r"(r[1]), "=r"(r[2]), "=r"(r[3]) : "r"(a));
}
__device__ __forceinline__ void cp16(void* sp, const void* gp) {
    unsigned s = (unsigned)__cvta_generic_to_shared(sp);
    asm volatile("cp.async.cg.shared.global [%0], [%1], 16;\n" :: "r"(s), "l"(gp));
}
#define CP_COMMIT() asm volatile("cp.async.commit_group;\n")
#define CP_WAIT(n)  asm volatile("cp.async.wait_group %0;\n" :: "n"(n))

// ---------------------------------------------------------------------------
// prep kernels
// ---------------------------------------------------------------------------
__global__ void round_kernel(const float* __restrict__ in,
                             __half* __restrict__ hi, int n4)
{
    int i = blockIdx.x * blockDim.x + threadIdx.x;
    if (i >= n4) return;
    float4 v = reinterpret_cast<const float4*>(in)[i];
    reinterpret_cast<uint2*>(hi)[i] = make_uint2(hpack2(v.x, v.y), hpack2(v.z, v.w));
}
__global__ void split_kernel(const float* __restrict__ in,
                             __half* __restrict__ hi, __half* __restrict__ lo, int n4)
{
    int i = blockIdx.x * blockDim.x + threadIdx.x;
    if (i >= n4) return;
    float4 v = reinterpret_cast<const float4*>(in)[i];
    unsigned h0, l0, h1, l1;
    hsplit2(v.x, v.y, h0, l0);
    hsplit2(v.z, v.w, h1, l1);
    reinterpret_cast<uint2*>(hi)[i] = make_uint2(h0, h1);
    reinterpret_cast<uint2*>(lo)[i] = make_uint2(l0, l1);
}

// ---------------------------------------------------------------------------
// fp16 2-product GEMM: C = A @ B + bias  (A hi-only, B split hi/lo)
// CTA 128x128, BK=32, 3-stage cp.async, 4 warps (2m x 2n), warp tile 64x64.
// ---------------------------------------------------------------------------
#define APG 40
#define BPG 136
#define SA_ST (128*APG)
#define SB_ST (32*BPG)
#define NSG 3
#define GEMM_SMEM ((NSG*SA_ST + NSG*2*SB_ST) * 2)   // 82944 B

#define GEMM_LOAD(s, k0)                                                        \
    {                                                                           \
        _Pragma("unroll")                                                       \
        for (int j = 0; j < 4; j++) {                                           \
            const int id = tid + 128 * j;                                       \
            const int arow = id >> 2, ac = (id & 3) * 8;                        \
            const size_t ga = (size_t)(m0 + arow) * K + (k0) + ac;              \
            cp16(sA + (s)*SA_ST + arow*APG + ac, Ah_g + ga);                    \
            const int brow = id >> 4, bc = (id & 15) * 8;                       \
            const size_t gb = (size_t)((k0) + brow) * N + n0 + bc;              \
            cp16(sB + ((s)*2+0)*SB_ST + brow*BPG + bc, Bh_g + gb);              \
            cp16(sB + ((s)*2+1)*SB_ST + brow*BPG + bc, Bl_g + gb);              \
        }                                                                       \
        CP_COMMIT();                                                            \
    }

template<bool SPLIT_OUT>
__global__ __launch_bounds__(128, 2) void gemm_h(
    const __half* __restrict__ Ah_g,
    const __half* __restrict__ Bh_g, const __half* __restrict__ Bl_g,
    const float* __restrict__ bias,
    float* __restrict__ C, __half* __restrict__ Ch, __half* __restrict__ Cl,
    int M, int N, int K)
{
    extern __shared__ __half smg[];
    __half* sA = smg;                       // [stage][128*APG]
    __half* sB = smg + NSG*SA_ST;           // [stage][half][32*BPG] natural [k][n]

    const int tid = threadIdx.x, warp = tid >> 5, lane = tid & 31;
    const int m0 = blockIdx.y * 128, n0 = blockIdx.x * 128;
    const int wm = (warp & 1) * 64, wn = (warp >> 1) * 64;

    float acc[4][8][4];
#pragma unroll
    for (int i = 0; i < 4; i++)
#pragma unroll
        for (int j = 0; j < 8; j++)
#pragma unroll
            for (int l = 0; l < 4; l++) acc[i][j][l] = 0.f;

    GEMM_LOAD(0, 0);
    GEMM_LOAD(1, 32);

    const int ntiles = K / 32;
    for (int t = 0; t < ntiles; t++) {
        if (t + 1 < ntiles) { CP_WAIT(1); } else { CP_WAIT(0); }
        __syncthreads();      // stage t visible to all; all warps done with stage (t-1)
        if (t + 2 < ntiles) GEMM_LOAD((t + 2) % NSG, (t + 2) * 32);

        const int s = t % NSG;
        const __half* Ahs = sA + s*SA_ST;
        const __half* Bhs = sB + (s*2+0)*SB_ST;
        const __half* Bls = sB + (s*2+1)*SB_ST;

#pragma unroll
        for (int ks = 0; ks < 32; ks += 16) {
            unsigned bh[4][4], bl[4][4];
            const int brr = ks + (lane & 8) + (lane & 7);
#pragma unroll
            for (int np = 0; np < 4; np++) {
                const int bcc = wn + np * 16 + ((lane >> 1) & 8);
                ldsm4t(bh[np], Bhs + brr * BPG + bcc);
                ldsm4t(bl[np], Bls + brr * BPG + bcc);
            }
#pragma unroll
            for (int mt = 0; mt < 4; mt++) {
                unsigned ah[4];
                const int r = (wm + mt * 16 + (lane & 15)) * APG + ks + ((lane & 16) >> 1);
                ldsm4(ah, Ahs + r);
#pragma unroll
                for (int nt = 0; nt < 8; nt++) {
                    const unsigned b0h = bh[nt >> 1][(nt & 1) * 2], b1h = bh[nt >> 1][(nt & 1) * 2 + 1];
                    const unsigned b0l = bl[nt >> 1][(nt & 1) * 2], b1l = bl[nt >> 1][(nt & 1) * 2 + 1];
                    mma16816(acc[mt][nt], ah[0], ah[1], ah[2], ah[3], b0h, b1h);
                    mma16816(acc[mt][nt], ah[0], ah[1], ah[2], ah[3], b0l, b1l);
                }
            }
        }
    }

    const int g = lane >> 2, tg = lane & 3;
#pragma unroll
    for (int mt = 0; mt < 4; mt++) {
        const int r = m0 + wm + mt * 16 + g;
#pragma unroll
        for (int nt = 0; nt < 8; nt++) {
            const int c = n0 + wn + nt * 8 + tg * 2;
            const float bx = bias[c], by = bias[c + 1];
            const float v0 = acc[mt][nt][0] + bx, v1 = acc[mt][nt][1] + by;
            const float v2 = acc[mt][nt][2] + bx, v3 = acc[mt][nt][3] + by;
            if (SPLIT_OUT) {
                unsigned h0, l0, h1, l1;
                hsplit2(v0, v1, h0, l0);
                hsplit2(v2, v3, h1, l1);
                *reinterpret_cast<unsigned*>(&Ch[(size_t)r * N + c])       = h0;
                *reinterpret_cast<unsigned*>(&Cl[(size_t)r * N + c])       = l0;
                *reinterpret_cast<unsigned*>(&Ch[(size_t)(r + 8) * N + c]) = h1;
                *reinterpret_cast<unsigned*>(&Cl[(size_t)(r + 8) * N + c]) = l1;
            } else {
                float2 o0 = {v0, v1}, o1 = {v2, v3};
                *reinterpret_cast<float2*>(&C[(size_t)r * N + c])       = o0;
                *reinterpret_cast<float2*>(&C[(size_t)(r + 8) * N + c]) = o1;
            }
        }
    }
}

// ---------------------------------------------------------------------------
// Fused causal retention attention, fp16 2-product.
// K/V double-buffered via cp.async (load kb+1 overlaps compute kb).
// Block (b, h, 128 q-rows), k-tiles of 64, 8 warps = 2(q:64) x 4(16-wide).
// ---------------------------------------------------------------------------
#define AP 72
#define KV_ST (64*AP)                 // one K or V (hi or lo) tile
#define KVBUF (4*KV_ST)               // Kh,Kl,Vh,Vl for one stage
#define ATT_SMEM ((128*AP + 2*KVBUF + 128*AP) * 2)   // 110592 B

#define ATT_LOAD(kb)                                                           \
    {                                                                          \
        const int _k0 = (kb) * 64;                                             \
        __half* _buf = KV + ((kb) & 1) * KVBUF;                                \
        _Pragma("unroll")                                                      \
        for (int _j = 0; _j < 2; _j++) {                                       \
            const int _id = tid * 2 + _j;                                      \
            const int _row = _id >> 3, _c8 = (_id & 7) * 8;                    \
            const size_t _g = (size_t)(_k0 + _row) * KQV_LD + _c8;             \
            const int _d = _row * AP + _c8;                                    \
            cp16(_buf + 0*KV_ST + _d, Khg + _g);                               \
            cp16(_buf + 1*KV_ST + _d, Klg + _g);                               \
            cp16(_buf + 2*KV_ST + _d, Vhg + _g);                               \
            cp16(_buf + 3*KV_ST + _d, Vlg + _g);                               \
        }                                                                      \
        CP_COMMIT();                                                           \
    }

__global__ __launch_bounds__(256, 2) void attn_mma(
    const __half* __restrict__ kqvh, const __half* __restrict__ kqvl,
    __half* __restrict__ aoh)
{
    extern __shared__ __half sma[];
    __half *Qh = sma;
    __half *KV = Qh + 128 * AP;           // [2][Kh|Kl|Vh|Vl][64*AP]
    __half *Sh = KV + 2 * KVBUF;

    const int tid = threadIdx.x, warp = tid >> 5, lane = tid & 31;
    const int g = lane >> 2, tg = lane & 3;
    const int qb = gridDim.x - 1 - blockIdx.x;    // heavy tiles first
    const int h = blockIdx.y, b = blockIdx.z;
    const int q0 = qb * 128;

    const size_t hoff = (size_t)b * TT * KQV_LD + h * DH;
    const __half *Khg = kqvh + hoff, *Klg = kqvl + hoff;
    const __half *Qhg = Khg + DD;
    const __half *Vhg = Khg + 2*DD, *Vlg = Klg + 2*DD;

    // prologue: start K/V load for kb=0
    ATT_LOAD(0);

    // load Q tile 128x64 (hi only) via plain vector loads
#pragma unroll
    for (int j = 0; j < 4; j++) {
        const int id = tid * 4 + j;
        const int row = id >> 3, c8 = (id & 7) * 8;
        const size_t gq = (size_t)(q0 + row) * KQV_LD + c8;
        *reinterpret_cast<uint4*>(&Qh[row * AP + c8]) = *reinterpret_cast<const uint4*>(&Qhg[gq]);
    }

    const int wq = (warp & 1) * 64;
    const int wk = (warp >> 1) * 16;

    float oacc[4][2][4];
#pragma unroll
    for (int i = 0; i < 4; i++)
#pragma unroll
        for (int j = 0; j < 2; j++)
#pragma unroll
            for (int l = 0; l < 4; l++) oacc[i][j][l] = 0.f;

    const int nkb = 2 * qb + 2;
    for (int kb = 0; kb < nkb; kb++) {
        const int k0 = kb * 64;
        CP_WAIT(0);           // K/V tile kb in smem
        __syncthreads();      // visible to all; prev iter done with S/KV

        if (kb + 1 < nkb) ATT_LOAD(kb + 1);   // overlaps this iter's compute

        const __half* buf = KV + (kb & 1) * KVBUF;
        const __half* Khs = buf + 0*KV_ST;
        const __half* Kls = buf + 1*KV_ST;
        const __half* Vhs = buf + 2*KV_ST;
        const __half* Vls = buf + 3*KV_ST;

        // ---- S = Q K^T (warp: 64q x 16k) ----
        float sacc[4][2][4];
#pragma unroll
        for (int i = 0; i < 4; i++)
#pragma unroll
            for (int j = 0; j < 2; j++)
#pragma unroll
                for (int l = 0; l < 4; l++) sacc[i][j][l] = 0.f;

#pragma unroll
        for (int ds = 0; ds < 64; ds += 16) {
            unsigned bh[4], bl[4];
            const int kr = wk + ((lane >> 1) & 8) + (lane & 7);
            const int kc = ds + (lane & 8);
            ldsm4(bh, Khs + kr * AP + kc);
            ldsm4(bl, Kls + kr * AP + kc);
#pragma unroll
            for (int mt = 0; mt < 4; mt++) {
                unsigned qh[4];
                const int r = (wq + mt * 16 + (lane & 15)) * AP + ds + ((lane & 16) >> 1);
                ldsm4(qh, Qh + r);
#pragma unroll
                for (int nt = 0; nt < 2; nt++) {
                    mma16816(sacc[mt][nt], qh[0], qh[1], qh[2], qh[3], bh[nt*2], bh[nt*2+1]);
                    mma16816(sacc[mt][nt], qh[0], qh[1], qh[2], qh[3], bl[nt*2], bl[nt*2+1]);
                }
            }
        }

        // mask (diagonal) + store S (hi only)
        const bool diag = (kb >= 2 * qb);
#pragma unroll
        for (int mt = 0; mt < 4; mt++) {
            const int qr = wq + mt * 16 + g;
#pragma unroll
            for (int nt = 0; nt < 2; nt++) {
                const int kc = wk + nt * 8 + tg * 2;
                float s0 = sacc[mt][nt][0], s1 = sacc[mt][nt][1];
                float s2 = sacc[mt][nt][2], s3 = sacc[mt][nt][3];
                if (diag) {
                    const int qg0 = q0 + qr, qg8 = qg0 + 8, kg = k0 + kc;
                    if (kg     > qg0) s0 = 0.f;
                    if (kg + 1 > qg0) s1 = 0.f;
                    if (kg     > qg8) s2 = 0.f;
                    if (kg + 1 > qg8) s3 = 0.f;
                }
                const int idx = qr * AP + kc;
                *reinterpret_cast<unsigned*>(&Sh[idx])          = hpack2(s0, s1);
                *reinterpret_cast<unsigned*>(&Sh[idx + 8 * AP]) = hpack2(s2, s3);
            }
        }
        __syncthreads();

        // ---- O += S V (warp: 64q x 16d) ----
#pragma unroll
        for (int ks = 0; ks < 64; ks += 16) {
            unsigned vh4[4], vl4[4];
            const int vr = ks + (lane & 8) + (lane & 7);
            const int vc = wk + ((lane >> 1) & 8);
            ldsm4t(vh4, Vhs + vr * AP + vc);
            ldsm4t(vl4, Vls + vr * AP + vc);
#pragma unroll
            for (int mt = 0; mt < 4; mt++) {
                unsigned sh4[4];
                const int r = (wq + mt * 16 + (lane & 15)) * AP + ks + ((lane & 16) >> 1);
                ldsm4(sh4, Sh + r);
#pragma unroll
                for (int nt = 0; nt < 2; nt++) {
                    mma16816(oacc[mt][nt], sh4[0], sh4[1], sh4[2], sh4[3], vh4[nt*2], vh4[nt*2+1]);
                    mma16816(oacc[mt][nt], sh4[0], sh4[1], sh4[2], sh4[3], vl4[nt*2], vl4[nt*2+1]);
                }
            }
        }
    }

    // write O (hi only) -> aoh[b*TT + q, h*64 + d]
#pragma unroll
    for (int mt = 0; mt < 4; mt++) {
        const size_t t = (size_t)b * TT + q0 + wq + mt * 16 + g;
#pragma unroll
        for (int nt = 0; nt < 2; nt++) {
            const int c = h * DH + wk + nt * 8 + tg * 2;
            *reinterpret_cast<unsigned*>(&aoh[t * DD + c])       = hpack2(oacc[mt][nt][0], oacc[mt][nt][1]);
            *reinterpret_cast<unsigned*>(&aoh[(t + 8) * DD + c]) = hpack2(oacc[mt][nt][2], oacc[mt][nt][3]);
        }
    }
}

// ---------------------------------------------------------------------------
extern "C" void kernel_launch(void* const* d_in, const int* in_sizes, int n_in,
                              void* d_out, int out_size)
{
    const float* x  = (const float*)d_in[0];
    const float* W1 = (const float*)d_in[1];
    const float* b1 = (const float*)d_in[2];
    const float* W2 = (const float*)d_in[3];
    const float* b2 = (const float*)d_in[4];
    float* out = (float*)d_out;

    __half *xh, *w1h, *w1l, *w2h, *w2l, *kqvh, *kqvl, *aoh;
    cudaGetSymbolAddress((void**)&xh,  g_xh);
    cudaGetSymbolAddress((void**)&w1h, g_w1h);  cudaGetSymbolAddress((void**)&w1l, g_w1l);
    cudaGetSymbolAddress((void**)&w2h, g_w2h);  cudaGetSymbolAddress((void**)&w2l, g_w2l);
    cudaGetSymbolAddress((void**)&kqvh, g_kqvh); cudaGetSymbolAddress((void**)&kqvl, g_kqvl);
    cudaGetSymbolAddress((void**)&aoh, g_aoh);

    cudaFuncSetAttribute(gemm_h<true>,
                         cudaFuncAttributeMaxDynamicSharedMemorySize, GEMM_SMEM);
    cudaFuncSetAttribute(gemm_h<false>,
                         cudaFuncAttributeMaxDynamicSharedMemorySize, GEMM_SMEM);
    cudaFuncSetAttribute(attn_mma,
                         cudaFuncAttributeMaxDynamicSharedMemorySize, ATT_SMEM);

    // 0) x -> fp16 hi; W1/W2 -> fp16 hi/lo
    {
        int n4;
        n4 = MROWS * DD / 4;   round_kernel<<<(n4 + 255) / 256, 256>>>(x, xh, n4);
        n4 = DD * 3 * DD / 4;  split_kernel<<<(n4 + 255) / 256, 256>>>(W1, w1h, w1l, n4);
        n4 = DD * DD / 4;      split_kernel<<<(n4 + 255) / 256, 256>>>(W2, w2h, w2l, n4);
    }
    // 1) kqv = x @ W1 + b1  (split fp16 output)
    {
        dim3 grid(3 * DD / 128, MROWS / 128);
        gemm_h<true><<<grid, 128, GEMM_SMEM>>>(xh, w1h, w1l, b1,
                                               nullptr, kqvh, kqvl,
                                               MROWS, 3 * DD, DD);
    }
    // 2) causal retention attention
    {
        dim3 grid(TT / 128, HH, BB);
        attn_mma<<<grid, 256, ATT_SMEM>>>(kqvh, kqvl, aoh);
    }
    // 3) out = ao @ W2 + b2  (fp32 output)
    {
        dim3 grid(DD / 128, MROWS / 128);
        gemm_h<false><<<grid, 128, GEMM_SMEM>>>(aoh, w2h, w2l, b2,
                                                out, nullptr, nullptr,
                                                MROWS, DD, DD);
    }
}

// round 8
// speedup vs baseline: 4.1933x; 1.0708x over previous
#include <cuda_runtime.h>
#include <cuda_fp16.h>

#define BB 2
#define TT 2048
#define DD 1024
#define HH 16
#define DH 64
#define MROWS (BB*TT)
#define KQV_LD (3*DD)

// fp16 operands (device globals; allocation is forbidden)
__device__ __half g_xh [(size_t)MROWS*DD];
__device__ __half g_w1h[(size_t)DD*3*DD], g_w1l[(size_t)DD*3*DD];   // natural [K][N]
__device__ __half g_w2h[(size_t)DD*DD],   g_w2l[(size_t)DD*DD];
__device__ __half g_kqvh[(size_t)MROWS*3*DD], g_kqvl[(size_t)MROWS*3*DD];
__device__ __half g_aoh[(size_t)MROWS*DD];

// ---------------------------------------------------------------------------
// helpers
// ---------------------------------------------------------------------------
__device__ __forceinline__ unsigned h2_pack(__half a, __half b) {
    __half2 t = __halves2half2(a, b);
    return *reinterpret_cast<unsigned*>(&t);
}
__device__ __forceinline__ void hsplit2(float x, float y, unsigned &hi, unsigned &lo) {
    __half hx = __float2half_rn(x), hy = __float2half_rn(y);
    __half lx = __float2half_rn(x - __half2float(hx));
    __half ly = __float2half_rn(y - __half2float(hy));
    hi = h2_pack(hx, hy);
    lo = h2_pack(lx, ly);
}
__device__ __forceinline__ unsigned hpack2(float x, float y) {
    return h2_pack(__float2half_rn(x), __float2half_rn(y));
}
__device__ __forceinline__ void mma16816(float* c,
    unsigned a0, unsigned a1, unsigned a2, unsigned a3,
    unsigned b0, unsigned b1)
{
    asm volatile(
        "mma.sync.aligned.m16n8k16.row.col.f32.f16.f16.f32 "
        "{%0,%1,%2,%3},{%4,%5,%6,%7},{%8,%9},{%0,%1,%2,%3};\n"
        : "+f"(c[0]), "+f"(c[1]), "+f"(c[2]), "+f"(c[3])
        : "r"(a0), "r"(a1), "r"(a2), "r"(a3), "r"(b0), "r"(b1));
}
__device__ __forceinline__ void ldsm4(unsigned* r, const void* p) {
    unsigned a = (unsigned)__cvta_generic_to_shared(p);
    asm volatile("ldmatrix.sync.aligned.m8n8.x4.shared.b16 {%0,%1,%2,%3}, [%4];\n"
        : "=r"(r[0]), "=r"(r[1]), "=r"(r[2]), "=r"(r[3]) : "r"(a));
}
__device__ __forceinline__ void ldsm4t(unsigned* r, const void* p) {
    unsigned a = (unsigned)__cvta_generic_to_shared(p);
    asm volatile("ldmatrix.sync.aligned.m8n8.x4.trans.shared.b16 {%0,%1,%2,%3}, [%4];\n"
        : "=r"(r[0]), "=r"(r[1]), "=r"(r[2]), "=r"(r[3]) : "r"(a));
}
__device__ __forceinline__ void cp16(void* sp, const void* gp) {
    unsigned s = (unsigned)__cvta_generic_to_shared(sp);
    asm volatile("cp.async.cg.shared.global [%0], [%1], 16;\n" :: "r"(s), "l"(gp));
}
#define CP_COMMIT() asm volatile("cp.async.commit_group;\n")
#define CP_WAIT(n)  asm volatile("cp.async.wait_group %0;\n" :: "n"(n))

// ---------------------------------------------------------------------------
// prep kernels
// ---------------------------------------------------------------------------
__global__ void round_kernel(const float* __restrict__ in,
                             __half* __restrict__ hi, int n4)
{
    int i = blockIdx.x * blockDim.x + threadIdx.x;
    if (i >= n4) return;
    float4 v = reinterpret_cast<const float4*>(in)[i];
    reinterpret_cast<uint2*>(hi)[i] = make_uint2(hpack2(v.x, v.y), hpack2(v.z, v.w));
}
__global__ void split_kernel(const float* __restrict__ in,
                             __half* __restrict__ hi, __half* __restrict__ lo, int n4)
{
    int i = blockIdx.x * blockDim.x + threadIdx.x;
    if (i >= n4) return;
    float4 v = reinterpret_cast<const float4*>(in)[i];
    unsigned h0, l0, h1, l1;
    hsplit2(v.x, v.y, h0, l0);
    hsplit2(v.z, v.w, h1, l1);
    reinterpret_cast<uint2*>(hi)[i] = make_uint2(h0, h1);
    reinterpret_cast<uint2*>(lo)[i] = make_uint2(l0, l1);
}

// ---------------------------------------------------------------------------
// fp16 2-product GEMM: C = A @ B + bias  (A hi-only, B split hi/lo)
// CTA 128x128, BK=32, 3-stage cp.async, 4 warps (2m x 2n), warp tile 64x64.
// B fragments register-pipelined (both ks sets loaded before MMA stream).
// ---------------------------------------------------------------------------
#define APG 40
#define BPG 136
#define SA_ST (128*APG)
#define SB_ST (32*BPG)
#define NSG 3
#define GEMM_SMEM ((NSG*SA_ST + NSG*2*SB_ST) * 2)   // 82944 B

#define GEMM_LOAD(s, k0)                                                        \
    {                                                                           \
        _Pragma("unroll")                                                       \
        for (int j = 0; j < 4; j++) {                                           \
            const int id = tid + 128 * j;                                       \
            const int arow = id >> 2, ac = (id & 3) * 8;                        \
            const size_t ga = (size_t)(m0 + arow) * K + (k0) + ac;              \
            cp16(sA + (s)*SA_ST + arow*APG + ac, Ah_g + ga);                    \
            const int brow = id >> 4, bc = (id & 15) * 8;                       \
            const size_t gb = (size_t)((k0) + brow) * N + n0 + bc;              \
            cp16(sB + ((s)*2+0)*SB_ST + brow*BPG + bc, Bh_g + gb);              \
            cp16(sB + ((s)*2+1)*SB_ST + brow*BPG + bc, Bl_g + gb);              \
        }                                                                       \
        CP_COMMIT();                                                            \
    }

template<bool SPLIT_OUT>
__global__ __launch_bounds__(128, 2) void gemm_h(
    const __half* __restrict__ Ah_g,
    const __half* __restrict__ Bh_g, const __half* __restrict__ Bl_g,
    const float* __restrict__ bias,
    float* __restrict__ C, __half* __restrict__ Ch, __half* __restrict__ Cl,
    int M, int N, int K)
{
    extern __shared__ __half smg[];
    __half* sA = smg;                       // [stage][128*APG]
    __half* sB = smg + NSG*SA_ST;           // [stage][half][32*BPG] natural [k][n]

    const int tid = threadIdx.x, warp = tid >> 5, lane = tid & 31;
    const int m0 = blockIdx.y * 128, n0 = blockIdx.x * 128;
    const int wm = (warp & 1) * 64, wn = (warp >> 1) * 64;

    float acc[4][8][4];
#pragma unroll
    for (int i = 0; i < 4; i++)
#pragma unroll
        for (int j = 0; j < 8; j++)
#pragma unroll
            for (int l = 0; l < 4; l++) acc[i][j][l] = 0.f;

    GEMM_LOAD(0, 0);
    GEMM_LOAD(1, 32);

    const int brr = (lane & 8) + (lane & 7);
    const int arr = (lane & 15), akk = ((lane & 16) >> 1);

    const int ntiles = K / 32;
    for (int t = 0; t < ntiles; t++) {
        if (t + 1 < ntiles) { CP_WAIT(1); } else { CP_WAIT(0); }
        __syncthreads();      // stage t visible; all warps done with stage (t-1)
        if (t + 2 < ntiles) GEMM_LOAD((t + 2) % NSG, (t + 2) * 32);

        const int s = t % NSG;
        const __half* Ahs = sA + s*SA_ST;
        const __half* Bhs = sB + (s*2+0)*SB_ST;
        const __half* Bls = sB + (s*2+1)*SB_ST;

        // register-pipelined B fragments: load BOTH ks sets up front
        unsigned bh0[4][4], bl0[4][4], bh1[4][4], bl1[4][4];
#pragma unroll
        for (int np = 0; np < 4; np++) {
            const int bcc = wn + np * 16 + ((lane >> 1) & 8);
            ldsm4t(bh0[np], Bhs + brr * BPG + bcc);
            ldsm4t(bl0[np], Bls + brr * BPG + bcc);
        }
#pragma unroll
        for (int np = 0; np < 4; np++) {
            const int bcc = wn + np * 16 + ((lane >> 1) & 8);
            ldsm4t(bh1[np], Bhs + (16 + brr) * BPG + bcc);
            ldsm4t(bl1[np], Bls + (16 + brr) * BPG + bcc);
        }

        // ks = 0
#pragma unroll
        for (int mt = 0; mt < 4; mt++) {
            unsigned ah[4];
            ldsm4(ah, Ahs + (wm + mt * 16 + arr) * APG + akk);
#pragma unroll
            for (int nt = 0; nt < 8; nt++) {
                const unsigned b0h = bh0[nt >> 1][(nt & 1) * 2], b1h = bh0[nt >> 1][(nt & 1) * 2 + 1];
                const unsigned b0l = bl0[nt >> 1][(nt & 1) * 2], b1l = bl0[nt >> 1][(nt & 1) * 2 + 1];
                mma16816(acc[mt][nt], ah[0], ah[1], ah[2], ah[3], b0h, b1h);
                mma16816(acc[mt][nt], ah[0], ah[1], ah[2], ah[3], b0l, b1l);
            }
        }
        // ks = 16
#pragma unroll
        for (int mt = 0; mt < 4; mt++) {
            unsigned ah[4];
            ldsm4(ah, Ahs + (wm + mt * 16 + arr) * APG + 16 + akk);
#pragma unroll
            for (int nt = 0; nt < 8; nt++) {
                const unsigned b0h = bh1[nt >> 1][(nt & 1) * 2], b1h = bh1[nt >> 1][(nt & 1) * 2 + 1];
                const unsigned b0l = bl1[nt >> 1][(nt & 1) * 2], b1l = bl1[nt >> 1][(nt & 1) * 2 + 1];
                mma16816(acc[mt][nt], ah[0], ah[1], ah[2], ah[3], b0h, b1h);
                mma16816(acc[mt][nt], ah[0], ah[1], ah[2], ah[3], b0l, b1l);
            }
        }
    }

    const int g = lane >> 2, tg = lane & 3;
#pragma unroll
    for (int mt = 0; mt < 4; mt++) {
        const int r = m0 + wm + mt * 16 + g;
#pragma unroll
        for (int nt = 0; nt < 8; nt++) {
            const int c = n0 + wn + nt * 8 + tg * 2;
            const float bx = bias[c], by = bias[c + 1];
            const float v0 = acc[mt][nt][0] + bx, v1 = acc[mt][nt][1] + by;
            const float v2 = acc[mt][nt][2] + bx, v3 = acc[mt][nt][3] + by;
            if (SPLIT_OUT) {
                unsigned h0, l0, h1, l1;
                hsplit2(v0, v1, h0, l0);
                hsplit2(v2, v3, h1, l1);
                *reinterpret_cast<unsigned*>(&Ch[(size_t)r * N + c])       = h0;
                *reinterpret_cast<unsigned*>(&Cl[(size_t)r * N + c])       = l0;
                *reinterpret_cast<unsigned*>(&Ch[(size_t)(r + 8) * N + c]) = h1;
                *reinterpret_cast<unsigned*>(&Cl[(size_t)(r + 8) * N + c]) = l1;
            } else {
                float2 o0 = {v0, v1}, o1 = {v2, v3};
                *reinterpret_cast<float2*>(&C[(size_t)r * N + c])       = o0;
                *reinterpret_cast<float2*>(&C[(size_t)(r + 8) * N + c]) = o1;
            }
        }
    }
}

// ---------------------------------------------------------------------------
// Fused causal retention attention, fp16 2-product.
// 4 warps (128 thr), warp tile 64q x 32(k|d). K/V double-buffered cp.async.
// ---------------------------------------------------------------------------
#define AP 72
#define KV_ST (64*AP)
#define KVBUF (4*KV_ST)
#define ATT_SMEM ((128*AP + 2*KVBUF + 128*AP) * 2)   // 110592 B

#define ATT_LOAD(kb)                                                           \
    {                                                                          \
        const int _k0 = (kb) * 64;                                             \
        __half* _buf = KV + ((kb) & 1) * KVBUF;                                \
        _Pragma("unroll")                                                      \
        for (int _j = 0; _j < 4; _j++) {                                       \
            const int _id = tid + 128 * _j;                                    \
            const int _row = _id >> 3, _c8 = (_id & 7) * 8;                    \
            const size_t _g = (size_t)(_k0 + _row) * KQV_LD + _c8;             \
            const int _d = _row * AP + _c8;                                    \
            cp16(_buf + 0*KV_ST + _d, Khg + _g);                               \
            cp16(_buf + 1*KV_ST + _d, Klg + _g);                               \
            cp16(_buf + 2*KV_ST + _d, Vhg + _g);                               \
            cp16(_buf + 3*KV_ST + _d, Vlg + _g);                               \
        }                                                                      \
        CP_COMMIT();                                                           \
    }

__global__ __launch_bounds__(128, 2) void attn_mma(
    const __half* __restrict__ kqvh, const __half* __restrict__ kqvl,
    __half* __restrict__ aoh)
{
    extern __shared__ __half sma[];
    __half *Qh = sma;
    __half *KV = Qh + 128 * AP;           // [2][Kh|Kl|Vh|Vl][64*AP]
    __half *Sh = KV + 2 * KVBUF;

    const int tid = threadIdx.x, warp = tid >> 5, lane = tid & 31;
    const int g = lane >> 2, tg = lane & 3;
    const int qb = gridDim.x - 1 - blockIdx.x;    // heavy tiles first
    const int h = blockIdx.y, b = blockIdx.z;
    const int q0 = qb * 128;

    const size_t hoff = (size_t)b * TT * KQV_LD + h * DH;
    const __half *Khg = kqvh + hoff, *Klg = kqvl + hoff;
    const __half *Qhg = Khg + DD;
    const __half *Vhg = Khg + 2*DD, *Vlg = Klg + 2*DD;

    // prologue: start K/V load for kb=0
    ATT_LOAD(0);

    // load Q tile 128x64 (hi only)
#pragma unroll
    for (int j = 0; j < 8; j++) {
        const int id = tid + 128 * j;
        const int row = id >> 3, c8 = (id & 7) * 8;
        const size_t gq = (size_t)(q0 + row) * KQV_LD + c8;
        *reinterpret_cast<uint4*>(&Qh[row * AP + c8]) = *reinterpret_cast<const uint4*>(&Qhg[gq]);
    }

    const int wq = (warp & 1) * 64;     // q offset
    const int wkd = (warp >> 1) * 32;   // k (S) / d (O) offset

    float oacc[4][4][4];
#pragma unroll
    for (int i = 0; i < 4; i++)
#pragma unroll
        for (int j = 0; j < 4; j++)
#pragma unroll
            for (int l = 0; l < 4; l++) oacc[i][j][l] = 0.f;

    const int nkb = 2 * qb + 2;
    for (int kb = 0; kb < nkb; kb++) {
        const int k0 = kb * 64;
        CP_WAIT(0);
        __syncthreads();      // K/V kb visible; prev iter done with S/KV

        if (kb + 1 < nkb) ATT_LOAD(kb + 1);   // overlaps this iter's compute

        const __half* buf = KV + (kb & 1) * KVBUF;
        const __half* Khs = buf + 0*KV_ST;
        const __half* Kls = buf + 1*KV_ST;
        const __half* Vhs = buf + 2*KV_ST;
        const __half* Vls = buf + 3*KV_ST;

        // ---- S = Q K^T (warp: 64q x 32k) ----
        float sacc[4][4][4];
#pragma unroll
        for (int i = 0; i < 4; i++)
#pragma unroll
            for (int j = 0; j < 4; j++)
#pragma unroll
                for (int l = 0; l < 4; l++) sacc[i][j][l] = 0.f;

#pragma unroll
        for (int ds = 0; ds < 64; ds += 16) {
            unsigned bh[2][4], bl[2][4];
            const int kc = ds + (lane & 8);
#pragma unroll
            for (int np = 0; np < 2; np++) {
                const int kr = wkd + np * 16 + ((lane >> 1) & 8) + (lane & 7);
                ldsm4(bh[np], Khs + kr * AP + kc);
                ldsm4(bl[np], Kls + kr * AP + kc);
            }
#pragma unroll
            for (int mt = 0; mt < 4; mt++) {
                unsigned qh[4];
                const int r = (wq + mt * 16 + (lane & 15)) * AP + ds + ((lane & 16) >> 1);
                ldsm4(qh, Qh + r);
#pragma unroll
                for (int nt = 0; nt < 4; nt++) {
                    const unsigned b0h = bh[nt >> 1][(nt & 1) * 2], b1h = bh[nt >> 1][(nt & 1) * 2 + 1];
                    const unsigned b0l = bl[nt >> 1][(nt & 1) * 2], b1l = bl[nt >> 1][(nt & 1) * 2 + 1];
                    mma16816(sacc[mt][nt], qh[0], qh[1], qh[2], qh[3], b0h, b1h);
                    mma16816(sacc[mt][nt], qh[0], qh[1], qh[2], qh[3], b0l, b1l);
                }
            }
        }

        // mask (diagonal) + store S (hi only)
        const bool diag = (kb >= 2 * qb);
#pragma unroll
        for (int mt = 0; mt < 4; mt++) {
            const int qr = wq + mt * 16 + g;
#pragma unroll
            for (int nt = 0; nt < 4; nt++) {
                const int kc = wkd + nt * 8 + tg * 2;
                float s0 = sacc[mt][nt][0], s1 = sacc[mt][nt][1];
                float s2 = sacc[mt][nt][2], s3 = sacc[mt][nt][3];
                if (diag) {
                    const int qg0 = q0 + qr, qg8 = qg0 + 8, kg = k0 + kc;
                    if (kg     > qg0) s0 = 0.f;
                    if (kg + 1 > qg0) s1 = 0.f;
                    if (kg     > qg8) s2 = 0.f;
                    if (kg + 1 > qg8) s3 = 0.f;
                }
                const int idx = qr * AP + kc;
                *reinterpret_cast<unsigned*>(&Sh[idx])          = hpack2(s0, s1);
                *reinterpret_cast<unsigned*>(&Sh[idx + 8 * AP]) = hpack2(s2, s3);
            }
        }
        __syncthreads();

        // ---- O += S V (warp: 64q x 32d) ----
#pragma unroll
        for (int ks = 0; ks < 64; ks += 16) {
            unsigned vh[2][4], vl[2][4];
            const int vr = ks + (lane & 8) + (lane & 7);
#pragma unroll
            for (int np = 0; np < 2; np++) {
                const int vc = wkd + np * 16 + ((lane >> 1) & 8);
                ldsm4t(vh[np], Vhs + vr * AP + vc);
                ldsm4t(vl[np], Vls + vr * AP + vc);
            }
#pragma unroll
            for (int mt = 0; mt < 4; mt++) {
                unsigned sh4[4];
                const int r = (wq + mt * 16 + (lane & 15)) * AP + ks + ((lane & 16) >> 1);
                ldsm4(sh4, Sh + r);
#pragma unroll
                for (int nt = 0; nt < 4; nt++) {
                    const unsigned b0h = vh[nt >> 1][(nt & 1) * 2], b1h = vh[nt >> 1][(nt & 1) * 2 + 1];
                    const unsigned b0l = vl[nt >> 1][(nt & 1) * 2], b1l = vl[nt >> 1][(nt & 1) * 2 + 1];
                    mma16816(oacc[mt][nt], sh4[0], sh4[1], sh4[2], sh4[3], b0h, b1h);
                    mma16816(oacc[mt][nt], sh4[0], sh4[1], sh4[2], sh4[3], b0l, b1l);
                }
            }
        }
    }

    // write O (hi only) -> aoh[b*TT + q, h*64 + d]
#pragma unroll
    for (int mt = 0; mt < 4; mt++) {
        const size_t t = (size_t)b * TT + q0 + wq + mt * 16 + g;
#pragma unroll
        for (int nt = 0; nt < 4; nt++) {
            const int c = h * DH + wkd + nt * 8 + tg * 2;
            *reinterpret_cast<unsigned*>(&aoh[t * DD + c])       = hpack2(oacc[mt][nt][0], oacc[mt][nt][1]);
            *reinterpret_cast<unsigned*>(&aoh[(t + 8) * DD + c]) = hpack2(oacc[mt][nt][2], oacc[mt][nt][3]);
        }
    }
}

// ---------------------------------------------------------------------------
extern "C" void kernel_launch(void* const* d_in, const int* in_sizes, int n_in,
                              void* d_out, int out_size)
{
    const float* x  = (const float*)d_in[0];
    const float* W1 = (const float*)d_in[1];
    const float* b1 = (const float*)d_in[2];
    const float* W2 = (const float*)d_in[3];
    const float* b2 = (const float*)d_in[4];
    float* out = (float*)d_out;

    __half *xh, *w1h, *w1l, *w2h, *w2l, *kqvh, *kqvl, *aoh;
    cudaGetSymbolAddress((void**)&xh,  g_xh);
    cudaGetSymbolAddress((void**)&w1h, g_w1h);  cudaGetSymbolAddress((void**)&w1l, g_w1l);
    cudaGetSymbolAddress((void**)&w2h, g_w2h);  cudaGetSymbolAddress((void**)&w2l, g_w2l);
    cudaGetSymbolAddress((void**)&kqvh, g_kqvh); cudaGetSymbolAddress((void**)&kqvl, g_kqvl);
    cudaGetSymbolAddress((void**)&aoh, g_aoh);

    cudaFuncSetAttribute(gemm_h<true>,
                         cudaFuncAttributeMaxDynamicSharedMemorySize, GEMM_SMEM);
    cudaFuncSetAttribute(gemm_h<false>,
                         cudaFuncAttributeMaxDynamicSharedMemorySize, GEMM_SMEM);
    cudaFuncSetAttribute(attn_mma,
                         cudaFuncAttributeMaxDynamicSharedMemorySize, ATT_SMEM);

    // 0) x -> fp16 hi; W1/W2 -> fp16 hi/lo
    {
        int n4;
        n4 = MROWS * DD / 4;   round_kernel<<<(n4 + 255) / 256, 256>>>(x, xh, n4);
        n4 = DD * 3 * DD / 4;  split_kernel<<<(n4 + 255) / 256, 256>>>(W1, w1h, w1l, n4);
        n4 = DD * DD / 4;      split_kernel<<<(n4 + 255) / 256, 256>>>(W2, w2h, w2l, n4);
    }
    // 1) kqv = x @ W1 + b1  (split fp16 output)
    {
        dim3 grid(3 * DD / 128, MROWS / 128);
        gemm_h<true><<<grid, 128, GEMM_SMEM>>>(xh, w1h, w1l, b1,
                                               nullptr, kqvh, kqvl,
                                               MROWS, 3 * DD, DD);
    }
    // 2) causal retention attention
    {
        dim3 grid(TT / 128, HH, BB);
        attn_mma<<<grid, 128, ATT_SMEM>>>(kqvh, kqvl, aoh);
    }
    // 3) out = ao @ W2 + b2  (fp32 output)
    {
        dim3 grid(DD / 128, MROWS / 128);
        gemm_h<false><<<grid, 128, GEMM_SMEM>>>(aoh, w2h, w2l, b2,
                                                out, nullptr, nullptr,
                                                MROWS, DD, DD);
    }
}

// round 9
// speedup vs baseline: 5.0969x; 1.2155x over previous
#include <cuda_runtime.h>
#include <cuda_fp16.h>

#define BB 2
#define TT 2048
#define DD 1024
#define HH 16
#define DH 64
#define MROWS (BB*TT)
#define KQV_LD (3*DD)

// fp16 operands (device globals; allocation is forbidden)
__device__ __half g_xh [(size_t)MROWS*DD];
__device__ __half g_w1h[(size_t)DD*3*DD], g_w1l[(size_t)DD*3*DD];   // natural [K][N]
__device__ __half g_w2h[(size_t)DD*DD],   g_w2l[(size_t)DD*DD];
__device__ __half g_kqvh[(size_t)MROWS*3*DD];
__device__ __half g_aoh[(size_t)MROWS*DD];

// ---------------------------------------------------------------------------
// helpers
// ---------------------------------------------------------------------------
__device__ __forceinline__ unsigned h2_pack(__half a, __half b) {
    __half2 t = __halves2half2(a, b);
    return *reinterpret_cast<unsigned*>(&t);
}
__device__ __forceinline__ void hsplit2(float x, float y, unsigned &hi, unsigned &lo) {
    __half hx = __float2half_rn(x), hy = __float2half_rn(y);
    __half lx = __float2half_rn(x - __half2float(hx));
    __half ly = __float2half_rn(y - __half2float(hy));
    hi = h2_pack(hx, hy);
    lo = h2_pack(lx, ly);
}
__device__ __forceinline__ unsigned hpack2(float x, float y) {
    return h2_pack(__float2half_rn(x), __float2half_rn(y));
}
__device__ __forceinline__ void mma16816(float* c,
    unsigned a0, unsigned a1, unsigned a2, unsigned a3,
    unsigned b0, unsigned b1)
{
    asm volatile(
        "mma.sync.aligned.m16n8k16.row.col.f32.f16.f16.f32 "
        "{%0,%1,%2,%3},{%4,%5,%6,%7},{%8,%9},{%0,%1,%2,%3};\n"
        : "+f"(c[0]), "+f"(c[1]), "+f"(c[2]), "+f"(c[3])
        : "r"(a0), "r"(a1), "r"(a2), "r"(a3), "r"(b0), "r"(b1));
}
__device__ __forceinline__ void ldsm4(unsigned* r, const void* p) {
    unsigned a = (unsigned)__cvta_generic_to_shared(p);
    asm volatile("ldmatrix.sync.aligned.m8n8.x4.shared.b16 {%0,%1,%2,%3}, [%4];\n"
        : "=r"(r[0]), "=r"(r[1]), "=r"(r[2]), "=r"(r[3]) : "r"(a));
}
__device__ __forceinline__ void ldsm4t(unsigned* r, const void* p) {
    unsigned a = (unsigned)__cvta_generic_to_shared(p);
    asm volatile("ldmatrix.sync.aligned.m8n8.x4.trans.shared.b16 {%0,%1,%2,%3}, [%4];\n"
        : "=r"(r[0]), "=r"(r[1]), "=r"(r[2]), "=r"(r[3]) : "r"(a));
}
__device__ __forceinline__ void cp16(void* sp, const void* gp) {
    unsigned s = (unsigned)__cvta_generic_to_shared(sp);
    asm volatile("cp.async.cg.shared.global [%0], [%1], 16;\n" :: "r"(s), "l"(gp));
}
#define CP_COMMIT() asm volatile("cp.async.commit_group;\n")
#define CP_WAIT(n)  asm volatile("cp.async.wait_group %0;\n" :: "n"(n))

// ---------------------------------------------------------------------------
// prep kernels
// ---------------------------------------------------------------------------
__global__ void round_kernel(const float* __restrict__ in,
                             __half* __restrict__ hi, int n4)
{
    int i = blockIdx.x * blockDim.x + threadIdx.x;
    if (i >= n4) return;
    float4 v = reinterpret_cast<const float4*>(in)[i];
    reinterpret_cast<uint2*>(hi)[i] = make_uint2(hpack2(v.x, v.y), hpack2(v.z, v.w));
}
__global__ void split_kernel(const float* __restrict__ in,
                             __half* __restrict__ hi, __half* __restrict__ lo, int n4)
{
    int i = blockIdx.x * blockDim.x + threadIdx.x;
    if (i >= n4) return;
    float4 v = reinterpret_cast<const float4*>(in)[i];
    unsigned h0, l0, h1, l1;
    hsplit2(v.x, v.y, h0, l0);
    hsplit2(v.z, v.w, h1, l1);
    reinterpret_cast<uint2*>(hi)[i] = make_uint2(h0, h1);
    reinterpret_cast<uint2*>(lo)[i] = make_uint2(l0, l1);
}

// ---------------------------------------------------------------------------
// fp16 2-product GEMM: C = A @ B + bias  (A hi-only, B split hi/lo)
// CTA 128x128, BK=32, 3-stage cp.async, 4 warps (2m x 2n), warp tile 64x64.
// OMODE: 0 = fp32 C, 1 = fp16 (rounded hi) C.
// ---------------------------------------------------------------------------
#define APG 40
#define BPG 136
#define SA_ST (128*APG)
#define SB_ST (32*BPG)
#define NSG 3
#define GEMM_SMEM ((NSG*SA_ST + NSG*2*SB_ST) * 2)   // 82944 B

#define GEMM_LOAD(s, k0)                                                        \
    {                                                                           \
        _Pragma("unroll")                                                       \
        for (int j = 0; j < 4; j++) {                                           \
            const int id = tid + 128 * j;                                       \
            const int arow = id >> 2, ac = (id & 3) * 8;                        \
            const size_t ga = (size_t)(m0 + arow) * K + (k0) + ac;              \
            cp16(sA + (s)*SA_ST + arow*APG + ac, Ah_g + ga);                    \
            const int brow = id >> 4, bc = (id & 15) * 8;                       \
            const size_t gb = (size_t)((k0) + brow) * N + n0 + bc;              \
            cp16(sB + ((s)*2+0)*SB_ST + brow*BPG + bc, Bh_g + gb);              \
            cp16(sB + ((s)*2+1)*SB_ST + brow*BPG + bc, Bl_g + gb);              \
        }                                                                       \
        CP_COMMIT();                                                            \
    }

template<int OMODE>
__global__ __launch_bounds__(128, 2) void gemm_h(
    const __half* __restrict__ Ah_g,
    const __half* __restrict__ Bh_g, const __half* __restrict__ Bl_g,
    const float* __restrict__ bias,
    float* __restrict__ C, __half* __restrict__ Ch,
    int M, int N, int K)
{
    extern __shared__ __half smg[];
    __half* sA = smg;                       // [stage][128*APG]
    __half* sB = smg + NSG*SA_ST;           // [stage][half][32*BPG] natural [k][n]

    const int tid = threadIdx.x, warp = tid >> 5, lane = tid & 31;
    const int m0 = blockIdx.y * 128, n0 = blockIdx.x * 128;
    const int wm = (warp & 1) * 64, wn = (warp >> 1) * 64;

    float acc[4][8][4];
#pragma unroll
    for (int i = 0; i < 4; i++)
#pragma unroll
        for (int j = 0; j < 8; j++)
#pragma unroll
            for (int l = 0; l < 4; l++) acc[i][j][l] = 0.f;

    GEMM_LOAD(0, 0);
    GEMM_LOAD(1, 32);

    const int brr = (lane & 8) + (lane & 7);
    const int arr = (lane & 15), akk = ((lane & 16) >> 1);

    const int ntiles = K / 32;
    for (int t = 0; t < ntiles; t++) {
        if (t + 1 < ntiles) { CP_WAIT(1); } else { CP_WAIT(0); }
        __syncthreads();      // stage t visible; all warps done with stage (t-1)
        if (t + 2 < ntiles) GEMM_LOAD((t + 2) % NSG, (t + 2) * 32);

        const int s = t % NSG;
        const __half* Ahs = sA + s*SA_ST;
        const __half* Bhs = sB + (s*2+0)*SB_ST;
        const __half* Bls = sB + (s*2+1)*SB_ST;

        // register-pipelined B fragments: load BOTH ks sets up front
        unsigned bh0[4][4], bl0[4][4], bh1[4][4], bl1[4][4];
#pragma unroll
        for (int np = 0; np < 4; np++) {
            const int bcc = wn + np * 16 + ((lane >> 1) & 8);
            ldsm4t(bh0[np], Bhs + brr * BPG + bcc);
            ldsm4t(bl0[np], Bls + brr * BPG + bcc);
        }
#pragma unroll
        for (int np = 0; np < 4; np++) {
            const int bcc = wn + np * 16 + ((lane >> 1) & 8);
            ldsm4t(bh1[np], Bhs + (16 + brr) * BPG + bcc);
            ldsm4t(bl1[np], Bls + (16 + brr) * BPG + bcc);
        }

        // ks = 0
#pragma unroll
        for (int mt = 0; mt < 4; mt++) {
            unsigned ah[4];
            ldsm4(ah, Ahs + (wm + mt * 16 + arr) * APG + akk);
#pragma unroll
            for (int nt = 0; nt < 8; nt++) {
                const unsigned b0h = bh0[nt >> 1][(nt & 1) * 2], b1h = bh0[nt >> 1][(nt & 1) * 2 + 1];
                const unsigned b0l = bl0[nt >> 1][(nt & 1) * 2], b1l = bl0[nt >> 1][(nt & 1) * 2 + 1];
                mma16816(acc[mt][nt], ah[0], ah[1], ah[2], ah[3], b0h, b1h);
                mma16816(acc[mt][nt], ah[0], ah[1], ah[2], ah[3], b0l, b1l);
            }
        }
        // ks = 16
#pragma unroll
        for (int mt = 0; mt < 4; mt++) {
            unsigned ah[4];
            ldsm4(ah, Ahs + (wm + mt * 16 + arr) * APG + 16 + akk);
#pragma unroll
            for (int nt = 0; nt < 8; nt++) {
                const unsigned b0h = bh1[nt >> 1][(nt & 1) * 2], b1h = bh1[nt >> 1][(nt & 1) * 2 + 1];
                const unsigned b0l = bl1[nt >> 1][(nt & 1) * 2], b1l = bl1[nt >> 1][(nt & 1) * 2 + 1];
                mma16816(acc[mt][nt], ah[0], ah[1], ah[2], ah[3], b0h, b1h);
                mma16816(acc[mt][nt], ah[0], ah[1], ah[2], ah[3], b0l, b1l);
            }
        }
    }

    const int g = lane >> 2, tg = lane & 3;
#pragma unroll
    for (int mt = 0; mt < 4; mt++) {
        const int r = m0 + wm + mt * 16 + g;
#pragma unroll
        for (int nt = 0; nt < 8; nt++) {
            const int c = n0 + wn + nt * 8 + tg * 2;
            const float bx = bias[c], by = bias[c + 1];
            const float v0 = acc[mt][nt][0] + bx, v1 = acc[mt][nt][1] + by;
            const float v2 = acc[mt][nt][2] + bx, v3 = acc[mt][nt][3] + by;
            if (OMODE == 1) {
                *reinterpret_cast<unsigned*>(&Ch[(size_t)r * N + c])       = hpack2(v0, v1);
                *reinterpret_cast<unsigned*>(&Ch[(size_t)(r + 8) * N + c]) = hpack2(v2, v3);
            } else {
                float2 o0 = {v0, v1}, o1 = {v2, v3};
                *reinterpret_cast<float2*>(&C[(size_t)r * N + c])       = o0;
                *reinterpret_cast<float2*>(&C[(size_t)(r + 8) * N + c]) = o1;
            }
        }
    }
}

// ---------------------------------------------------------------------------
// Fused causal retention attention, fp16 hi-only (single product per phase).
// 4 warps (128 thr), warp tile 64q x 32(k|d). K/V double-buffered cp.async.
// ---------------------------------------------------------------------------
#define AP 72
#define KV_ST (64*AP)
#define KVBUF (2*KV_ST)               // Kh, Vh for one stage
#define ATT_SMEM ((128*AP + 2*KVBUF + 128*AP) * 2)   // 73728 B

#define ATT_LOAD(kb)                                                           \
    {                                                                          \
        const int _k0 = (kb) * 64;                                             \
        __half* _buf = KV + ((kb) & 1) * KVBUF;                                \
        _Pragma("unroll")                                                      \
        for (int _j = 0; _j < 4; _j++) {                                       \
            const int _id = tid + 128 * _j;                                    \
            const int _row = _id >> 3, _c8 = (_id & 7) * 8;                    \
            const size_t _g = (size_t)(_k0 + _row) * KQV_LD + _c8;             \
            const int _d = _row * AP + _c8;                                    \
            cp16(_buf + 0*KV_ST + _d, Khg + _g);                               \
            cp16(_buf + 1*KV_ST + _d, Vhg + _g);                               \
        }                                                                      \
        CP_COMMIT();                                                           \
    }

__global__ __launch_bounds__(128, 2) void attn_mma(
    const __half* __restrict__ kqvh, __half* __restrict__ aoh)
{
    extern __shared__ __half sma[];
    __half *Qh = sma;
    __half *KV = Qh + 128 * AP;           // [2][Kh|Vh][64*AP]
    __half *Sh = KV + 2 * KVBUF;

    const int tid = threadIdx.x, warp = tid >> 5, lane = tid & 31;
    const int g = lane >> 2, tg = lane & 3;
    const int qb = gridDim.x - 1 - blockIdx.x;    // heavy tiles first
    const int h = blockIdx.y, b = blockIdx.z;
    const int q0 = qb * 128;

    const size_t hoff = (size_t)b * TT * KQV_LD + h * DH;
    const __half *Khg = kqvh + hoff;
    const __half *Qhg = Khg + DD;
    const __half *Vhg = Khg + 2*DD;

    // prologue: start K/V load for kb=0
    ATT_LOAD(0);

    // load Q tile 128x64 (hi only)
#pragma unroll
    for (int j = 0; j < 8; j++) {
        const int id = tid + 128 * j;
        const int row = id >> 3, c8 = (id & 7) * 8;
        const size_t gq = (size_t)(q0 + row) * KQV_LD + c8;
        *reinterpret_cast<uint4*>(&Qh[row * AP + c8]) = *reinterpret_cast<const uint4*>(&Qhg[gq]);
    }

    const int wq = (warp & 1) * 64;     // q offset
    const int wkd = (warp >> 1) * 32;   // k (S) / d (O) offset

    float oacc[4][4][4];
#pragma unroll
    for (int i = 0; i < 4; i++)
#pragma unroll
        for (int j = 0; j < 4; j++)
#pragma unroll
            for (int l = 0; l < 4; l++) oacc[i][j][l] = 0.f;

    const int nkb = 2 * qb + 2;
    for (int kb = 0; kb < nkb; kb++) {
        const int k0 = kb * 64;
        CP_WAIT(0);
        __syncthreads();      // K/V kb visible; prev iter done with S/KV

        if (kb + 1 < nkb) ATT_LOAD(kb + 1);   // overlaps this iter's compute

        const __half* buf = KV + (kb & 1) * KVBUF;
        const __half* Khs = buf + 0*KV_ST;
        const __half* Vhs = buf + 1*KV_ST;

        // ---- S = Q K^T (warp: 64q x 32k), single product ----
        float sacc[4][4][4];
#pragma unroll
        for (int i = 0; i < 4; i++)
#pragma unroll
            for (int j = 0; j < 4; j++)
#pragma unroll
                for (int l = 0; l < 4; l++) sacc[i][j][l] = 0.f;

#pragma unroll
        for (int ds = 0; ds < 64; ds += 16) {
            unsigned bh[2][4];
            const int kc = ds + (lane & 8);
#pragma unroll
            for (int np = 0; np < 2; np++) {
                const int kr = wkd + np * 16 + ((lane >> 1) & 8) + (lane & 7);
                ldsm4(bh[np], Khs + kr * AP + kc);
            }
#pragma unroll
            for (int mt = 0; mt < 4; mt++) {
                unsigned qh[4];
                const int r = (wq + mt * 16 + (lane & 15)) * AP + ds + ((lane & 16) >> 1);
                ldsm4(qh, Qh + r);
#pragma unroll
                for (int nt = 0; nt < 4; nt++) {
                    const unsigned b0 = bh[nt >> 1][(nt & 1) * 2], b1 = bh[nt >> 1][(nt & 1) * 2 + 1];
                    mma16816(sacc[mt][nt], qh[0], qh[1], qh[2], qh[3], b0, b1);
                }
            }
        }

        // mask (diagonal) + store S (fp16)
        const bool diag = (kb >= 2 * qb);
#pragma unroll
        for (int mt = 0; mt < 4; mt++) {
            const int qr = wq + mt * 16 + g;
#pragma unroll
            for (int nt = 0; nt < 4; nt++) {
                const int kc = wkd + nt * 8 + tg * 2;
                float s0 = sacc[mt][nt][0], s1 = sacc[mt][nt][1];
                float s2 = sacc[mt][nt][2], s3 = sacc[mt][nt][3];
                if (diag) {
                    const int qg0 = q0 + qr, qg8 = qg0 + 8, kg = k0 + kc;
                    if (kg     > qg0) s0 = 0.f;
                    if (kg + 1 > qg0) s1 = 0.f;
                    if (kg     > qg8) s2 = 0.f;
                    if (kg + 1 > qg8) s3 = 0.f;
                }
                const int idx = qr * AP + kc;
                *reinterpret_cast<unsigned*>(&Sh[idx])          = hpack2(s0, s1);
                *reinterpret_cast<unsigned*>(&Sh[idx + 8 * AP]) = hpack2(s2, s3);
            }
        }
        __syncthreads();

        // ---- O += S V (warp: 64q x 32d), single product ----
#pragma unroll
        for (int ks = 0; ks < 64; ks += 16) {
            unsigned vh[2][4];
            const int vr = ks + (lane & 8) + (lane & 7);
#pragma unroll
            for (int np = 0; np < 2; np++) {
                const int vc = wkd + np * 16 + ((lane >> 1) & 8);
                ldsm4t(vh[np], Vhs + vr * AP + vc);
            }
#pragma unroll
            for (int mt = 0; mt < 4; mt++) {
                unsigned sh4[4];
                const int r = (wq + mt * 16 + (lane & 15)) * AP + ks + ((lane & 16) >> 1);
                ldsm4(sh4, Sh + r);
#pragma unroll
                for (int nt = 0; nt < 4; nt++) {
                    const unsigned b0 = vh[nt >> 1][(nt & 1) * 2], b1 = vh[nt >> 1][(nt & 1) * 2 + 1];
                    mma16816(oacc[mt][nt], sh4[0], sh4[1], sh4[2], sh4[3], b0, b1);
                }
            }
        }
    }

    // write O (fp16) -> aoh[b*TT + q, h*64 + d]
#pragma unroll
    for (int mt = 0; mt < 4; mt++) {
        const size_t t = (size_t)b * TT + q0 + wq + mt * 16 + g;
#pragma unroll
        for (int nt = 0; nt < 4; nt++) {
            const int c = h * DH + wkd + nt * 8 + tg * 2;
            *reinterpret_cast<unsigned*>(&aoh[t * DD + c])       = hpack2(oacc[mt][nt][0], oacc[mt][nt][1]);
            *reinterpret_cast<unsigned*>(&aoh[(t + 8) * DD + c]) = hpack2(oacc[mt][nt][2], oacc[mt][nt][3]);
        }
    }
}

// ---------------------------------------------------------------------------
extern "C" void kernel_launch(void* const* d_in, const int* in_sizes, int n_in,
                              void* d_out, int out_size)
{
    const float* x  = (const float*)d_in[0];
    const float* W1 = (const float*)d_in[1];
    const float* b1 = (const float*)d_in[2];
    const float* W2 = (const float*)d_in[3];
    const float* b2 = (const float*)d_in[4];
    float* out = (float*)d_out;

    __half *xh, *w1h, *w1l, *w2h, *w2l, *kqvh, *aoh;
    cudaGetSymbolAddress((void**)&xh,  g_xh);
    cudaGetSymbolAddress((void**)&w1h, g_w1h);  cudaGetSymbolAddress((void**)&w1l, g_w1l);
    cudaGetSymbolAddress((void**)&w2h, g_w2h);  cudaGetSymbolAddress((void**)&w2l, g_w2l);
    cudaGetSymbolAddress((void**)&kqvh, g_kqvh);
    cudaGetSymbolAddress((void**)&aoh, g_aoh);

    cudaFuncSetAttribute(gemm_h<1>,
                         cudaFuncAttributeMaxDynamicSharedMemorySize, GEMM_SMEM);
    cudaFuncSetAttribute(gemm_h<0>,
                         cudaFuncAttributeMaxDynamicSharedMemorySize, GEMM_SMEM);
    cudaFuncSetAttribute(attn_mma,
                         cudaFuncAttributeMaxDynamicSharedMemorySize, ATT_SMEM);

    // 0) x -> fp16 hi; W1/W2 -> fp16 hi/lo
    {
        int n4;
        n4 = MROWS * DD / 4;   round_kernel<<<(n4 + 255) / 256, 256>>>(x, xh, n4);
        n4 = DD * 3 * DD / 4;  split_kernel<<<(n4 + 255) / 256, 256>>>(W1, w1h, w1l, n4);
        n4 = DD * DD / 4;      split_kernel<<<(n4 + 255) / 256, 256>>>(W2, w2h, w2l, n4);
    }
    // 1) kqv = x @ W1 + b1  (fp16 hi output)
    {
        dim3 grid(3 * DD / 128, MROWS / 128);
        gemm_h<1><<<grid, 128, GEMM_SMEM>>>(xh, w1h, w1l, b1,
                                            nullptr, kqvh,
                                            MROWS, 3 * DD, DD);
    }
    // 2) causal retention attention (hi-only, single product)
    {
        dim3 grid(TT / 128, HH, BB);
        attn_mma<<<grid, 128, ATT_SMEM>>>(kqvh, aoh);
    }
    // 3) out = ao @ W2 + b2  (fp32 output)
    {
        dim3 grid(DD / 128, MROWS / 128);
        gemm_h<0><<<grid, 128, GEMM_SMEM>>>(aoh, w2h, w2l, b2,
                                            out, nullptr,
                                            MROWS, DD, DD);
    }
}

// round 10
// speedup vs baseline: 7.0550x; 1.3842x over previous
#include <cuda_runtime.h>
#include <cuda_fp16.h>

#define BB 2
#define TT 2048
#define DD 1024
#define HH 16
#define DH 64
#define MROWS (BB*TT)
#define KQV_LD (3*DD)

// fp16 operands (device globals; allocation is forbidden)
__device__ __half g_xh [(size_t)MROWS*DD];
__device__ __half g_w1h[(size_t)DD*3*DD];   // natural [K][N]
__device__ __half g_w2h[(size_t)DD*DD];
__device__ __half g_kqvh[(size_t)MROWS*3*DD];
__device__ __half g_aoh[(size_t)MROWS*DD];

// ---------------------------------------------------------------------------
// helpers
// ---------------------------------------------------------------------------
__device__ __forceinline__ unsigned h2_pack(__half a, __half b) {
    __half2 t = __halves2half2(a, b);
    return *reinterpret_cast<unsigned*>(&t);
}
__device__ __forceinline__ unsigned hpack2(float x, float y) {
    return h2_pack(__float2half_rn(x), __float2half_rn(y));
}
__device__ __forceinline__ void mma16816(float* c,
    unsigned a0, unsigned a1, unsigned a2, unsigned a3,
    unsigned b0, unsigned b1)
{
    asm volatile(
        "mma.sync.aligned.m16n8k16.row.col.f32.f16.f16.f32 "
        "{%0,%1,%2,%3},{%4,%5,%6,%7},{%8,%9},{%0,%1,%2,%3};\n"
        : "+f"(c[0]), "+f"(c[1]), "+f"(c[2]), "+f"(c[3])
        : "r"(a0), "r"(a1), "r"(a2), "r"(a3), "r"(b0), "r"(b1));
}
__device__ __forceinline__ void ldsm4(unsigned* r, const void* p) {
    unsigned a = (unsigned)__cvta_generic_to_shared(p);
    asm volatile("ldmatrix.sync.aligned.m8n8.x4.shared.b16 {%0,%1,%2,%3}, [%4];\n"
        : "=r"(r[0]), "=r"(r[1]), "=r"(r[2]), "=r"(r[3]) : "r"(a));
}
__device__ __forceinline__ void ldsm4t(unsigned* r, const void* p) {
    unsigned a = (unsigned)__cvta_generic_to_shared(p);
    asm volatile("ldmatrix.sync.aligned.m8n8.x4.trans.shared.b16 {%0,%1,%2,%3}, [%4];\n"
        : "=r"(r[0]), "=r"(r[1]), "=r"(r[2]), "=r"(r[3]) : "r"(a));
}
__device__ __forceinline__ void cp16(void* sp, const void* gp) {
    unsigned s = (unsigned)__cvta_generic_to_shared(sp);
    asm volatile("cp.async.cg.shared.global [%0], [%1], 16;\n" :: "r"(s), "l"(gp));
}
#define CP_COMMIT() asm volatile("cp.async.commit_group;\n")
#define CP_WAIT(n)  asm volatile("cp.async.wait_group %0;\n" :: "n"(n))

// ---------------------------------------------------------------------------
// prep: fp32 -> fp16 (round)
// ---------------------------------------------------------------------------
__global__ void round_kernel(const float* __restrict__ in,
                             __half* __restrict__ hi, int n4)
{
    int i = blockIdx.x * blockDim.x + threadIdx.x;
    if (i >= n4) return;
    float4 v = reinterpret_cast<const float4*>(in)[i];
    reinterpret_cast<uint2*>(hi)[i] = make_uint2(hpack2(v.x, v.y), hpack2(v.z, v.w));
}

// ---------------------------------------------------------------------------
// fp16 single-product GEMM: C = A @ B + bias
// CTA 128x128, BK=32, 3-stage cp.async, 4 warps (2m x 2n), warp tile 64x64.
// OMODE: 0 = fp32 C, 1 = fp16 C.
// ---------------------------------------------------------------------------
#define APG 40
#define BPG 136
#define SA_ST (128*APG)
#define SB_ST (32*BPG)
#define NSG 3
#define GEMM_SMEM ((NSG*SA_ST + NSG*SB_ST) * 2)   // 56832 B

#define GEMM_LOAD(s, k0)                                                        \
    {                                                                           \
        _Pragma("unroll")                                                       \
        for (int j = 0; j < 4; j++) {                                           \
            const int id = tid + 128 * j;                                       \
            const int arow = id >> 2, ac = (id & 3) * 8;                        \
            const size_t ga = (size_t)(m0 + arow) * K + (k0) + ac;              \
            cp16(sA + (s)*SA_ST + arow*APG + ac, Ah_g + ga);                    \
            const int brow = id >> 4, bc = (id & 15) * 8;                       \
            const size_t gb = (size_t)((k0) + brow) * N + n0 + bc;              \
            cp16(sB + (s)*SB_ST + brow*BPG + bc, Bh_g + gb);                    \
        }                                                                       \
        CP_COMMIT();                                                            \
    }

template<int OMODE>
__global__ __launch_bounds__(128, 2) void gemm_h(
    const __half* __restrict__ Ah_g,
    const __half* __restrict__ Bh_g,
    const float* __restrict__ bias,
    float* __restrict__ C, __half* __restrict__ Ch,
    int M, int N, int K)
{
    extern __shared__ __half smg[];
    __half* sA = smg;                       // [stage][128*APG]
    __half* sB = smg + NSG*SA_ST;           // [stage][32*BPG] natural [k][n]

    const int tid = threadIdx.x, warp = tid >> 5, lane = tid & 31;
    const int m0 = blockIdx.y * 128, n0 = blockIdx.x * 128;
    const int wm = (warp & 1) * 64, wn = (warp >> 1) * 64;

    float acc[4][8][4];
#pragma unroll
    for (int i = 0; i < 4; i++)
#pragma unroll
        for (int j = 0; j < 8; j++)
#pragma unroll
            for (int l = 0; l < 4; l++) acc[i][j][l] = 0.f;

    GEMM_LOAD(0, 0);
    GEMM_LOAD(1, 32);

    const int brr = (lane & 8) + (lane & 7);
    const int arr = (lane & 15), akk = ((lane & 16) >> 1);

    const int ntiles = K / 32;
    for (int t = 0; t < ntiles; t++) {
        if (t + 1 < ntiles) { CP_WAIT(1); } else { CP_WAIT(0); }
        __syncthreads();      // stage t visible; all warps done with stage (t-1)
        if (t + 2 < ntiles) GEMM_LOAD((t + 2) % NSG, (t + 2) * 32);

        const int s = t % NSG;
        const __half* Ahs = sA + s*SA_ST;
        const __half* Bhs = sB + s*SB_ST;

        // register-pipelined B fragments: both ks sets up front
        unsigned bh0[4][4], bh1[4][4];
#pragma unroll
        for (int np = 0; np < 4; np++) {
            const int bcc = wn + np * 16 + ((lane >> 1) & 8);
            ldsm4t(bh0[np], Bhs + brr * BPG + bcc);
            ldsm4t(bh1[np], Bhs + (16 + brr) * BPG + bcc);
        }

        // ks = 0
#pragma unroll
        for (int mt = 0; mt < 4; mt++) {
            unsigned ah[4];
            ldsm4(ah, Ahs + (wm + mt * 16 + arr) * APG + akk);
#pragma unroll
            for (int nt = 0; nt < 8; nt++) {
                mma16816(acc[mt][nt], ah[0], ah[1], ah[2], ah[3],
                         bh0[nt >> 1][(nt & 1) * 2], bh0[nt >> 1][(nt & 1) * 2 + 1]);
            }
        }
        // ks = 16
#pragma unroll
        for (int mt = 0; mt < 4; mt++) {
            unsigned ah[4];
            ldsm4(ah, Ahs + (wm + mt * 16 + arr) * APG + 16 + akk);
#pragma unroll
            for (int nt = 0; nt < 8; nt++) {
                mma16816(acc[mt][nt], ah[0], ah[1], ah[2], ah[3],
                         bh1[nt >> 1][(nt & 1) * 2], bh1[nt >> 1][(nt & 1) * 2 + 1]);
            }
        }
    }

    const int g = lane >> 2, tg = lane & 3;
#pragma unroll
    for (int mt = 0; mt < 4; mt++) {
        const int r = m0 + wm + mt * 16 + g;
#pragma unroll
        for (int nt = 0; nt < 8; nt++) {
            const int c = n0 + wn + nt * 8 + tg * 2;
            const float bx = bias[c], by = bias[c + 1];
            const float v0 = acc[mt][nt][0] + bx, v1 = acc[mt][nt][1] + by;
            const float v2 = acc[mt][nt][2] + bx, v3 = acc[mt][nt][3] + by;
            if (OMODE == 1) {
                *reinterpret_cast<unsigned*>(&Ch[(size_t)r * N + c])       = hpack2(v0, v1);
                *reinterpret_cast<unsigned*>(&Ch[(size_t)(r + 8) * N + c]) = hpack2(v2, v3);
            } else {
                float2 o0 = {v0, v1}, o1 = {v2, v3};
                *reinterpret_cast<float2*>(&C[(size_t)r * N + c])       = o0;
                *reinterpret_cast<float2*>(&C[(size_t)(r + 8) * N + c]) = o1;
            }
        }
    }
}

// ---------------------------------------------------------------------------
// Fused causal retention attention, fp16 hi-only (single product per phase).
// 4 warps (128 thr), warp tile 64q x 32(k|d). K/V double-buffered cp.async.
// ---------------------------------------------------------------------------
#define AP 72
#define KV_ST (64*AP)
#define KVBUF (2*KV_ST)               // Kh, Vh for one stage
#define ATT_SMEM ((128*AP + 2*KVBUF + 128*AP) * 2)   // 73728 B

#define ATT_LOAD(kb)                                                           \
    {                                                                          \
        const int _k0 = (kb) * 64;                                             \
        __half* _buf = KV + ((kb) & 1) * KVBUF;                                \
        _Pragma("unroll")                                                      \
        for (int _j = 0; _j < 4; _j++) {                                       \
            const int _id = tid + 128 * _j;                                    \
            const int _row = _id >> 3, _c8 = (_id & 7) * 8;                    \
            const size_t _g = (size_t)(_k0 + _row) * KQV_LD + _c8;             \
            const int _d = _row * AP + _c8;                                    \
            cp16(_buf + 0*KV_ST + _d, Khg + _g);                               \
            cp16(_buf + 1*KV_ST + _d, Vhg + _g);                               \
        }                                                                      \
        CP_COMMIT();                                                           \
    }

__global__ __launch_bounds__(128, 2) void attn_mma(
    const __half* __restrict__ kqvh, __half* __restrict__ aoh)
{
    extern __shared__ __half sma[];
    __half *Qh = sma;
    __half *KV = Qh + 128 * AP;           // [2][Kh|Vh][64*AP]
    __half *Sh = KV + 2 * KVBUF;

    const int tid = threadIdx.x, warp = tid >> 5, lane = tid & 31;
    const int g = lane >> 2, tg = lane & 3;
    const int qb = gridDim.x - 1 - blockIdx.x;    // heavy tiles first
    const int h = blockIdx.y, b = blockIdx.z;
    const int q0 = qb * 128;

    const size_t hoff = (size_t)b * TT * KQV_LD + h * DH;
    const __half *Khg = kqvh + hoff;
    const __half *Qhg = Khg + DD;
    const __half *Vhg = Khg + 2*DD;

    // prologue: start K/V load for kb=0
    ATT_LOAD(0);

    // load Q tile 128x64
#pragma unroll
    for (int j = 0; j < 8; j++) {
        const int id = tid + 128 * j;
        const int row = id >> 3, c8 = (id & 7) * 8;
        const size_t gq = (size_t)(q0 + row) * KQV_LD + c8;
        *reinterpret_cast<uint4*>(&Qh[row * AP + c8]) = *reinterpret_cast<const uint4*>(&Qhg[gq]);
    }

    const int wq = (warp & 1) * 64;     // q offset
    const int wkd = (warp >> 1) * 32;   // k (S) / d (O) offset

    float oacc[4][4][4];
#pragma unroll
    for (int i = 0; i < 4; i++)
#pragma unroll
        for (int j = 0; j < 4; j++)
#pragma unroll
            for (int l = 0; l < 4; l++) oacc[i][j][l] = 0.f;

    const int nkb = 2 * qb + 2;
    for (int kb = 0; kb < nkb; kb++) {
        const int k0 = kb * 64;
        CP_WAIT(0);
        __syncthreads();      // K/V kb visible; prev iter done with S/KV

        if (kb + 1 < nkb) ATT_LOAD(kb + 1);   // overlaps this iter's compute

        const __half* buf = KV + (kb & 1) * KVBUF;
        const __half* Khs = buf + 0*KV_ST;
        const __half* Vhs = buf + 1*KV_ST;

        // ---- S = Q K^T (warp: 64q x 32k) ----
        float sacc[4][4][4];
#pragma unroll
        for (int i = 0; i < 4; i++)
#pragma unroll
            for (int j = 0; j < 4; j++)
#pragma unroll
                for (int l = 0; l < 4; l++) sacc[i][j][l] = 0.f;

#pragma unroll
        for (int ds = 0; ds < 64; ds += 16) {
            unsigned bh[2][4];
            const int kc = ds + (lane & 8);
#pragma unroll
            for (int np = 0; np < 2; np++) {
                const int kr = wkd + np * 16 + ((lane >> 1) & 8) + (lane & 7);
                ldsm4(bh[np], Khs + kr * AP + kc);
            }
#pragma unroll
            for (int mt = 0; mt < 4; mt++) {
                unsigned qh[4];
                const int r = (wq + mt * 16 + (lane & 15)) * AP + ds + ((lane & 16) >> 1);
                ldsm4(qh, Qh + r);
#pragma unroll
                for (int nt = 0; nt < 4; nt++) {
                    mma16816(sacc[mt][nt], qh[0], qh[1], qh[2], qh[3],
                             bh[nt >> 1][(nt & 1) * 2], bh[nt >> 1][(nt & 1) * 2 + 1]);
                }
            }
        }

        // mask (diagonal) + store S (fp16)
        const bool diag = (kb >= 2 * qb);
#pragma unroll
        for (int mt = 0; mt < 4; mt++) {
            const int qr = wq + mt * 16 + g;
#pragma unroll
            for (int nt = 0; nt < 4; nt++) {
                const int kc = wkd + nt * 8 + tg * 2;
                float s0 = sacc[mt][nt][0], s1 = sacc[mt][nt][1];
                float s2 = sacc[mt][nt][2], s3 = sacc[mt][nt][3];
                if (diag) {
                    const int qg0 = q0 + qr, qg8 = qg0 + 8, kg = k0 + kc;
                    if (kg     > qg0) s0 = 0.f;
                    if (kg + 1 > qg0) s1 = 0.f;
                    if (kg     > qg8) s2 = 0.f;
                    if (kg + 1 > qg8) s3 = 0.f;
                }
                const int idx = qr * AP + kc;
                *reinterpret_cast<unsigned*>(&Sh[idx])          = hpack2(s0, s1);
                *reinterpret_cast<unsigned*>(&Sh[idx + 8 * AP]) = hpack2(s2, s3);
            }
        }
        __syncthreads();

        // ---- O += S V (warp: 64q x 32d) ----
#pragma unroll
        for (int ks = 0; ks < 64; ks += 16) {
            unsigned vh[2][4];
            const int vr = ks + (lane & 8) + (lane & 7);
#pragma unroll
            for (int np = 0; np < 2; np++) {
                const int vc = wkd + np * 16 + ((lane >> 1) & 8);
                ldsm4t(vh[np], Vhs + vr * AP + vc);
            }
#pragma unroll
            for (int mt = 0; mt < 4; mt++) {
                unsigned sh4[4];
                const int r = (wq + mt * 16 + (lane & 15)) * AP + ks + ((lane & 16) >> 1);
                ldsm4(sh4, Sh + r);
#pragma unroll
                for (int nt = 0; nt < 4; nt++) {
                    mma16816(oacc[mt][nt], sh4[0], sh4[1], sh4[2], sh4[3],
                             vh[nt >> 1][(nt & 1) * 2], vh[nt >> 1][(nt & 1) * 2 + 1]);
                }
            }
        }
    }

    // write O (fp16) -> aoh[b*TT + q, h*64 + d]
#pragma unroll
    for (int mt = 0; mt < 4; mt++) {
        const size_t t = (size_t)b * TT + q0 + wq + mt * 16 + g;
#pragma unroll
        for (int nt = 0; nt < 4; nt++) {
            const int c = h * DH + wkd + nt * 8 + tg * 2;
            *reinterpret_cast<unsigned*>(&aoh[t * DD + c])       = hpack2(oacc[mt][nt][0], oacc[mt][nt][1]);
            *reinterpret_cast<unsigned*>(&aoh[(t + 8) * DD + c]) = hpack2(oacc[mt][nt][2], oacc[mt][nt][3]);
        }
    }
}

// ---------------------------------------------------------------------------
extern "C" void kernel_launch(void* const* d_in, const int* in_sizes, int n_in,
                              void* d_out, int out_size)
{
    const float* x  = (const float*)d_in[0];
    const float* W1 = (const float*)d_in[1];
    const float* b1 = (const float*)d_in[2];
    const float* W2 = (const float*)d_in[3];
    const float* b2 = (const float*)d_in[4];
    float* out = (float*)d_out;

    __half *xh, *w1h, *w2h, *kqvh, *aoh;
    cudaGetSymbolAddress((void**)&xh,  g_xh);
    cudaGetSymbolAddress((void**)&w1h, g_w1h);
    cudaGetSymbolAddress((void**)&w2h, g_w2h);
    cudaGetSymbolAddress((void**)&kqvh, g_kqvh);
    cudaGetSymbolAddress((void**)&aoh, g_aoh);

    cudaFuncSetAttribute(gemm_h<1>,
                         cudaFuncAttributeMaxDynamicSharedMemorySize, GEMM_SMEM);
    cudaFuncSetAttribute(gemm_h<0>,
                         cudaFuncAttributeMaxDynamicSharedMemorySize, GEMM_SMEM);
    cudaFuncSetAttribute(attn_mma,
                         cudaFuncAttributeMaxDynamicSharedMemorySize, ATT_SMEM);

    // 0) x/W1/W2 -> fp16
    {
        int n4;
        n4 = MROWS * DD / 4;   round_kernel<<<(n4 + 255) / 256, 256>>>(x,  xh,  n4);
        n4 = DD * 3 * DD / 4;  round_kernel<<<(n4 + 255) / 256, 256>>>(W1, w1h, n4);
        n4 = DD * DD / 4;      round_kernel<<<(n4 + 255) / 256, 256>>>(W2, w2h, n4);
    }
    // 1) kqv = x @ W1 + b1  (fp16 output)
    {
        dim3 grid(3 * DD / 128, MROWS / 128);
        gemm_h<1><<<grid, 128, GEMM_SMEM>>>(xh, w1h, b1, nullptr, kqvh,
                                            MROWS, 3 * DD, DD);
    }
    // 2) causal retention attention
    {
        dim3 grid(TT / 128, HH, BB);
        attn_mma<<<grid, 128, ATT_SMEM>>>(kqvh, aoh);
    }
    // 3) out = ao @ W2 + b2  (fp32 output)
    {
        dim3 grid(DD / 128, MROWS / 128);
        gemm_h<0><<<grid, 128, GEMM_SMEM>>>(aoh, w2h, b2, out, nullptr,
                                            MROWS, DD, DD);
    }
}

// round 11
// speedup vs baseline: 7.2958x; 1.0341x over previous
#include <cuda_runtime.h>
#include <cuda_fp16.h>

#define BB 2
#define TT 2048
#define DD 1024
#define HH 16
#define DH 64
#define MROWS (BB*TT)
#define KQV_LD (3*DD)

// fp16 operands (device globals; allocation is forbidden)
__device__ __half g_xh [(size_t)MROWS*DD];
__device__ __half g_w1h[(size_t)DD*3*DD];   // natural [K][N]
__device__ __half g_w2h[(size_t)DD*DD];
__device__ __half g_kqvh[(size_t)MROWS*3*DD];
__device__ __half g_aoh[(size_t)MROWS*DD];

// ---------------------------------------------------------------------------
// helpers
// ---------------------------------------------------------------------------
__device__ __forceinline__ unsigned h2_pack(__half a, __half b) {
    __half2 t = __halves2half2(a, b);
    return *reinterpret_cast<unsigned*>(&t);
}
__device__ __forceinline__ unsigned hpack2(float x, float y) {
    return h2_pack(__float2half_rn(x), __float2half_rn(y));
}
__device__ __forceinline__ void mma16816(float* c,
    unsigned a0, unsigned a1, unsigned a2, unsigned a3,
    unsigned b0, unsigned b1)
{
    asm volatile(
        "mma.sync.aligned.m16n8k16.row.col.f32.f16.f16.f32 "
        "{%0,%1,%2,%3},{%4,%5,%6,%7},{%8,%9},{%0,%1,%2,%3};\n"
        : "+f"(c[0]), "+f"(c[1]), "+f"(c[2]), "+f"(c[3])
        : "r"(a0), "r"(a1), "r"(a2), "r"(a3), "r"(b0), "r"(b1));
}
__device__ __forceinline__ void ldsm4(unsigned* r, const void* p) {
    unsigned a = (unsigned)__cvta_generic_to_shared(p);
    asm volatile("ldmatrix.sync.aligned.m8n8.x4.shared.b16 {%0,%1,%2,%3}, [%4];\n"
        : "=r"(r[0]), "=r"(r[1]), "=r"(r[2]), "=r"(r[3]) : "r"(a));
}
__device__ __forceinline__ void ldsm4t(unsigned* r, const void* p) {
    unsigned a = (unsigned)__cvta_generic_to_shared(p);
    asm volatile("ldmatrix.sync.aligned.m8n8.x4.trans.shared.b16 {%0,%1,%2,%3}, [%4];\n"
        : "=r"(r[0]), "=r"(r[1]), "=r"(r[2]), "=r"(r[3]) : "r"(a));
}
__device__ __forceinline__ void cp16(void* sp, const void* gp) {
    unsigned s = (unsigned)__cvta_generic_to_shared(sp);
    asm volatile("cp.async.cg.shared.global [%0], [%1], 16;\n" :: "r"(s), "l"(gp));
}
#define CP_COMMIT() asm volatile("cp.async.commit_group;\n")
#define CP_WAIT(n)  asm volatile("cp.async.wait_group %0;\n" :: "n"(n))

// ---------------------------------------------------------------------------
// prep: fp32 -> fp16 (round)
// ---------------------------------------------------------------------------
__global__ void round_kernel(const float* __restrict__ in,
                             __half* __restrict__ hi, int n4)
{
    int i = blockIdx.x * blockDim.x + threadIdx.x;
    if (i >= n4) return;
    float4 v = reinterpret_cast<const float4*>(in)[i];
    reinterpret_cast<uint2*>(hi)[i] = make_uint2(hpack2(v.x, v.y), hpack2(v.z, v.w));
}

// ---------------------------------------------------------------------------
// fp16 single-product GEMM: C = A @ B + bias
// CTA 128x128, BK=64, 3-stage cp.async, 4 warps (2m x 2n), warp tile 64x64.
// A and B fragments register double-buffered. OMODE: 0 = fp32 C, 1 = fp16 C.
// ---------------------------------------------------------------------------
#define APG 72
#define BPG 136
#define SA_ST (128*APG)
#define SB_ST (64*BPG)
#define NSG 3
#define GEMM_SMEM ((NSG*SA_ST + NSG*SB_ST) * 2)   // 107520 B

#define GEMM_LOAD(s, k0)                                                        \
    {                                                                           \
        _Pragma("unroll")                                                       \
        for (int j = 0; j < 8; j++) {                                           \
            const int id = tid + 128 * j;                                       \
            const int arow = id >> 3, ac = (id & 7) * 8;                        \
            const size_t ga = (size_t)(m0 + arow) * K + (k0) + ac;              \
            cp16(sA + (s)*SA_ST + arow*APG + ac, Ah_g + ga);                    \
            const int brow = id >> 4, bc = (id & 15) * 8;                       \
            const size_t gb = (size_t)((k0) + brow) * N + n0 + bc;              \
            cp16(sB + (s)*SB_ST + brow*BPG + bc, Bh_g + gb);                    \
        }                                                                       \
        CP_COMMIT();                                                            \
    }

template<int OMODE>
__global__ __launch_bounds__(128, 2) void gemm_h(
    const __half* __restrict__ Ah_g,
    const __half* __restrict__ Bh_g,
    const float* __restrict__ bias,
    float* __restrict__ C, __half* __restrict__ Ch,
    int M, int N, int K)
{
    extern __shared__ __half smg[];
    __half* sA = smg;                       // [stage][128*APG]
    __half* sB = smg + NSG*SA_ST;           // [stage][64*BPG] natural [k][n]

    const int tid = threadIdx.x, warp = tid >> 5, lane = tid & 31;
    const int m0 = blockIdx.y * 128, n0 = blockIdx.x * 128;
    const int wm = (warp & 1) * 64, wn = (warp >> 1) * 64;

    float acc[4][8][4];
#pragma unroll
    for (int i = 0; i < 4; i++)
#pragma unroll
        for (int j = 0; j < 8; j++)
#pragma unroll
            for (int l = 0; l < 4; l++) acc[i][j][l] = 0.f;

    GEMM_LOAD(0, 0);
    GEMM_LOAD(1, 64);

    const int brr = (lane & 8) + (lane & 7);
    const int bcsel = (lane >> 1) & 8;
    const int arr = (lane & 15), akk = ((lane & 16) >> 1);

    const int ntiles = K / 64;
    for (int t = 0; t < ntiles; t++) {
        if (t + 1 < ntiles) { CP_WAIT(1); } else { CP_WAIT(0); }
        __syncthreads();      // stage t visible; all warps done with stage (t-1)
        if (t + 2 < ntiles) GEMM_LOAD((t + 2) % NSG, (t + 2) * 64);

        const int s = t % NSG;
        const __half* Ahs = sA + s*SA_ST;
        const __half* Bhs = sB + s*SB_ST;

        // register double-buffered fragments
        unsigned bb[2][4][4], aa[2][4];
#pragma unroll
        for (int np = 0; np < 4; np++)
            ldsm4t(bb[0][np], Bhs + brr * BPG + wn + np * 16 + bcsel);

#pragma unroll
        for (int ki = 0; ki < 4; ki++) {
            const int ks = ki * 16;
            // prefetch next B set during this ks' MMAs
            if (ki < 3) {
#pragma unroll
                for (int np = 0; np < 4; np++)
                    ldsm4t(bb[(ki + 1) & 1][np], Bhs + (ks + 16 + brr) * BPG + wn + np * 16 + bcsel);
            }
            ldsm4(aa[0], Ahs + (wm + arr) * APG + ks + akk);
#pragma unroll
            for (int mt = 0; mt < 4; mt++) {
                if (mt < 3)
                    ldsm4(aa[(mt + 1) & 1], Ahs + (wm + (mt + 1) * 16 + arr) * APG + ks + akk);
                const unsigned* a = aa[mt & 1];
#pragma unroll
                for (int nt = 0; nt < 8; nt++) {
                    mma16816(acc[mt][nt], a[0], a[1], a[2], a[3],
                             bb[ki & 1][nt >> 1][(nt & 1) * 2],
                             bb[ki & 1][nt >> 1][(nt & 1) * 2 + 1]);
                }
            }
        }
    }

    const int g = lane >> 2, tg = lane & 3;
#pragma unroll
    for (int mt = 0; mt < 4; mt++) {
        const int r = m0 + wm + mt * 16 + g;
#pragma unroll
        for (int nt = 0; nt < 8; nt++) {
            const int c = n0 + wn + nt * 8 + tg * 2;
            const float bx = bias[c], by = bias[c + 1];
            const float v0 = acc[mt][nt][0] + bx, v1 = acc[mt][nt][1] + by;
            const float v2 = acc[mt][nt][2] + bx, v3 = acc[mt][nt][3] + by;
            if (OMODE == 1) {
                *reinterpret_cast<unsigned*>(&Ch[(size_t)r * N + c])       = hpack2(v0, v1);
                *reinterpret_cast<unsigned*>(&Ch[(size_t)(r + 8) * N + c]) = hpack2(v2, v3);
            } else {
                float2 o0 = {v0, v1}, o1 = {v2, v3};
                *reinterpret_cast<float2*>(&C[(size_t)r * N + c])       = o0;
                *reinterpret_cast<float2*>(&C[(size_t)(r + 8) * N + c]) = o1;
            }
        }
    }
}

// ---------------------------------------------------------------------------
// Fused causal retention attention, fp16 hi-only (single product per phase).
// 4 warps (128 thr), warp tile 64q x 32(k|d). K/V double-buffered cp.async.
// ---------------------------------------------------------------------------
#define AP 72
#define KV_ST (64*AP)
#define KVBUF (2*KV_ST)               // Kh, Vh for one stage
#define ATT_SMEM ((128*AP + 2*KVBUF + 128*AP) * 2)   // 73728 B

#define ATT_LOAD(kb)                                                           \
    {                                                                          \
        const int _k0 = (kb) * 64;                                             \
        __half* _buf = KV + ((kb) & 1) * KVBUF;                                \
        _Pragma("unroll")                                                      \
        for (int _j = 0; _j < 4; _j++) {                                       \
            const int _id = tid + 128 * _j;                                    \
            const int _row = _id >> 3, _c8 = (_id & 7) * 8;                    \
            const size_t _g = (size_t)(_k0 + _row) * KQV_LD + _c8;             \
            const int _d = _row * AP + _c8;                                    \
            cp16(_buf + 0*KV_ST + _d, Khg + _g);                               \
            cp16(_buf + 1*KV_ST + _d, Vhg + _g);                               \
        }                                                                      \
        CP_COMMIT();                                                           \
    }

__global__ __launch_bounds__(128, 2) void attn_mma(
    const __half* __restrict__ kqvh, __half* __restrict__ aoh)
{
    extern __shared__ __half sma[];
    __half *Qh = sma;
    __half *KV = Qh + 128 * AP;           // [2][Kh|Vh][64*AP]
    __half *Sh = KV + 2 * KVBUF;

    const int tid = threadIdx.x, warp = tid >> 5, lane = tid & 31;
    const int g = lane >> 2, tg = lane & 3;
    const int qb = gridDim.x - 1 - blockIdx.x;    // heavy tiles first
    const int h = blockIdx.y, b = blockIdx.z;
    const int q0 = qb * 128;

    const size_t hoff = (size_t)b * TT * KQV_LD + h * DH;
    const __half *Khg = kqvh + hoff;
    const __half *Qhg = Khg + DD;
    const __half *Vhg = Khg + 2*DD;

    // prologue: start K/V load for kb=0
    ATT_LOAD(0);

    // load Q tile 128x64
#pragma unroll
    for (int j = 0; j < 8; j++) {
        const int id = tid + 128 * j;
        const int row = id >> 3, c8 = (id & 7) * 8;
        const size_t gq = (size_t)(q0 + row) * KQV_LD + c8;
        *reinterpret_cast<uint4*>(&Qh[row * AP + c8]) = *reinterpret_cast<const uint4*>(&Qhg[gq]);
    }

    const int wq = (warp & 1) * 64;     // q offset
    const int wkd = (warp >> 1) * 32;   // k (S) / d (O) offset

    float oacc[4][4][4];
#pragma unroll
    for (int i = 0; i < 4; i++)
#pragma unroll
        for (int j = 0; j < 4; j++)
#pragma unroll
            for (int l = 0; l < 4; l++) oacc[i][j][l] = 0.f;

    const int nkb = 2 * qb + 2;
    for (int kb = 0; kb < nkb; kb++) {
        const int k0 = kb * 64;
        CP_WAIT(0);
        __syncthreads();      // K/V kb visible; prev iter done with S/KV

        if (kb + 1 < nkb) ATT_LOAD(kb + 1);   // overlaps this iter's compute

        const __half* buf = KV + (kb & 1) * KVBUF;
        const __half* Khs = buf + 0*KV_ST;
        const __half* Vhs = buf + 1*KV_ST;

        // ---- S = Q K^T (warp: 64q x 32k) ----
        float sacc[4][4][4];
#pragma unroll
        for (int i = 0; i < 4; i++)
#pragma unroll
            for (int j = 0; j < 4; j++)
#pragma unroll
                for (int l = 0; l < 4; l++) sacc[i][j][l] = 0.f;

#pragma unroll
        for (int ds = 0; ds < 64; ds += 16) {
            unsigned bh[2][4];
            const int kc = ds + (lane & 8);
#pragma unroll
            for (int np = 0; np < 2; np++) {
                const int kr = wkd + np * 16 + ((lane >> 1) & 8) + (lane & 7);
                ldsm4(bh[np], Khs + kr * AP + kc);
            }
#pragma unroll
            for (int mt = 0; mt < 4; mt++) {
                unsigned qh[4];
                const int r = (wq + mt * 16 + (lane & 15)) * AP + ds + ((lane & 16) >> 1);
                ldsm4(qh, Qh + r);
#pragma unroll
                for (int nt = 0; nt < 4; nt++) {
                    mma16816(sacc[mt][nt], qh[0], qh[1], qh[2], qh[3],
                             bh[nt >> 1][(nt & 1) * 2], bh[nt >> 1][(nt & 1) * 2 + 1]);
                }
            }
        }

        // mask (diagonal) + store S (fp16)
        const bool diag = (kb >= 2 * qb);
#pragma unroll
        for (int mt = 0; mt < 4; mt++) {
            const int qr = wq + mt * 16 + g;
#pragma unroll
            for (int nt = 0; nt < 4; nt++) {
                const int kc = wkd + nt * 8 + tg * 2;
                float s0 = sacc[mt][nt][0], s1 = sacc[mt][nt][1];
                float s2 = sacc[mt][nt][2], s3 = sacc[mt][nt][3];
                if (diag) {
                    const int qg0 = q0 + qr, qg8 = qg0 + 8, kg = k0 + kc;
                    if (kg     > qg0) s0 = 0.f;
                    if (kg + 1 > qg0) s1 = 0.f;
                    if (kg     > qg8) s2 = 0.f;
                    if (kg + 1 > qg8) s3 = 0.f;
                }
                const int idx = qr * AP + kc;
                *reinterpret_cast<unsigned*>(&Sh[idx])          = hpack2(s0, s1);
                *reinterpret_cast<unsigned*>(&Sh[idx + 8 * AP]) = hpack2(s2, s3);
            }
        }
        __syncthreads();

        // ---- O += S V (warp: 64q x 32d) ----
#pragma unroll
        for (int ks = 0; ks < 64; ks += 16) {
            unsigned vh[2][4];
            const int vr = ks + (lane & 8) + (lane & 7);
#pragma unroll
            for (int np = 0; np < 2; np++) {
                const int vc = wkd + np * 16 + ((lane >> 1) & 8);
                ldsm4t(vh[np], Vhs + vr * AP + vc);
            }
#pragma unroll
            for (int mt = 0; mt < 4; mt++) {
                unsigned sh4[4];
                const int r = (wq + mt * 16 + (lane & 15)) * AP + ks + ((lane & 16) >> 1);
                ldsm4(sh4, Sh + r);
#pragma unroll
                for (int nt = 0; nt < 4; nt++) {
                    mma16816(oacc[mt][nt], sh4[0], sh4[1], sh4[2], sh4[3],
                             vh[nt >> 1][(nt & 1) * 2], vh[nt >> 1][(nt & 1) * 2 + 1]);
                }
            }
        }
    }

    // write O (fp16) -> aoh[b*TT + q, h*64 + d]
#pragma unroll
    for (int mt = 0; mt < 4; mt++) {
        const size_t t = (size_t)b * TT + q0 + wq + mt * 16 + g;
#pragma unroll
        for (int nt = 0; nt < 4; nt++) {
            const int c = h * DH + wkd + nt * 8 + tg * 2;
            *reinterpret_cast<unsigned*>(&aoh[t * DD + c])       = hpack2(oacc[mt][nt][0], oacc[mt][nt][1]);
            *reinterpret_cast<unsigned*>(&aoh[(t + 8) * DD + c]) = hpack2(oacc[mt][nt][2], oacc[mt][nt][3]);
        }
    }
}

// ---------------------------------------------------------------------------
extern "C" void kernel_launch(void* const* d_in, const int* in_sizes, int n_in,
                              void* d_out, int out_size)
{
    const float* x  = (const float*)d_in[0];
    const float* W1 = (const float*)d_in[1];
    const float* b1 = (const float*)d_in[2];
    const float* W2 = (const float*)d_in[3];
    const float* b2 = (const float*)d_in[4];
    float* out = (float*)d_out;

    __half *xh, *w1h, *w2h, *kqvh, *aoh;
    cudaGetSymbolAddress((void**)&xh,  g_xh);
    cudaGetSymbolAddress((void**)&w1h, g_w1h);
    cudaGetSymbolAddress((void**)&w2h, g_w2h);
    cudaGetSymbolAddress((void**)&kqvh, g_kqvh);
    cudaGetSymbolAddress((void**)&aoh, g_aoh);

    cudaFuncSetAttribute(gemm_h<1>,
                         cudaFuncAttributeMaxDynamicSharedMemorySize, GEMM_SMEM);
    cudaFuncSetAttribute(gemm_h<0>,
                         cudaFuncAttributeMaxDynamicSharedMemorySize, GEMM_SMEM);
    cudaFuncSetAttribute(attn_mma,
                         cudaFuncAttributeMaxDynamicSharedMemorySize, ATT_SMEM);

    // 0) x/W1/W2 -> fp16
    {
        int n4;
        n4 = MROWS * DD / 4;   round_kernel<<<(n4 + 255) / 256, 256>>>(x,  xh,  n4);
        n4 = DD * 3 * DD / 4;  round_kernel<<<(n4 + 255) / 256, 256>>>(W1, w1h, n4);
        n4 = DD * DD / 4;      round_kernel<<<(n4 + 255) / 256, 256>>>(W2, w2h, n4);
    }
    // 1) kqv = x @ W1 + b1  (fp16 output)
    {
        dim3 grid(3 * DD / 128, MROWS / 128);
        gemm_h<1><<<grid, 128, GEMM_SMEM>>>(xh, w1h, b1, nullptr, kqvh,
                                            MROWS, 3 * DD, DD);
    }
    // 2) causal retention attention
    {
        dim3 grid(TT / 128, HH, BB);
        attn_mma<<<grid, 128, ATT_SMEM>>>(kqvh, aoh);
    }
    // 3) out = ao @ W2 + b2  (fp32 output)
    {
        dim3 grid(DD / 128, MROWS / 128);
        gemm_h<0><<<grid, 128, GEMM_SMEM>>>(aoh, w2h, b2, out, nullptr,
                                            MROWS, DD, DD);
    }
}

// round 12
// speedup vs baseline: 7.6551x; 1.0492x over previous
#include <cuda_runtime.h>
#include <cuda_fp16.h>

#define BB 2
#define TT 2048
#define DD 1024
#define HH 16
#define DH 64
#define MROWS (BB*TT)
#define KQV_LD (3*DD)

// fp16 operands (device globals; allocation is forbidden)
__device__ __half g_xh [(size_t)MROWS*DD];
__device__ __half g_w1h[(size_t)DD*3*DD];   // natural [K][N]
__device__ __half g_w2h[(size_t)DD*DD];
__device__ __half g_kqvh[(size_t)MROWS*3*DD];
__device__ __half g_aoh[(size_t)MROWS*DD];

// ---------------------------------------------------------------------------
// helpers
// ---------------------------------------------------------------------------
__device__ __forceinline__ unsigned h2_pack(__half a, __half b) {
    __half2 t = __halves2half2(a, b);
    return *reinterpret_cast<unsigned*>(&t);
}
__device__ __forceinline__ unsigned hpack2(float x, float y) {
    return h2_pack(__float2half_rn(x), __float2half_rn(y));
}
__device__ __forceinline__ void mma16816(float* c,
    unsigned a0, unsigned a1, unsigned a2, unsigned a3,
    unsigned b0, unsigned b1)
{
    asm volatile(
        "mma.sync.aligned.m16n8k16.row.col.f32.f16.f16.f32 "
        "{%0,%1,%2,%3},{%4,%5,%6,%7},{%8,%9},{%0,%1,%2,%3};\n"
        : "+f"(c[0]), "+f"(c[1]), "+f"(c[2]), "+f"(c[3])
        : "r"(a0), "r"(a1), "r"(a2), "r"(a3), "r"(b0), "r"(b1));
}
__device__ __forceinline__ void ldsm4(unsigned* r, const void* p) {
    unsigned a = (unsigned)__cvta_generic_to_shared(p);
    asm volatile("ldmatrix.sync.aligned.m8n8.x4.shared.b16 {%0,%1,%2,%3}, [%4];\n"
        : "=r"(r[0]), "=r"(r[1]), "=r"(r[2]), "=r"(r[3]) : "r"(a));
}
__device__ __forceinline__ void ldsm4t(unsigned* r, const void* p) {
    unsigned a = (unsigned)__cvta_generic_to_shared(p);
    asm volatile("ldmatrix.sync.aligned.m8n8.x4.trans.shared.b16 {%0,%1,%2,%3}, [%4];\n"
        : "=r"(r[0]), "=r"(r[1]), "=r"(r[2]), "=r"(r[3]) : "r"(a));
}
__device__ __forceinline__ void cp16(void* sp, const void* gp) {
    unsigned s = (unsigned)__cvta_generic_to_shared(sp);
    asm volatile("cp.async.cg.shared.global [%0], [%1], 16;\n" :: "r"(s), "l"(gp));
}
#define CP_COMMIT() asm volatile("cp.async.commit_group;\n")
#define CP_WAIT(n)  asm volatile("cp.async.wait_group %0;\n" :: "n"(n))

// ---------------------------------------------------------------------------
// prep: fp32 -> fp16 (round)
// ---------------------------------------------------------------------------
__global__ void round_kernel(const float* __restrict__ in,
                             __half* __restrict__ hi, int n4)
{
    int i = blockIdx.x * blockDim.x + threadIdx.x;
    if (i >= n4) return;
    float4 v = reinterpret_cast<const float4*>(in)[i];
    reinterpret_cast<uint2*>(hi)[i] = make_uint2(hpack2(v.x, v.y), hpack2(v.z, v.w));
}

// ---------------------------------------------------------------------------
// fp16 single-product GEMM: C = A @ B + bias  (unchanged from R11)
// CTA 128x128, BK=64, 3-stage cp.async, 4 warps (2m x 2n), warp tile 64x64.
// ---------------------------------------------------------------------------
#define APG 72
#define BPG 136
#define SA_ST (128*APG)
#define SB_ST (64*BPG)
#define NSG 3
#define GEMM_SMEM ((NSG*SA_ST + NSG*SB_ST) * 2)   // 107520 B

#define GEMM_LOAD(s, k0)                                                        \
    {                                                                           \
        _Pragma("unroll")                                                       \
        for (int j = 0; j < 8; j++) {                                           \
            const int id = tid + 128 * j;                                       \
            const int arow = id >> 3, ac = (id & 7) * 8;                        \
            const size_t ga = (size_t)(m0 + arow) * K + (k0) + ac;              \
            cp16(sA + (s)*SA_ST + arow*APG + ac, Ah_g + ga);                    \
            const int brow = id >> 4, bc = (id & 15) * 8;                       \
            const size_t gb = (size_t)((k0) + brow) * N + n0 + bc;              \
            cp16(sB + (s)*SB_ST + brow*BPG + bc, Bh_g + gb);                    \
        }                                                                       \
        CP_COMMIT();                                                            \
    }

template<int OMODE>
__global__ __launch_bounds__(128, 2) void gemm_h(
    const __half* __restrict__ Ah_g,
    const __half* __restrict__ Bh_g,
    const float* __restrict__ bias,
    float* __restrict__ C, __half* __restrict__ Ch,
    int M, int N, int K)
{
    extern __shared__ __half smg[];
    __half* sA = smg;
    __half* sB = smg + NSG*SA_ST;

    const int tid = threadIdx.x, warp = tid >> 5, lane = tid & 31;
    const int m0 = blockIdx.y * 128, n0 = blockIdx.x * 128;
    const int wm = (warp & 1) * 64, wn = (warp >> 1) * 64;

    float acc[4][8][4];
#pragma unroll
    for (int i = 0; i < 4; i++)
#pragma unroll
        for (int j = 0; j < 8; j++)
#pragma unroll
            for (int l = 0; l < 4; l++) acc[i][j][l] = 0.f;

    GEMM_LOAD(0, 0);
    GEMM_LOAD(1, 64);

    const int brr = (lane & 8) + (lane & 7);
    const int bcsel = (lane >> 1) & 8;
    const int arr = (lane & 15), akk = ((lane & 16) >> 1);

    const int ntiles = K / 64;
    for (int t = 0; t < ntiles; t++) {
        if (t + 1 < ntiles) { CP_WAIT(1); } else { CP_WAIT(0); }
        __syncthreads();
        if (t + 2 < ntiles) GEMM_LOAD((t + 2) % NSG, (t + 2) * 64);

        const int s = t % NSG;
        const __half* Ahs = sA + s*SA_ST;
        const __half* Bhs = sB + s*SB_ST;

        unsigned bb[2][4][4], aa[2][4];
#pragma unroll
        for (int np = 0; np < 4; np++)
            ldsm4t(bb[0][np], Bhs + brr * BPG + wn + np * 16 + bcsel);

#pragma unroll
        for (int ki = 0; ki < 4; ki++) {
            const int ks = ki * 16;
            if (ki < 3) {
#pragma unroll
                for (int np = 0; np < 4; np++)
                    ldsm4t(bb[(ki + 1) & 1][np], Bhs + (ks + 16 + brr) * BPG + wn + np * 16 + bcsel);
            }
            ldsm4(aa[0], Ahs + (wm + arr) * APG + ks + akk);
#pragma unroll
            for (int mt = 0; mt < 4; mt++) {
                if (mt < 3)
                    ldsm4(aa[(mt + 1) & 1], Ahs + (wm + (mt + 1) * 16 + arr) * APG + ks + akk);
                const unsigned* a = aa[mt & 1];
#pragma unroll
                for (int nt = 0; nt < 8; nt++) {
                    mma16816(acc[mt][nt], a[0], a[1], a[2], a[3],
                             bb[ki & 1][nt >> 1][(nt & 1) * 2],
                             bb[ki & 1][nt >> 1][(nt & 1) * 2 + 1]);
                }
            }
        }
    }

    const int g = lane >> 2, tg = lane & 3;
#pragma unroll
    for (int mt = 0; mt < 4; mt++) {
        const int r = m0 + wm + mt * 16 + g;
#pragma unroll
        for (int nt = 0; nt < 8; nt++) {
            const int c = n0 + wn + nt * 8 + tg * 2;
            const float bx = bias[c], by = bias[c + 1];
            const float v0 = acc[mt][nt][0] + bx, v1 = acc[mt][nt][1] + by;
            const float v2 = acc[mt][nt][2] + bx, v3 = acc[mt][nt][3] + by;
            if (OMODE == 1) {
                *reinterpret_cast<unsigned*>(&Ch[(size_t)r * N + c])       = hpack2(v0, v1);
                *reinterpret_cast<unsigned*>(&Ch[(size_t)(r + 8) * N + c]) = hpack2(v2, v3);
            } else {
                float2 o0 = {v0, v1}, o1 = {v2, v3};
                *reinterpret_cast<float2*>(&C[(size_t)r * N + c])       = o0;
                *reinterpret_cast<float2*>(&C[(size_t)(r + 8) * N + c]) = o1;
            }
        }
    }
}

// ---------------------------------------------------------------------------
// Fused causal retention attention, FA2-style register S reuse.
// 4 warps (128 thr); warp w owns q-rows [32w, 32w+32), full 64 k / 64 d.
// S lives in registers: C-frag of QK^T packed to fp16 = A-frag of S·V.
// Q fragments cached in registers across all k-tiles. One barrier per k-tile.
// ---------------------------------------------------------------------------
#define AP 72
#define KV_ST (64*AP)
#define KVBUF (2*KV_ST)               // Kh, Vh for one stage
#define ATT_SMEM ((128*AP + 2*KVBUF) * 2)   // 55296 B

#define ATT_LOAD(kb)                                                           \
    {                                                                          \
        const int _k0 = (kb) * 64;                                             \
        __half* _buf = KV + ((kb) & 1) * KVBUF;                                \
        _Pragma("unroll")                                                      \
        for (int _j = 0; _j < 4; _j++) {                                       \
            const int _id = tid + 128 * _j;                                    \
            const int _row = _id >> 3, _c8 = (_id & 7) * 8;                    \
            const size_t _g = (size_t)(_k0 + _row) * KQV_LD + _c8;             \
            const int _d = _row * AP + _c8;                                    \
            cp16(_buf + 0*KV_ST + _d, Khg + _g);                               \
            cp16(_buf + 1*KV_ST + _d, Vhg + _g);                               \
        }                                                                      \
        CP_COMMIT();                                                           \
    }

__global__ __launch_bounds__(128, 2) void attn_mma(
    const __half* __restrict__ kqvh, __half* __restrict__ aoh)
{
    extern __shared__ __half sma[];
    __half *Qh = sma;
    __half *KV = Qh + 128 * AP;           // [2][Kh|Vh][64*AP]

    const int tid = threadIdx.x, warp = tid >> 5, lane = tid & 31;
    const int g = lane >> 2, tg = lane & 3;
    const int qb = gridDim.x - 1 - blockIdx.x;    // heavy tiles first
    const int h = blockIdx.y, b = blockIdx.z;
    const int q0 = qb * 128;

    const size_t hoff = (size_t)b * TT * KQV_LD + h * DH;
    const __half *Khg = kqvh + hoff;
    const __half *Qhg = Khg + DD;
    const __half *Vhg = Khg + 2*DD;

    // prologue: start K/V load for kb=0
    ATT_LOAD(0);

    // load Q tile 128x64 to smem
#pragma unroll
    for (int j = 0; j < 8; j++) {
        const int id = tid + 128 * j;
        const int row = id >> 3, c8 = (id & 7) * 8;
        const size_t gq = (size_t)(q0 + row) * KQV_LD + c8;
        *reinterpret_cast<uint4*>(&Qh[row * AP + c8]) = *reinterpret_cast<const uint4*>(&Qhg[gq]);
    }
    __syncthreads();

    const int wq = warp * 32;             // warp's q offset (32 rows)

    // cache Q fragments in registers: qf[mt][dsi][4]  (mt: 2x16 rows, dsi: 4x16 d)
    unsigned qf[2][4][4];
#pragma unroll
    for (int mt = 0; mt < 2; mt++)
#pragma unroll
        for (int dsi = 0; dsi < 4; dsi++)
            ldsm4(qf[mt][dsi], Qh + (wq + mt * 16 + (lane & 15)) * AP + dsi * 16 + ((lane & 16) >> 1));

    float oacc[2][8][4];
#pragma unroll
    for (int i = 0; i < 2; i++)
#pragma unroll
        for (int j = 0; j < 8; j++)
#pragma unroll
            for (int l = 0; l < 4; l++) oacc[i][j][l] = 0.f;

    const int krr = (lane >> 1) & 8;      // ldsm row-group select for K (n-dim)
    const int kdd = lane & 8;             // ldsm col select (d/k dim)
    const int vrr = (lane & 8) + (lane & 7);
    const int vcc = (lane >> 1) & 8;

    const int nkb = 2 * qb + 2;
    for (int kb = 0; kb < nkb; kb++) {
        const int k0 = kb * 64;
        CP_WAIT(0);
        __syncthreads();      // K/V kb visible; all warps done with prev KV reads

        if (kb + 1 < nkb) ATT_LOAD(kb + 1);   // overlaps this iter's compute

        const __half* buf = KV + (kb & 1) * KVBUF;
        const __half* Khs = buf + 0*KV_ST;
        const __half* Vhs = buf + 1*KV_ST;

        // ---- S = Q K^T (warp: 32q x 64k), accumulate fp32 in registers ----
        float sacc[2][8][4];
#pragma unroll
        for (int i = 0; i < 2; i++)
#pragma unroll
            for (int j = 0; j < 8; j++)
#pragma unroll
                for (int l = 0; l < 4; l++) sacc[i][j][l] = 0.f;

#pragma unroll
        for (int dsi = 0; dsi < 4; dsi++) {
            const int ds = dsi * 16;
            unsigned bh[4][4];
#pragma unroll
            for (int np = 0; np < 4; np++) {
                const int kr = np * 16 + krr + (lane & 7);   // k-col rows 0..63
                ldsm4(bh[np], Khs + kr * AP + ds + kdd);
            }
#pragma unroll
            for (int mt = 0; mt < 2; mt++) {
#pragma unroll
                for (int nt = 0; nt < 8; nt++) {
                    mma16816(sacc[mt][nt], qf[mt][dsi][0], qf[mt][dsi][1],
                             qf[mt][dsi][2], qf[mt][dsi][3],
                             bh[nt >> 1][(nt & 1) * 2], bh[nt >> 1][(nt & 1) * 2 + 1]);
                }
            }
        }

        // ---- mask (diagonal) + in-register pack to A-fragments ----
        const bool diag = (kb >= 2 * qb);
        unsigned aS[2][4][4];   // [mt][kchunk][4]
#pragma unroll
        for (int mt = 0; mt < 2; mt++) {
            const int qg0 = q0 + wq + mt * 16 + g;
            const int qg8 = qg0 + 8;
#pragma unroll
            for (int nt = 0; nt < 8; nt++) {
                float s0 = sacc[mt][nt][0], s1 = sacc[mt][nt][1];
                float s2 = sacc[mt][nt][2], s3 = sacc[mt][nt][3];
                if (diag) {
                    const int kg = k0 + nt * 8 + tg * 2;
                    if (kg     > qg0) s0 = 0.f;
                    if (kg + 1 > qg0) s1 = 0.f;
                    if (kg     > qg8) s2 = 0.f;
                    if (kg + 1 > qg8) s3 = 0.f;
                }
                const int kc4 = nt >> 1, hi = (nt & 1) * 2;
                aS[mt][kc4][hi + 0] = hpack2(s0, s1);
                aS[mt][kc4][hi + 1] = hpack2(s2, s3);
            }
        }

        // ---- O += S V (warp: 32q x 64d), S from registers ----
#pragma unroll
        for (int kc4 = 0; kc4 < 4; kc4++) {
            const int ks = kc4 * 16;
            unsigned vh[4][4];
#pragma unroll
            for (int np = 0; np < 4; np++)
                ldsm4t(vh[np], Vhs + (ks + vrr) * AP + np * 16 + vcc);
#pragma unroll
            for (int mt = 0; mt < 2; mt++) {
                // A-frag order for m16n8k16: {k0-7 rows g,g+8} then {k8-15}
                const unsigned a0 = aS[mt][kc4][0], a1 = aS[mt][kc4][1];
                const unsigned a2 = aS[mt][kc4][2], a3 = aS[mt][kc4][3];
#pragma unroll
                for (int nt = 0; nt < 8; nt++) {
                    mma16816(oacc[mt][nt], a0, a1, a2, a3,
                             vh[nt >> 1][(nt & 1) * 2], vh[nt >> 1][(nt & 1) * 2 + 1]);
                }
            }
        }
    }

    // write O (fp16) -> aoh[b*TT + q, h*64 + d]
#pragma unroll
    for (int mt = 0; mt < 2; mt++) {
        const size_t t = (size_t)b * TT + q0 + wq + mt * 16 + g;
#pragma unroll
        for (int nt = 0; nt < 8; nt++) {
            const int c = h * DH + nt * 8 + tg * 2;
            *reinterpret_cast<unsigned*>(&aoh[t * DD + c])       = hpack2(oacc[mt][nt][0], oacc[mt][nt][1]);
            *reinterpret_cast<unsigned*>(&aoh[(t + 8) * DD + c]) = hpack2(oacc[mt][nt][2], oacc[mt][nt][3]);
        }
    }
}

// ---------------------------------------------------------------------------
extern "C" void kernel_launch(void* const* d_in, const int* in_sizes, int n_in,
                              void* d_out, int out_size)
{
    const float* x  = (const float*)d_in[0];
    const float* W1 = (const float*)d_in[1];
    const float* b1 = (const float*)d_in[2];
    const float* W2 = (const float*)d_in[3];
    const float* b2 = (const float*)d_in[4];
    float* out = (float*)d_out;

    __half *xh, *w1h, *w2h, *kqvh, *aoh;
    cudaGetSymbolAddress((void**)&xh,  g_xh);
    cudaGetSymbolAddress((void**)&w1h, g_w1h);
    cudaGetSymbolAddress((void**)&w2h, g_w2h);
    cudaGetSymbolAddress((void**)&kqvh, g_kqvh);
    cudaGetSymbolAddress((void**)&aoh, g_aoh);

    cudaFuncSetAttribute(gemm_h<1>,
                         cudaFuncAttributeMaxDynamicSharedMemorySize, GEMM_SMEM);
    cudaFuncSetAttribute(gemm_h<0>,
                         cudaFuncAttributeMaxDynamicSharedMemorySize, GEMM_SMEM);
    cudaFuncSetAttribute(attn_mma,
                         cudaFuncAttributeMaxDynamicSharedMemorySize, ATT_SMEM);

    // 0) x/W1/W2 -> fp16
    {
        int n4;
        n4 = MROWS * DD / 4;   round_kernel<<<(n4 + 255) / 256, 256>>>(x,  xh,  n4);
        n4 = DD * 3 * DD / 4;  round_kernel<<<(n4 + 255) / 256, 256>>>(W1, w1h, n4);
        n4 = DD * DD / 4;      round_kernel<<<(n4 + 255) / 256, 256>>>(W2, w2h, n4);
    }
    // 1) kqv = x @ W1 + b1  (fp16 output)
    {
        dim3 grid(3 * DD / 128, MROWS / 128);
        gemm_h<1><<<grid, 128, GEMM_SMEM>>>(xh, w1h, b1, nullptr, kqvh,
                                            MROWS, 3 * DD, DD);
    }
    // 2) causal retention attention (FA2 register-S)
    {
        dim3 grid(TT / 128, HH, BB);
        attn_mma<<<grid, 128, ATT_SMEM>>>(kqvh, aoh);
    }
    // 3) out = ao @ W2 + b2  (fp32 output)
    {
        dim3 grid(DD / 128, MROWS / 128);
        gemm_h<0><<<grid, 128, GEMM_SMEM>>>(aoh, w2h, b2, out, nullptr,
                                            MROWS, DD, DD);
    }
}

// round 13
// speedup vs baseline: 9.9672x; 1.3020x over previous
#include <cuda_runtime.h>
#include <cuda_fp16.h>

#define BB 2
#define TT 2048
#define DD 1024
#define HH 16
#define DH 64
#define MROWS (BB*TT)
#define KQV_LD (3*DD)
#define NCHUNK 32          // 2048 / 64

// fp16 operands + scratch (device globals; allocation is forbidden)
__device__ __half g_xh [(size_t)MROWS*DD];
__device__ __half g_w1h[(size_t)DD*3*DD];   // natural [K][N]
__device__ __half g_w2h[(size_t)DD*DD];
__device__ __half g_kqvh[(size_t)MROWS*3*DD];
__device__ __half g_aoh[(size_t)MROWS*DD];
__device__ float  g_C  [(size_t)BB*HH*NCHUNK*DH*DH];   // per-chunk K^T V (fp32)
__device__ __half g_ph [(size_t)BB*HH*NCHUNK*DH*DH];   // exclusive prefix, hi
__device__ __half g_pl [(size_t)BB*HH*NCHUNK*DH*DH];   // exclusive prefix, lo

// ---------------------------------------------------------------------------
// helpers
// ---------------------------------------------------------------------------
__device__ __forceinline__ unsigned h2_pack(__half a, __half b) {
    __half2 t = __halves2half2(a, b);
    return *reinterpret_cast<unsigned*>(&t);
}
__device__ __forceinline__ unsigned hpack2(float x, float y) {
    return h2_pack(__float2half_rn(x), __float2half_rn(y));
}
__device__ __forceinline__ void mma16816(float* c,
    unsigned a0, unsigned a1, unsigned a2, unsigned a3,
    unsigned b0, unsigned b1)
{
    asm volatile(
        "mma.sync.aligned.m16n8k16.row.col.f32.f16.f16.f32 "
        "{%0,%1,%2,%3},{%4,%5,%6,%7},{%8,%9},{%0,%1,%2,%3};\n"
        : "+f"(c[0]), "+f"(c[1]), "+f"(c[2]), "+f"(c[3])
        : "r"(a0), "r"(a1), "r"(a2), "r"(a3), "r"(b0), "r"(b1));
}
__device__ __forceinline__ void ldsm4(unsigned* r, const void* p) {
    unsigned a = (unsigned)__cvta_generic_to_shared(p);
    asm volatile("ldmatrix.sync.aligned.m8n8.x4.shared.b16 {%0,%1,%2,%3}, [%4];\n"
        : "=r"(r[0]), "=r"(r[1]), "=r"(r[2]), "=r"(r[3]) : "r"(a));
}
__device__ __forceinline__ void ldsm4t(unsigned* r, const void* p) {
    unsigned a = (unsigned)__cvta_generic_to_shared(p);
    asm volatile("ldmatrix.sync.aligned.m8n8.x4.trans.shared.b16 {%0,%1,%2,%3}, [%4];\n"
        : "=r"(r[0]), "=r"(r[1]), "=r"(r[2]), "=r"(r[3]) : "r"(a));
}
__device__ __forceinline__ void cp16(void* sp, const void* gp) {
    unsigned s = (unsigned)__cvta_generic_to_shared(sp);
    asm volatile("cp.async.cg.shared.global [%0], [%1], 16;\n" :: "r"(s), "l"(gp));
}
#define CP_COMMIT() asm volatile("cp.async.commit_group;\n")
#define CP_WAIT(n)  asm volatile("cp.async.wait_group %0;\n" :: "n"(n))

// ---------------------------------------------------------------------------
// prep: one kernel converts x, W1, W2 -> fp16
// ---------------------------------------------------------------------------
#define NX4  (MROWS*DD/4)
#define NW14 (DD*3*DD/4)
#define NW24 (DD*DD/4)
__global__ void prep_all(const float* __restrict__ x,
                         const float* __restrict__ W1,
                         const float* __restrict__ W2,
                         __half* __restrict__ xh,
                         __half* __restrict__ w1h,
                         __half* __restrict__ w2h)
{
    int i = blockIdx.x * blockDim.x + threadIdx.x;
    const float* src; __half* dst; int off;
    if (i < NX4)                   { src = x;  dst = xh;  off = i; }
    else if (i < NX4 + NW14)       { src = W1; dst = w1h; off = i - NX4; }
    else if (i < NX4 + NW14 + NW24){ src = W2; dst = w2h; off = i - NX4 - NW14; }
    else return;
    float4 v = reinterpret_cast<const float4*>(src)[off];
    reinterpret_cast<uint2*>(dst)[off] = make_uint2(hpack2(v.x, v.y), hpack2(v.z, v.w));
}

// ---------------------------------------------------------------------------
// fp16 single-product GEMM (unchanged, proven R11/R12)
// ---------------------------------------------------------------------------
#define APG 72
#define BPG 136
#define SA_ST (128*APG)
#define SB_ST (64*BPG)
#define NSG 3
#define GEMM_SMEM ((NSG*SA_ST + NSG*SB_ST) * 2)

#define GEMM_LOAD(s, k0)                                                        \
    {                                                                           \
        _Pragma("unroll")                                                       \
        for (int j = 0; j < 8; j++) {                                           \
            const int id = tid + 128 * j;                                       \
            const int arow = id >> 3, ac = (id & 7) * 8;                        \
            const size_t ga = (size_t)(m0 + arow) * K + (k0) + ac;              \
            cp16(sA + (s)*SA_ST + arow*APG + ac, Ah_g + ga);                    \
            const int brow = id >> 4, bc = (id & 15) * 8;                       \
            const size_t gb = (size_t)((k0) + brow) * N + n0 + bc;              \
            cp16(sB + (s)*SB_ST + brow*BPG + bc, Bh_g + gb);                    \
        }                                                                       \
        CP_COMMIT();                                                            \
    }

template<int OMODE>
__global__ __launch_bounds__(128, 2) void gemm_h(
    const __half* __restrict__ Ah_g,
    const __half* __restrict__ Bh_g,
    const float* __restrict__ bias,
    float* __restrict__ C, __half* __restrict__ Ch,
    int M, int N, int K)
{
    extern __shared__ __half smg[];
    __half* sA = smg;
    __half* sB = smg + NSG*SA_ST;

    const int tid = threadIdx.x, warp = tid >> 5, lane = tid & 31;
    const int m0 = blockIdx.y * 128, n0 = blockIdx.x * 128;
    const int wm = (warp & 1) * 64, wn = (warp >> 1) * 64;

    float acc[4][8][4];
#pragma unroll
    for (int i = 0; i < 4; i++)
#pragma unroll
        for (int j = 0; j < 8; j++)
#pragma unroll
            for (int l = 0; l < 4; l++) acc[i][j][l] = 0.f;

    GEMM_LOAD(0, 0);
    GEMM_LOAD(1, 64);

    const int brr = (lane & 8) + (lane & 7);
    const int bcsel = (lane >> 1) & 8;
    const int arr = (lane & 15), akk = ((lane & 16) >> 1);

    const int ntiles = K / 64;
    for (int t = 0; t < ntiles; t++) {
        if (t + 1 < ntiles) { CP_WAIT(1); } else { CP_WAIT(0); }
        __syncthreads();
        if (t + 2 < ntiles) GEMM_LOAD((t + 2) % NSG, (t + 2) * 64);

        const int s = t % NSG;
        const __half* Ahs = sA + s*SA_ST;
        const __half* Bhs = sB + s*SB_ST;

        unsigned bb[2][4][4], aa[2][4];
#pragma unroll
        for (int np = 0; np < 4; np++)
            ldsm4t(bb[0][np], Bhs + brr * BPG + wn + np * 16 + bcsel);

#pragma unroll
        for (int ki = 0; ki < 4; ki++) {
            const int ks = ki * 16;
            if (ki < 3) {
#pragma unroll
                for (int np = 0; np < 4; np++)
                    ldsm4t(bb[(ki + 1) & 1][np], Bhs + (ks + 16 + brr) * BPG + wn + np * 16 + bcsel);
            }
            ldsm4(aa[0], Ahs + (wm + arr) * APG + ks + akk);
#pragma unroll
            for (int mt = 0; mt < 4; mt++) {
                if (mt < 3)
                    ldsm4(aa[(mt + 1) & 1], Ahs + (wm + (mt + 1) * 16 + arr) * APG + ks + akk);
                const unsigned* a = aa[mt & 1];
#pragma unroll
                for (int nt = 0; nt < 8; nt++) {
                    mma16816(acc[mt][nt], a[0], a[1], a[2], a[3],
                             bb[ki & 1][nt >> 1][(nt & 1) * 2],
                             bb[ki & 1][nt >> 1][(nt & 1) * 2 + 1]);
                }
            }
        }
    }

    const int g = lane >> 2, tg = lane & 3;
#pragma unroll
    for (int mt = 0; mt < 4; mt++) {
        const int r = m0 + wm + mt * 16 + g;
#pragma unroll
        for (int nt = 0; nt < 8; nt++) {
            const int c = n0 + wn + nt * 8 + tg * 2;
            const float bx = bias[c], by = bias[c + 1];
            const float v0 = acc[mt][nt][0] + bx, v1 = acc[mt][nt][1] + by;
            const float v2 = acc[mt][nt][2] + bx, v3 = acc[mt][nt][3] + by;
            if (OMODE == 1) {
                *reinterpret_cast<unsigned*>(&Ch[(size_t)r * N + c])       = hpack2(v0, v1);
                *reinterpret_cast<unsigned*>(&Ch[(size_t)(r + 8) * N + c]) = hpack2(v2, v3);
            } else {
                float2 o0 = {v0, v1}, o1 = {v2, v3};
                *reinterpret_cast<float2*>(&C[(size_t)r * N + c])       = o0;
                *reinterpret_cast<float2*>(&C[(size_t)(r + 8) * N + c]) = o1;
            }
        }
    }
}

// ---------------------------------------------------------------------------
// Kernel A: per-(b,h,chunk) outer-product sum  C_c = K_c^T V_c  (64x64 fp32)
// 4 warps, warp w computes d1 rows [16w, 16w+16) x all 64 d2.
// ---------------------------------------------------------------------------
#define AP 72
__global__ __launch_bounds__(128, 2) void kv_outer(
    const __half* __restrict__ kqvh, float* __restrict__ Cc)
{
    __shared__ __half Ks[64*AP], Vs[64*AP];

    const int tid = threadIdx.x, warp = tid >> 5, lane = tid & 31;
    const int chunk = blockIdx.x, h = blockIdx.y, b = blockIdx.z;
    const int k0 = chunk * 64;

    const size_t hoff = (size_t)b * TT * KQV_LD + h * DH;
    const __half *Khg = kqvh + hoff;
    const __half *Vhg = Khg + 2*DD;

#pragma unroll
    for (int j = 0; j < 4; j++) {
        const int id = tid + 128 * j;
        const int row = id >> 3, c8 = (id & 7) * 8;
        const size_t gk = (size_t)(k0 + row) * KQV_LD + c8;
        cp16(Ks + row * AP + c8, Khg + gk);
        cp16(Vs + row * AP + c8, Vhg + gk);
    }
    CP_COMMIT();
    CP_WAIT(0);
    __syncthreads();

    const int m = warp * 16;                       // d1 base
    const int vrr = (lane & 8) + (lane & 7);       // B-frag row pattern
    const int vcc = (lane >> 1) & 8;
    const int arow = ((lane & 16) >> 1) + (lane & 7);  // A-frag (trans) row
    const int acol = lane & 8;                          // A-frag (trans) col

    float cacc[8][4];
#pragma unroll
    for (int j = 0; j < 8; j++)
#pragma unroll
        for (int l = 0; l < 4; l++) cacc[j][l] = 0.f;

#pragma unroll
    for (int ks = 0; ks < 64; ks += 16) {
        unsigned af[4];
        ldsm4t(af, Ks + (ks + arow) * AP + m + acol);   // A = K^T fragment
        unsigned vf[4][4];
#pragma unroll
        for (int np = 0; np < 4; np++)
            ldsm4t(vf[np], Vs + (ks + vrr) * AP + np * 16 + vcc);
#pragma unroll
        for (int nt = 0; nt < 8; nt++)
            mma16816(cacc[nt], af[0], af[1], af[2], af[3],
                     vf[nt >> 1][(nt & 1) * 2], vf[nt >> 1][(nt & 1) * 2 + 1]);
    }

    const int g = lane >> 2, tg = lane & 3;
    const size_t cbase = ((size_t)(b * HH + h) * NCHUNK + chunk) * (DH * DH);
#pragma unroll
    for (int nt = 0; nt < 8; nt++) {
        const int col = nt * 8 + tg * 2;
        const int r0 = m + g;
        float2 o0 = {cacc[nt][0], cacc[nt][1]};
        float2 o1 = {cacc[nt][2], cacc[nt][3]};
        *reinterpret_cast<float2*>(&Cc[cbase + (size_t)r0 * 64 + col])       = o0;
        *reinterpret_cast<float2*>(&Cc[cbase + (size_t)(r0 + 8) * 64 + col]) = o1;
    }
}

// ---------------------------------------------------------------------------
// Kernel B: exclusive prefix over chunks, split to fp16 hi/lo.
// grid (32 bh, 16 eblocks), 256 thr; each thread owns one of 4096 elements.
// ---------------------------------------------------------------------------
__global__ void prefix_split(const float* __restrict__ Cc,
                             __half* __restrict__ ph, __half* __restrict__ pl)
{
    const int bh = blockIdx.x;
    const int e  = blockIdx.y * 256 + threadIdx.x;     // 0..4095
    const size_t base = (size_t)bh * NCHUNK * (DH*DH) + e;
    float run = 0.f;
#pragma unroll 4
    for (int c = 0; c < NCHUNK; c++) {
        const __half hi = __float2half_rn(run);
        ph[base + (size_t)c * (DH*DH)] = hi;
        pl[base + (size_t)c * (DH*DH)] = __float2half_rn(run - __half2float(hi));
        run += Cc[base + (size_t)c * (DH*DH)];
    }
}

// ---------------------------------------------------------------------------
// Kernel C: per-(b,h,chunk)  O_c = Q_c P_prev(hi+lo) + tril(Q_c K_c^T) V_c
// 4 warps, warp w owns q rows [16w, 16w+16) x all 64 d.
// ---------------------------------------------------------------------------
#define ATTC_SMEM (5 * 64 * AP * 2)   // Qs,Ks,Vs,Ph,Pl = 46080 B

__global__ __launch_bounds__(128, 2) void attn_chunk(
    const __half* __restrict__ kqvh,
    const __half* __restrict__ ph, const __half* __restrict__ pl,
    __half* __restrict__ aoh)
{
    extern __shared__ __half smc[];
    __half *Qs = smc;
    __half *Ks = Qs + 64*AP;
    __half *Vs = Ks + 64*AP;
    __half *Ph = Vs + 64*AP;
    __half *Pl = Ph + 64*AP;

    const int tid = threadIdx.x, warp = tid >> 5, lane = tid & 31;
    const int chunk = blockIdx.x, h = blockIdx.y, b = blockIdx.z;
    const int q0 = chunk * 64;
    const int bh = b * HH + h;

    const size_t hoff = (size_t)b * TT * KQV_LD + h * DH;
    const __half *Khg = kqvh + hoff;
    const __half *Qhg = Khg + DD;
    const __half *Vhg = Khg + 2*DD;
    const size_t pbase = ((size_t)bh * NCHUNK + chunk) * (DH*DH);

#pragma unroll
    for (int j = 0; j < 4; j++) {
        const int id = tid + 128 * j;
        const int row = id >> 3, c8 = (id & 7) * 8;
        const size_t gk = (size_t)(q0 + row) * KQV_LD + c8;
        const int d = row * AP + c8;
        cp16(Qs + d, Qhg + gk);
        cp16(Ks + d, Khg + gk);
        cp16(Vs + d, Vhg + gk);
        const size_t pp = pbase + (size_t)row * 64 + c8;
        cp16(Ph + d, ph + pp);
        cp16(Pl + d, pl + pp);
    }
    CP_COMMIT();
    CP_WAIT(0);
    __syncthreads();

    const int wq = warp * 16;
    const int g = lane >> 2, tg = lane & 3;
    const int vrr = (lane & 8) + (lane & 7);
    const int vcc = (lane >> 1) & 8;
    const int krr = (lane >> 1) & 8;
    const int kdd = lane & 8;

    // Q fragments (A-operand, row-major)
    unsigned qf[4][4];
#pragma unroll
    for (int dsi = 0; dsi < 4; dsi++)
        ldsm4(qf[dsi], Qs + (wq + (lane & 15)) * AP + dsi * 16 + ((lane & 16) >> 1));

    float oacc[8][4];
#pragma unroll
    for (int j = 0; j < 8; j++)
#pragma unroll
        for (int l = 0; l < 4; l++) oacc[j][l] = 0.f;

    // ---- O = Q * P_prev (hi + lo) ----
#pragma unroll
    for (int dsi = 0; dsi < 4; dsi++) {
        const int ds = dsi * 16;
        unsigned phf[4][4], plf[4][4];
#pragma unroll
        for (int np = 0; np < 4; np++) {
            ldsm4t(phf[np], Ph + (ds + vrr) * AP + np * 16 + vcc);
            ldsm4t(plf[np], Pl + (ds + vrr) * AP + np * 16 + vcc);
        }
#pragma unroll
        for (int nt = 0; nt < 8; nt++) {
            mma16816(oacc[nt], qf[dsi][0], qf[dsi][1], qf[dsi][2], qf[dsi][3],
                     phf[nt >> 1][(nt & 1) * 2], phf[nt >> 1][(nt & 1) * 2 + 1]);
            mma16816(oacc[nt], qf[dsi][0], qf[dsi][1], qf[dsi][2], qf[dsi][3],
                     plf[nt >> 1][(nt & 1) * 2], plf[nt >> 1][(nt & 1) * 2 + 1]);
        }
    }

    // ---- S = Q K^T (intra-chunk) ----
    float sacc[8][4];
#pragma unroll
    for (int j = 0; j < 8; j++)
#pragma unroll
        for (int l = 0; l < 4; l++) sacc[j][l] = 0.f;

#pragma unroll
    for (int dsi = 0; dsi < 4; dsi++) {
        const int ds = dsi * 16;
        unsigned kf[4][4];
#pragma unroll
        for (int np = 0; np < 4; np++)
            ldsm4(kf[np], Ks + (np * 16 + krr + (lane & 7)) * AP + ds + kdd);
#pragma unroll
        for (int nt = 0; nt < 8; nt++)
            mma16816(sacc[nt], qf[dsi][0], qf[dsi][1], qf[dsi][2], qf[dsi][3],
                     kf[nt >> 1][(nt & 1) * 2], kf[nt >> 1][(nt & 1) * 2 + 1]);
    }

    // mask (local tril) + pack to A-fragments
    const int qr0 = wq + g, qr8 = qr0 + 8;
    unsigned aS[4][4];
#pragma unroll
    for (int nt = 0; nt < 8; nt++) {
        const int kc = nt * 8 + tg * 2;
        float s0 = sacc[nt][0], s1 = sacc[nt][1];
        float s2 = sacc[nt][2], s3 = sacc[nt][3];
        if (kc     > qr0) s0 = 0.f;
        if (kc + 1 > qr0) s1 = 0.f;
        if (kc     > qr8) s2 = 0.f;
        if (kc + 1 > qr8) s3 = 0.f;
        aS[nt >> 1][(nt & 1) * 2 + 0] = hpack2(s0, s1);
        aS[nt >> 1][(nt & 1) * 2 + 1] = hpack2(s2, s3);
    }

    // ---- O += S V (intra) ----
#pragma unroll
    for (int kc4 = 0; kc4 < 4; kc4++) {
        const int ks = kc4 * 16;
        unsigned vf[4][4];
#pragma unroll
        for (int np = 0; np < 4; np++)
            ldsm4t(vf[np], Vs + (ks + vrr) * AP + np * 16 + vcc);
#pragma unroll
        for (int nt = 0; nt < 8; nt++)
            mma16816(oacc[nt], aS[kc4][0], aS[kc4][1], aS[kc4][2], aS[kc4][3],
                     vf[nt >> 1][(nt & 1) * 2], vf[nt >> 1][(nt & 1) * 2 + 1]);
    }

    // write O (fp16)
    const size_t t = (size_t)b * TT + q0 + wq + g;
#pragma unroll
    for (int nt = 0; nt < 8; nt++) {
        const int c = h * DH + nt * 8 + tg * 2;
        *reinterpret_cast<unsigned*>(&aoh[t * DD + c])       = hpack2(oacc[nt][0], oacc[nt][1]);
        *reinterpret_cast<unsigned*>(&aoh[(t + 8) * DD + c]) = hpack2(oacc[nt][2], oacc[nt][3]);
    }
}

// ---------------------------------------------------------------------------
extern "C" void kernel_launch(void* const* d_in, const int* in_sizes, int n_in,
                              void* d_out, int out_size)
{
    const float* x  = (const float*)d_in[0];
    const float* W1 = (const float*)d_in[1];
    const float* b1 = (const float*)d_in[2];
    const float* W2 = (const float*)d_in[3];
    const float* b2 = (const float*)d_in[4];
    float* out = (float*)d_out;

    __half *xh, *w1h, *w2h, *kqvh, *aoh, *ph, *pl;
    float* Cc;
    cudaGetSymbolAddress((void**)&xh,  g_xh);
    cudaGetSymbolAddress((void**)&w1h, g_w1h);
    cudaGetSymbolAddress((void**)&w2h, g_w2h);
    cudaGetSymbolAddress((void**)&kqvh, g_kqvh);
    cudaGetSymbolAddress((void**)&aoh, g_aoh);
    cudaGetSymbolAddress((void**)&Cc,  g_C);
    cudaGetSymbolAddress((void**)&ph,  g_ph);
    cudaGetSymbolAddress((void**)&pl,  g_pl);

    cudaFuncSetAttribute(gemm_h<1>,
                         cudaFuncAttributeMaxDynamicSharedMemorySize, GEMM_SMEM);
    cudaFuncSetAttribute(gemm_h<0>,
                         cudaFuncAttributeMaxDynamicSharedMemorySize, GEMM_SMEM);
    cudaFuncSetAttribute(attn_chunk,
                         cudaFuncAttributeMaxDynamicSharedMemorySize, ATTC_SMEM);

    // 0) x/W1/W2 -> fp16 (single fused launch)
    {
        const int total = NX4 + NW14 + NW24;
        prep_all<<<(total + 255) / 256, 256>>>(x, W1, W2, xh, w1h, w2h);
    }
    // 1) kqv = x @ W1 + b1  (fp16 output)
    {
        dim3 grid(3 * DD / 128, MROWS / 128);
        gemm_h<1><<<grid, 128, GEMM_SMEM>>>(xh, w1h, b1, nullptr, kqvh,
                                            MROWS, 3 * DD, DD);
    }
    // 2a) per-chunk outer products C_c = K_c^T V_c
    {
        dim3 grid(NCHUNK, HH, BB);
        kv_outer<<<grid, 128>>>(kqvh, Cc);
    }
    // 2b) exclusive prefix over chunks + fp16 split
    {
        dim3 grid(BB * HH, (DH * DH) / 256);
        prefix_split<<<grid, 256>>>(Cc, ph, pl);
    }
    // 2c) O_c = Q_c P_prev + tril(Q_c K_c^T) V_c
    {
        dim3 grid(NCHUNK, HH, BB);
        attn_chunk<<<grid, 128, ATTC_SMEM>>>(kqvh, ph, pl, aoh);
    }
    // 3) out = ao @ W2 + b2  (fp32 output)
    {
        dim3 grid(DD / 128, MROWS / 128);
        gemm_h<0><<<grid, 128, GEMM_SMEM>>>(aoh, w2h, b2, out, nullptr,
                                            MROWS, DD, DD);
    }
}

// round 14
// speedup vs baseline: 10.1268x; 1.0160x over previous
#include <cuda_runtime.h>
#include <cuda_fp16.h>

#define BB 2
#define TT 2048
#define DD 1024
#define HH 16
#define DH 64
#define MROWS (BB*TT)
#define KQV_LD (3*DD)
#define NCHUNK 32          // 2048 / 64

// fp16 operands + scratch (device globals; allocation is forbidden)
__device__ __half g_xh [(size_t)MROWS*DD];
__device__ __half g_w1h[(size_t)DD*3*DD];   // natural [K][N]
__device__ __half g_w2h[(size_t)DD*DD];
__device__ __half g_kqvh[(size_t)MROWS*3*DD];
__device__ __half g_aoh[(size_t)MROWS*DD];
__device__ float  g_C  [(size_t)BB*HH*NCHUNK*DH*DH];   // per-chunk K^T V (fp32)
__device__ __half g_ph [(size_t)BB*HH*NCHUNK*DH*DH];   // exclusive prefix (fp16)

// ---------------------------------------------------------------------------
// helpers
// ---------------------------------------------------------------------------
__device__ __forceinline__ unsigned h2_pack(__half a, __half b) {
    __half2 t = __halves2half2(a, b);
    return *reinterpret_cast<unsigned*>(&t);
}
__device__ __forceinline__ unsigned hpack2(float x, float y) {
    return h2_pack(__float2half_rn(x), __float2half_rn(y));
}
__device__ __forceinline__ void mma16816(float* c,
    unsigned a0, unsigned a1, unsigned a2, unsigned a3,
    unsigned b0, unsigned b1)
{
    asm volatile(
        "mma.sync.aligned.m16n8k16.row.col.f32.f16.f16.f32 "
        "{%0,%1,%2,%3},{%4,%5,%6,%7},{%8,%9},{%0,%1,%2,%3};\n"
        : "+f"(c[0]), "+f"(c[1]), "+f"(c[2]), "+f"(c[3])
        : "r"(a0), "r"(a1), "r"(a2), "r"(a3), "r"(b0), "r"(b1));
}
__device__ __forceinline__ void ldsm4(unsigned* r, const void* p) {
    unsigned a = (unsigned)__cvta_generic_to_shared(p);
    asm volatile("ldmatrix.sync.aligned.m8n8.x4.shared.b16 {%0,%1,%2,%3}, [%4];\n"
        : "=r"(r[0]), "=r"(r[1]), "=r"(r[2]), "=r"(r[3]) : "r"(a));
}
__device__ __forceinline__ void ldsm4t(unsigned* r, const void* p) {
    unsigned a = (unsigned)__cvta_generic_to_shared(p);
    asm volatile("ldmatrix.sync.aligned.m8n8.x4.trans.shared.b16 {%0,%1,%2,%3}, [%4];\n"
        : "=r"(r[0]), "=r"(r[1]), "=r"(r[2]), "=r"(r[3]) : "r"(a));
}
__device__ __forceinline__ void cp16(void* sp, const void* gp) {
    unsigned s = (unsigned)__cvta_generic_to_shared(sp);
    asm volatile("cp.async.cg.shared.global [%0], [%1], 16;\n" :: "r"(s), "l"(gp));
}
#define CP_COMMIT() asm volatile("cp.async.commit_group;\n")
#define CP_WAIT(n)  asm volatile("cp.async.wait_group %0;\n" :: "n"(n))

// ---------------------------------------------------------------------------
// prep: one kernel converts x, W1, W2 -> fp16
// ---------------------------------------------------------------------------
#define NX4  (MROWS*DD/4)
#define NW14 (DD*3*DD/4)
#define NW24 (DD*DD/4)
__global__ void prep_all(const float* __restrict__ x,
                         const float* __restrict__ W1,
                         const float* __restrict__ W2,
                         __half* __restrict__ xh,
                         __half* __restrict__ w1h,
                         __half* __restrict__ w2h)
{
    int i = blockIdx.x * blockDim.x + threadIdx.x;
    const float* src; __half* dst; int off;
    if (i < NX4)                   { src = x;  dst = xh;  off = i; }
    else if (i < NX4 + NW14)       { src = W1; dst = w1h; off = i - NX4; }
    else if (i < NX4 + NW14 + NW24){ src = W2; dst = w2h; off = i - NX4 - NW14; }
    else return;
    float4 v = reinterpret_cast<const float4*>(src)[off];
    reinterpret_cast<uint2*>(dst)[off] = make_uint2(hpack2(v.x, v.y), hpack2(v.z, v.w));
}

// ---------------------------------------------------------------------------
// fp16 single-product GEMM (unchanged, proven R11/R12)
// ---------------------------------------------------------------------------
#define APG 72
#define BPG 136
#define SA_ST (128*APG)
#define SB_ST (64*BPG)
#define NSG 3
#define GEMM_SMEM ((NSG*SA_ST + NSG*SB_ST) * 2)

#define GEMM_LOAD(s, k0)                                                        \
    {                                                                           \
        _Pragma("unroll")                                                       \
        for (int j = 0; j < 8; j++) {                                           \
            const int id = tid + 128 * j;                                       \
            const int arow = id >> 3, ac = (id & 7) * 8;                        \
            const size_t ga = (size_t)(m0 + arow) * K + (k0) + ac;              \
            cp16(sA + (s)*SA_ST + arow*APG + ac, Ah_g + ga);                    \
            const int brow = id >> 4, bc = (id & 15) * 8;                       \
            const size_t gb = (size_t)((k0) + brow) * N + n0 + bc;              \
            cp16(sB + (s)*SB_ST + brow*BPG + bc, Bh_g + gb);                    \
        }                                                                       \
        CP_COMMIT();                                                            \
    }

template<int OMODE>
__global__ __launch_bounds__(128, 2) void gemm_h(
    const __half* __restrict__ Ah_g,
    const __half* __restrict__ Bh_g,
    const float* __restrict__ bias,
    float* __restrict__ C, __half* __restrict__ Ch,
    int M, int N, int K)
{
    extern __shared__ __half smg[];
    __half* sA = smg;
    __half* sB = smg + NSG*SA_ST;

    const int tid = threadIdx.x, warp = tid >> 5, lane = tid & 31;
    const int m0 = blockIdx.y * 128, n0 = blockIdx.x * 128;
    const int wm = (warp & 1) * 64, wn = (warp >> 1) * 64;

    float acc[4][8][4];
#pragma unroll
    for (int i = 0; i < 4; i++)
#pragma unroll
        for (int j = 0; j < 8; j++)
#pragma unroll
            for (int l = 0; l < 4; l++) acc[i][j][l] = 0.f;

    GEMM_LOAD(0, 0);
    GEMM_LOAD(1, 64);

    const int brr = (lane & 8) + (lane & 7);
    const int bcsel = (lane >> 1) & 8;
    const int arr = (lane & 15), akk = ((lane & 16) >> 1);

    const int ntiles = K / 64;
    for (int t = 0; t < ntiles; t++) {
        if (t + 1 < ntiles) { CP_WAIT(1); } else { CP_WAIT(0); }
        __syncthreads();
        if (t + 2 < ntiles) GEMM_LOAD((t + 2) % NSG, (t + 2) * 64);

        const int s = t % NSG;
        const __half* Ahs = sA + s*SA_ST;
        const __half* Bhs = sB + s*SB_ST;

        unsigned bb[2][4][4], aa[2][4];
#pragma unroll
        for (int np = 0; np < 4; np++)
            ldsm4t(bb[0][np], Bhs + brr * BPG + wn + np * 16 + bcsel);

#pragma unroll
        for (int ki = 0; ki < 4; ki++) {
            const int ks = ki * 16;
            if (ki < 3) {
#pragma unroll
                for (int np = 0; np < 4; np++)
                    ldsm4t(bb[(ki + 1) & 1][np], Bhs + (ks + 16 + brr) * BPG + wn + np * 16 + bcsel);
            }
            ldsm4(aa[0], Ahs + (wm + arr) * APG + ks + akk);
#pragma unroll
            for (int mt = 0; mt < 4; mt++) {
                if (mt < 3)
                    ldsm4(aa[(mt + 1) & 1], Ahs + (wm + (mt + 1) * 16 + arr) * APG + ks + akk);
                const unsigned* a = aa[mt & 1];
#pragma unroll
                for (int nt = 0; nt < 8; nt++) {
                    mma16816(acc[mt][nt], a[0], a[1], a[2], a[3],
                             bb[ki & 1][nt >> 1][(nt & 1) * 2],
                             bb[ki & 1][nt >> 1][(nt & 1) * 2 + 1]);
                }
            }
        }
    }

    const int g = lane >> 2, tg = lane & 3;
#pragma unroll
    for (int mt = 0; mt < 4; mt++) {
        const int r = m0 + wm + mt * 16 + g;
#pragma unroll
        for (int nt = 0; nt < 8; nt++) {
            const int c = n0 + wn + nt * 8 + tg * 2;
            const float bx = bias[c], by = bias[c + 1];
            const float v0 = acc[mt][nt][0] + bx, v1 = acc[mt][nt][1] + by;
            const float v2 = acc[mt][nt][2] + bx, v3 = acc[mt][nt][3] + by;
            if (OMODE == 1) {
                *reinterpret_cast<unsigned*>(&Ch[(size_t)r * N + c])       = hpack2(v0, v1);
                *reinterpret_cast<unsigned*>(&Ch[(size_t)(r + 8) * N + c]) = hpack2(v2, v3);
            } else {
                float2 o0 = {v0, v1}, o1 = {v2, v3};
                *reinterpret_cast<float2*>(&C[(size_t)r * N + c])       = o0;
                *reinterpret_cast<float2*>(&C[(size_t)(r + 8) * N + c]) = o1;
            }
        }
    }
}

// ---------------------------------------------------------------------------
// Kernel A: per-(b,h,chunk) outer-product sum  C_c = K_c^T V_c  (64x64 fp32)
// ---------------------------------------------------------------------------
#define AP 72
__global__ __launch_bounds__(128, 2) void kv_outer(
    const __half* __restrict__ kqvh, float* __restrict__ Cc)
{
    __shared__ __half Ks[64*AP], Vs[64*AP];

    const int tid = threadIdx.x, warp = tid >> 5, lane = tid & 31;
    const int chunk = blockIdx.x, h = blockIdx.y, b = blockIdx.z;
    const int k0 = chunk * 64;

    const size_t hoff = (size_t)b * TT * KQV_LD + h * DH;
    const __half *Khg = kqvh + hoff;
    const __half *Vhg = Khg + 2*DD;

#pragma unroll
    for (int j = 0; j < 4; j++) {
        const int id = tid + 128 * j;
        const int row = id >> 3, c8 = (id & 7) * 8;
        const size_t gk = (size_t)(k0 + row) * KQV_LD + c8;
        cp16(Ks + row * AP + c8, Khg + gk);
        cp16(Vs + row * AP + c8, Vhg + gk);
    }
    CP_COMMIT();
    CP_WAIT(0);
    __syncthreads();

    const int m = warp * 16;
    const int vrr = (lane & 8) + (lane & 7);
    const int vcc = (lane >> 1) & 8;
    const int arow = ((lane & 16) >> 1) + (lane & 7);
    const int acol = lane & 8;

    float cacc[8][4];
#pragma unroll
    for (int j = 0; j < 8; j++)
#pragma unroll
        for (int l = 0; l < 4; l++) cacc[j][l] = 0.f;

#pragma unroll
    for (int ks = 0; ks < 64; ks += 16) {
        unsigned af[4];
        ldsm4t(af, Ks + (ks + arow) * AP + m + acol);
        unsigned vf[4][4];
#pragma unroll
        for (int np = 0; np < 4; np++)
            ldsm4t(vf[np], Vs + (ks + vrr) * AP + np * 16 + vcc);
#pragma unroll
        for (int nt = 0; nt < 8; nt++)
            mma16816(cacc[nt], af[0], af[1], af[2], af[3],
                     vf[nt >> 1][(nt & 1) * 2], vf[nt >> 1][(nt & 1) * 2 + 1]);
    }

    const int g = lane >> 2, tg = lane & 3;
    const size_t cbase = ((size_t)(b * HH + h) * NCHUNK + chunk) * (DH * DH);
#pragma unroll
    for (int nt = 0; nt < 8; nt++) {
        const int col = nt * 8 + tg * 2;
        const int r0 = m + g;
        float2 o0 = {cacc[nt][0], cacc[nt][1]};
        float2 o1 = {cacc[nt][2], cacc[nt][3]};
        *reinterpret_cast<float2*>(&Cc[cbase + (size_t)r0 * 64 + col])       = o0;
        *reinterpret_cast<float2*>(&Cc[cbase + (size_t)(r0 + 8) * 64 + col]) = o1;
    }
}

// ---------------------------------------------------------------------------
// Kernel B: exclusive prefix over chunks -> fp16 (vectorized float4/thread)
// grid (32 bh, 4), 256 thr; each thread owns 4 consecutive elements.
// ---------------------------------------------------------------------------
__global__ void prefix_split(const float* __restrict__ Cc,
                             __half* __restrict__ ph)
{
    const int bh = blockIdx.x;
    const int e4 = blockIdx.y * 256 + threadIdx.x;       // 0..1023 float4 slots
    const size_t base4 = (size_t)bh * NCHUNK * (DH*DH/4) + e4;

    float4 run = {0.f, 0.f, 0.f, 0.f};
    float4 v = reinterpret_cast<const float4*>(Cc)[base4];
#pragma unroll 8
    for (int c = 0; c < NCHUNK; c++) {
        const size_t idx = base4 + (size_t)c * (DH*DH/4);
        reinterpret_cast<uint2*>(ph)[idx] =
            make_uint2(hpack2(run.x, run.y), hpack2(run.z, run.w));
        float4 vn;
        if (c + 1 < NCHUNK)
            vn = reinterpret_cast<const float4*>(Cc)[idx + (DH*DH/4)];
        run.x += v.x; run.y += v.y; run.z += v.z; run.w += v.w;
        v = vn;
    }
}

// ---------------------------------------------------------------------------
// Kernel C: per-(b,h,chunk)  O_c = Q_c P_prev + tril(Q_c K_c^T) V_c
// 4 warps, warp w owns q rows [16w, 16w+16) x all 64 d. P hi-only.
// ---------------------------------------------------------------------------
#define ATTC_SMEM (4 * 64 * AP * 2)   // Qs,Ks,Vs,Ph = 36864 B

__global__ __launch_bounds__(128, 2) void attn_chunk(
    const __half* __restrict__ kqvh,
    const __half* __restrict__ ph,
    __half* __restrict__ aoh)
{
    extern __shared__ __half smc[];
    __half *Qs = smc;
    __half *Ks = Qs + 64*AP;
    __half *Vs = Ks + 64*AP;
    __half *Ph = Vs + 64*AP;

    const int tid = threadIdx.x, warp = tid >> 5, lane = tid & 31;
    const int chunk = blockIdx.x, h = blockIdx.y, b = blockIdx.z;
    const int q0 = chunk * 64;
    const int bh = b * HH + h;

    const size_t hoff = (size_t)b * TT * KQV_LD + h * DH;
    const __half *Khg = kqvh + hoff;
    const __half *Qhg = Khg + DD;
    const __half *Vhg = Khg + 2*DD;
    const size_t pbase = ((size_t)bh * NCHUNK + chunk) * (DH*DH);

#pragma unroll
    for (int j = 0; j < 4; j++) {
        const int id = tid + 128 * j;
        const int row = id >> 3, c8 = (id & 7) * 8;
        const size_t gk = (size_t)(q0 + row) * KQV_LD + c8;
        const int d = row * AP + c8;
        cp16(Qs + d, Qhg + gk);
        cp16(Ks + d, Khg + gk);
        cp16(Vs + d, Vhg + gk);
        cp16(Ph + d, ph + pbase + (size_t)row * 64 + c8);
    }
    CP_COMMIT();
    CP_WAIT(0);
    __syncthreads();

    const int wq = warp * 16;
    const int g = lane >> 2, tg = lane & 3;
    const int vrr = (lane & 8) + (lane & 7);
    const int vcc = (lane >> 1) & 8;
    const int krr = (lane >> 1) & 8;
    const int kdd = lane & 8;

    // Q fragments (A-operand, row-major)
    unsigned qf[4][4];
#pragma unroll
    for (int dsi = 0; dsi < 4; dsi++)
        ldsm4(qf[dsi], Qs + (wq + (lane & 15)) * AP + dsi * 16 + ((lane & 16) >> 1));

    float oacc[8][4];
#pragma unroll
    for (int j = 0; j < 8; j++)
#pragma unroll
        for (int l = 0; l < 4; l++) oacc[j][l] = 0.f;

    // ---- O = Q * P_prev (hi-only) ----
#pragma unroll
    for (int dsi = 0; dsi < 4; dsi++) {
        const int ds = dsi * 16;
        unsigned phf[4][4];
#pragma unroll
        for (int np = 0; np < 4; np++)
            ldsm4t(phf[np], Ph + (ds + vrr) * AP + np * 16 + vcc);
#pragma unroll
        for (int nt = 0; nt < 8; nt++)
            mma16816(oacc[nt], qf[dsi][0], qf[dsi][1], qf[dsi][2], qf[dsi][3],
                     phf[nt >> 1][(nt & 1) * 2], phf[nt >> 1][(nt & 1) * 2 + 1]);
    }

    // ---- S = Q K^T (intra-chunk) ----
    float sacc[8][4];
#pragma unroll
    for (int j = 0; j < 8; j++)
#pragma unroll
        for (int l = 0; l < 4; l++) sacc[j][l] = 0.f;

#pragma unroll
    for (int dsi = 0; dsi < 4; dsi++) {
        const int ds = dsi * 16;
        unsigned kf[4][4];
#pragma unroll
        for (int np = 0; np < 4; np++)
            ldsm4(kf[np], Ks + (np * 16 + krr + (lane & 7)) * AP + ds + kdd);
#pragma unroll
        for (int nt = 0; nt < 8; nt++)
            mma16816(sacc[nt], qf[dsi][0], qf[dsi][1], qf[dsi][2], qf[dsi][3],
                     kf[nt >> 1][(nt & 1) * 2], kf[nt >> 1][(nt & 1) * 2 + 1]);
    }

    // mask (local tril) + pack to A-fragments
    const int qr0 = wq + g, qr8 = qr0 + 8;
    unsigned aS[4][4];
#pragma unroll
    for (int nt = 0; nt < 8; nt++) {
        const int kc = nt * 8 + tg * 2;
        float s0 = sacc[nt][0], s1 = sacc[nt][1];
        float s2 = sacc[nt][2], s3 = sacc[nt][3];
        if (kc     > qr0) s0 = 0.f;
        if (kc + 1 > qr0) s1 = 0.f;
        if (kc     > qr8) s2 = 0.f;
        if (kc + 1 > qr8) s3 = 0.f;
        aS[nt >> 1][(nt & 1) * 2 + 0] = hpack2(s0, s1);
        aS[nt >> 1][(nt & 1) * 2 + 1] = hpack2(s2, s3);
    }

    // ---- O += S V (intra) ----
#pragma unroll
    for (int kc4 = 0; kc4 < 4; kc4++) {
        const int ks = kc4 * 16;
        unsigned vf[4][4];
#pragma unroll
        for (int np = 0; np < 4; np++)
            ldsm4t(vf[np], Vs + (ks + vrr) * AP + np * 16 + vcc);
#pragma unroll
        for (int nt = 0; nt < 8; nt++)
            mma16816(oacc[nt], aS[kc4][0], aS[kc4][1], aS[kc4][2], aS[kc4][3],
                     vf[nt >> 1][(nt & 1) * 2], vf[nt >> 1][(nt & 1) * 2 + 1]);
    }

    // write O (fp16)
    const size_t t = (size_t)b * TT + q0 + wq + g;
#pragma unroll
    for (int nt = 0; nt < 8; nt++) {
        const int c = h * DH + nt * 8 + tg * 2;
        *reinterpret_cast<unsigned*>(&aoh[t * DD + c])       = hpack2(oacc[nt][0], oacc[nt][1]);
        *reinterpret_cast<unsigned*>(&aoh[(t + 8) * DD + c]) = hpack2(oacc[nt][2], oacc[nt][3]);
    }
}

// ---------------------------------------------------------------------------
extern "C" void kernel_launch(void* const* d_in, const int* in_sizes, int n_in,
                              void* d_out, int out_size)
{
    const float* x  = (const float*)d_in[0];
    const float* W1 = (const float*)d_in[1];
    const float* b1 = (const float*)d_in[2];
    const float* W2 = (const float*)d_in[3];
    const float* b2 = (const float*)d_in[4];
    float* out = (float*)d_out;

    __half *xh, *w1h, *w2h, *kqvh, *aoh, *ph;
    float* Cc;
    cudaGetSymbolAddress((void**)&xh,  g_xh);
    cudaGetSymbolAddress((void**)&w1h, g_w1h);
    cudaGetSymbolAddress((void**)&w2h, g_w2h);
    cudaGetSymbolAddress((void**)&kqvh, g_kqvh);
    cudaGetSymbolAddress((void**)&aoh, g_aoh);
    cudaGetSymbolAddress((void**)&Cc,  g_C);
    cudaGetSymbolAddress((void**)&ph,  g_ph);

    cudaFuncSetAttribute(gemm_h<1>,
                         cudaFuncAttributeMaxDynamicSharedMemorySize, GEMM_SMEM);
    cudaFuncSetAttribute(gemm_h<0>,
                         cudaFuncAttributeMaxDynamicSharedMemorySize, GEMM_SMEM);
    cudaFuncSetAttribute(attn_chunk,
                         cudaFuncAttributeMaxDynamicSharedMemorySize, ATTC_SMEM);

    // 0) x/W1/W2 -> fp16 (single fused launch)
    {
        const int total = NX4 + NW14 + NW24;
        prep_all<<<(total + 255) / 256, 256>>>(x, W1, W2, xh, w1h, w2h);
    }
    // 1) kqv = x @ W1 + b1  (fp16 output)
    {
        dim3 grid(3 * DD / 128, MROWS / 128);
        gemm_h<1><<<grid, 128, GEMM_SMEM>>>(xh, w1h, b1, nullptr, kqvh,
                                            MROWS, 3 * DD, DD);
    }
    // 2a) per-chunk outer products C_c = K_c^T V_c
    {
        dim3 grid(NCHUNK, HH, BB);
        kv_outer<<<grid, 128>>>(kqvh, Cc);
    }
    // 2b) exclusive prefix over chunks (vectorized, fp16 out)
    {
        dim3 grid(BB * HH, (DH * DH / 4) / 256);
        prefix_split<<<grid, 256>>>(Cc, ph);
    }
    // 2c) O_c = Q_c P_prev + tril(Q_c K_c^T) V_c
    {
        dim3 grid(NCHUNK, HH, BB);
        attn_chunk<<<grid, 128, ATTC_SMEM>>>(kqvh, ph, aoh);
    }
    // 3) out = ao @ W2 + b2  (fp32 output)
    {
        dim3 grid(DD / 128, MROWS / 128);
        gemm_h<0><<<grid, 128, GEMM_SMEM>>>(aoh, w2h, b2, out, nullptr,
                                            MROWS, DD, DD);
    }
}

// round 15
// speedup vs baseline: 10.1557x; 1.0029x over previous
#include <cuda_runtime.h>
#include <cuda_fp16.h>

#define BB 2
#define TT 2048
#define DD 1024
#define HH 16
#define DH 64
#define MROWS (BB*TT)
#define KQV_LD (3*DD)
#define NCHUNK 32          // 2048 / 64

// fp16 operands + scratch (device globals; allocation is forbidden)
__device__ __half g_xh [(size_t)MROWS*DD];
__device__ __half g_w1h[(size_t)DD*3*DD];   // natural [K][N]
__device__ __half g_w2h[(size_t)DD*DD];
__device__ __half g_kqvh[(size_t)MROWS*3*DD];
__device__ __half g_aoh[(size_t)MROWS*DD];
__device__ float  g_C  [(size_t)BB*HH*NCHUNK*DH*DH];   // per-chunk K^T V (fp32)
__device__ __half g_ph [(size_t)BB*HH*NCHUNK*DH*DH];   // exclusive prefix (fp16)

// ---------------------------------------------------------------------------
// helpers
// ---------------------------------------------------------------------------
__device__ __forceinline__ unsigned h2_pack(__half a, __half b) {
    __half2 t = __halves2half2(a, b);
    return *reinterpret_cast<unsigned*>(&t);
}
__device__ __forceinline__ unsigned hpack2(float x, float y) {
    return h2_pack(__float2half_rn(x), __float2half_rn(y));
}
__device__ __forceinline__ void mma16816(float* c,
    unsigned a0, unsigned a1, unsigned a2, unsigned a3,
    unsigned b0, unsigned b1)
{
    asm volatile(
        "mma.sync.aligned.m16n8k16.row.col.f32.f16.f16.f32 "
        "{%0,%1,%2,%3},{%4,%5,%6,%7},{%8,%9},{%0,%1,%2,%3};\n"
        : "+f"(c[0]), "+f"(c[1]), "+f"(c[2]), "+f"(c[3])
        : "r"(a0), "r"(a1), "r"(a2), "r"(a3), "r"(b0), "r"(b1));
}
__device__ __forceinline__ void ldsm4(unsigned* r, const void* p) {
    unsigned a = (unsigned)__cvta_generic_to_shared(p);
    asm volatile("ldmatrix.sync.aligned.m8n8.x4.shared.b16 {%0,%1,%2,%3}, [%4];\n"
        : "=r"(r[0]), "=r"(r[1]), "=r"(r[2]), "=r"(r[3]) : "r"(a));
}
__device__ __forceinline__ void ldsm4t(unsigned* r, const void* p) {
    unsigned a = (unsigned)__cvta_generic_to_shared(p);
    asm volatile("ldmatrix.sync.aligned.m8n8.x4.trans.shared.b16 {%0,%1,%2,%3}, [%4];\n"
        : "=r"(r[0]), "=r"(r[1]), "=r"(r[2]), "=r"(r[3]) : "r"(a));
}
__device__ __forceinline__ void cp16(void* sp, const void* gp) {
    unsigned s = (unsigned)__cvta_generic_to_shared(sp);
    asm volatile("cp.async.cg.shared.global [%0], [%1], 16;\n" :: "r"(s), "l"(gp));
}
#define CP_COMMIT() asm volatile("cp.async.commit_group;\n")
#define CP_WAIT(n)  asm volatile("cp.async.wait_group %0;\n" :: "n"(n))

// ---------------------------------------------------------------------------
// prep: one kernel converts x, W1, W2 -> fp16
// ---------------------------------------------------------------------------
#define NX4  (MROWS*DD/4)
#define NW14 (DD*3*DD/4)
#define NW24 (DD*DD/4)
__global__ void prep_all(const float* __restrict__ x,
                         const float* __restrict__ W1,
                         const float* __restrict__ W2,
                         __half* __restrict__ xh,
                         __half* __restrict__ w1h,
                         __half* __restrict__ w2h)
{
    int i = blockIdx.x * blockDim.x + threadIdx.x;
    const float* src; __half* dst; int off;
    if (i < NX4)                   { src = x;  dst = xh;  off = i; }
    else if (i < NX4 + NW14)       { src = W1; dst = w1h; off = i - NX4; }
    else if (i < NX4 + NW14 + NW24){ src = W2; dst = w2h; off = i - NX4 - NW14; }
    else return;
    float4 v = reinterpret_cast<const float4*>(src)[off];
    reinterpret_cast<uint2*>(dst)[off] = make_uint2(hpack2(v.x, v.y), hpack2(v.z, v.w));
}

// ---------------------------------------------------------------------------
// fp16 single-product GEMM (unchanged, proven R11/R12)
// ---------------------------------------------------------------------------
#define APG 72
#define BPG 136
#define SA_ST (128*APG)
#define SB_ST (64*BPG)
#define NSG 3
#define GEMM_SMEM ((NSG*SA_ST + NSG*SB_ST) * 2)

#define GEMM_LOAD(s, k0)                                                        \
    {                                                                           \
        _Pragma("unroll")                                                       \
        for (int j = 0; j < 8; j++) {                                           \
            const int id = tid + 128 * j;                                       \
            const int arow = id >> 3, ac = (id & 7) * 8;                        \
            const size_t ga = (size_t)(m0 + arow) * K + (k0) + ac;              \
            cp16(sA + (s)*SA_ST + arow*APG + ac, Ah_g + ga);                    \
            const int brow = id >> 4, bc = (id & 15) * 8;                       \
            const size_t gb = (size_t)((k0) + brow) * N + n0 + bc;              \
            cp16(sB + (s)*SB_ST + brow*BPG + bc, Bh_g + gb);                    \
        }                                                                       \
        CP_COMMIT();                                                            \
    }

template<int OMODE>
__global__ __launch_bounds__(128, 2) void gemm_h(
    const __half* __restrict__ Ah_g,
    const __half* __restrict__ Bh_g,
    const float* __restrict__ bias,
    float* __restrict__ C, __half* __restrict__ Ch,
    int M, int N, int K)
{
    extern __shared__ __half smg[];
    __half* sA = smg;
    __half* sB = smg + NSG*SA_ST;

    const int tid = threadIdx.x, warp = tid >> 5, lane = tid & 31;
    const int m0 = blockIdx.y * 128, n0 = blockIdx.x * 128;
    const int wm = (warp & 1) * 64, wn = (warp >> 1) * 64;

    float acc[4][8][4];
#pragma unroll
    for (int i = 0; i < 4; i++)
#pragma unroll
        for (int j = 0; j < 8; j++)
#pragma unroll
            for (int l = 0; l < 4; l++) acc[i][j][l] = 0.f;

    GEMM_LOAD(0, 0);
    GEMM_LOAD(1, 64);

    const int brr = (lane & 8) + (lane & 7);
    const int bcsel = (lane >> 1) & 8;
    const int arr = (lane & 15), akk = ((lane & 16) >> 1);

    const int ntiles = K / 64;
    for (int t = 0; t < ntiles; t++) {
        if (t + 1 < ntiles) { CP_WAIT(1); } else { CP_WAIT(0); }
        __syncthreads();
        if (t + 2 < ntiles) GEMM_LOAD((t + 2) % NSG, (t + 2) * 64);

        const int s = t % NSG;
        const __half* Ahs = sA + s*SA_ST;
        const __half* Bhs = sB + s*SB_ST;

        unsigned bb[2][4][4], aa[2][4];
#pragma unroll
        for (int np = 0; np < 4; np++)
            ldsm4t(bb[0][np], Bhs + brr * BPG + wn + np * 16 + bcsel);

#pragma unroll
        for (int ki = 0; ki < 4; ki++) {
            const int ks = ki * 16;
            if (ki < 3) {
#pragma unroll
                for (int np = 0; np < 4; np++)
                    ldsm4t(bb[(ki + 1) & 1][np], Bhs + (ks + 16 + brr) * BPG + wn + np * 16 + bcsel);
            }
            ldsm4(aa[0], Ahs + (wm + arr) * APG + ks + akk);
#pragma unroll
            for (int mt = 0; mt < 4; mt++) {
                if (mt < 3)
                    ldsm4(aa[(mt + 1) & 1], Ahs + (wm + (mt + 1) * 16 + arr) * APG + ks + akk);
                const unsigned* a = aa[mt & 1];
#pragma unroll
                for (int nt = 0; nt < 8; nt++) {
                    mma16816(acc[mt][nt], a[0], a[1], a[2], a[3],
                             bb[ki & 1][nt >> 1][(nt & 1) * 2],
                             bb[ki & 1][nt >> 1][(nt & 1) * 2 + 1]);
                }
            }
        }
    }

    const int g = lane >> 2, tg = lane & 3;
#pragma unroll
    for (int mt = 0; mt < 4; mt++) {
        const int r = m0 + wm + mt * 16 + g;
#pragma unroll
        for (int nt = 0; nt < 8; nt++) {
            const int c = n0 + wn + nt * 8 + tg * 2;
            const float bx = bias[c], by = bias[c + 1];
            const float v0 = acc[mt][nt][0] + bx, v1 = acc[mt][nt][1] + by;
            const float v2 = acc[mt][nt][2] + bx, v3 = acc[mt][nt][3] + by;
            if (OMODE == 1) {
                *reinterpret_cast<unsigned*>(&Ch[(size_t)r * N + c])       = hpack2(v0, v1);
                *reinterpret_cast<unsigned*>(&Ch[(size_t)(r + 8) * N + c]) = hpack2(v2, v3);
            } else {
                float2 o0 = {v0, v1}, o1 = {v2, v3};
                *reinterpret_cast<float2*>(&C[(size_t)r * N + c])       = o0;
                *reinterpret_cast<float2*>(&C[(size_t)(r + 8) * N + c]) = o1;
            }
        }
    }
}

// ---------------------------------------------------------------------------
// Kernel A: per-(b,h,chunk) outer-product sum  C_c = K_c^T V_c  (64x64 fp32)
// ---------------------------------------------------------------------------
#define AP 72
__global__ __launch_bounds__(128, 2) void kv_outer(
    const __half* __restrict__ kqvh, float* __restrict__ Cc)
{
    __shared__ __half Ks[64*AP], Vs[64*AP];

    const int tid = threadIdx.x, warp = tid >> 5, lane = tid & 31;
    const int chunk = blockIdx.x, h = blockIdx.y, b = blockIdx.z;
    const int k0 = chunk * 64;

    const size_t hoff = (size_t)b * TT * KQV_LD + h * DH;
    const __half *Khg = kqvh + hoff;
    const __half *Vhg = Khg + 2*DD;

#pragma unroll
    for (int j = 0; j < 4; j++) {
        const int id = tid + 128 * j;
        const int row = id >> 3, c8 = (id & 7) * 8;
        const size_t gk = (size_t)(k0 + row) * KQV_LD + c8;
        cp16(Ks + row * AP + c8, Khg + gk);
        cp16(Vs + row * AP + c8, Vhg + gk);
    }
    CP_COMMIT();
    CP_WAIT(0);
    __syncthreads();

    const int m = warp * 16;
    const int vrr = (lane & 8) + (lane & 7);
    const int vcc = (lane >> 1) & 8;
    const int arow = ((lane & 16) >> 1) + (lane & 7);
    const int acol = lane & 8;

    float cacc[8][4];
#pragma unroll
    for (int j = 0; j < 8; j++)
#pragma unroll
        for (int l = 0; l < 4; l++) cacc[j][l] = 0.f;

#pragma unroll
    for (int ks = 0; ks < 64; ks += 16) {
        unsigned af[4];
        ldsm4t(af, Ks + (ks + arow) * AP + m + acol);
        unsigned vf[4][4];
#pragma unroll
        for (int np = 0; np < 4; np++)
            ldsm4t(vf[np], Vs + (ks + vrr) * AP + np * 16 + vcc);
#pragma unroll
        for (int nt = 0; nt < 8; nt++)
            mma16816(cacc[nt], af[0], af[1], af[2], af[3],
                     vf[nt >> 1][(nt & 1) * 2], vf[nt >> 1][(nt & 1) * 2 + 1]);
    }

    const int g = lane >> 2, tg = lane & 3;
    const size_t cbase = ((size_t)(b * HH + h) * NCHUNK + chunk) * (DH * DH);
#pragma unroll
    for (int nt = 0; nt < 8; nt++) {
        const int col = nt * 8 + tg * 2;
        const int r0 = m + g;
        float2 o0 = {cacc[nt][0], cacc[nt][1]};
        float2 o1 = {cacc[nt][2], cacc[nt][3]};
        *reinterpret_cast<float2*>(&Cc[cbase + (size_t)r0 * 64 + col])       = o0;
        *reinterpret_cast<float2*>(&Cc[cbase + (size_t)(r0 + 8) * 64 + col]) = o1;
    }
}

// ---------------------------------------------------------------------------
// Kernel B: exclusive prefix over chunks -> fp16.
// float4/thread, 4-deep register prefetch ring (MLP=4).
// grid (32 bh, 4), 256 thr.
// ---------------------------------------------------------------------------
#define E4C (DH*DH/4)    // 1024 float4 per chunk matrix
__global__ void prefix_split(const float* __restrict__ Cc,
                             __half* __restrict__ ph)
{
    const int bh = blockIdx.x;
    const int e4 = blockIdx.y * 256 + threadIdx.x;       // 0..1023
    const size_t base4 = (size_t)bh * NCHUNK * E4C + e4;
    const float4* src = reinterpret_cast<const float4*>(Cc);
    uint2* dst = reinterpret_cast<uint2*>(ph);

    float4 buf[4];
#pragma unroll
    for (int p = 0; p < 4; p++)
        buf[p] = src[base4 + (size_t)p * E4C];

    float4 run = {0.f, 0.f, 0.f, 0.f};
#pragma unroll
    for (int c = 0; c < NCHUNK; c++) {
        const size_t idx = base4 + (size_t)c * E4C;
        dst[idx] = make_uint2(hpack2(run.x, run.y), hpack2(run.z, run.w));
        const float4 v = buf[c & 3];
        if (c + 4 < NCHUNK)
            buf[c & 3] = src[idx + 4 * E4C];
        run.x += v.x; run.y += v.y; run.z += v.z; run.w += v.w;
    }
}

// ---------------------------------------------------------------------------
// Kernel C: per-(b,h,chunk)  O_c = Q_c P_prev + tril(Q_c K_c^T) V_c
// 4 warps, warp w owns q rows [16w, 16w+16) x all 64 d. P hi-only.
// ---------------------------------------------------------------------------
#define ATTC_SMEM (4 * 64 * AP * 2)   // Qs,Ks,Vs,Ph = 36864 B

__global__ __launch_bounds__(128, 2) void attn_chunk(
    const __half* __restrict__ kqvh,
    const __half* __restrict__ ph,
    __half* __restrict__ aoh)
{
    extern __shared__ __half smc[];
    __half *Qs = smc;
    __half *Ks = Qs + 64*AP;
    __half *Vs = Ks + 64*AP;
    __half *Ph = Vs + 64*AP;

    const int tid = threadIdx.x, warp = tid >> 5, lane = tid & 31;
    const int chunk = blockIdx.x, h = blockIdx.y, b = blockIdx.z;
    const int q0 = chunk * 64;
    const int bh = b * HH + h;

    const size_t hoff = (size_t)b * TT * KQV_LD + h * DH;
    const __half *Khg = kqvh + hoff;
    const __half *Qhg = Khg + DD;
    const __half *Vhg = Khg + 2*DD;
    const size_t pbase = ((size_t)bh * NCHUNK + chunk) * (DH*DH);

#pragma unroll
    for (int j = 0; j < 4; j++) {
        const int id = tid + 128 * j;
        const int row = id >> 3, c8 = (id & 7) * 8;
        const size_t gk = (size_t)(q0 + row) * KQV_LD + c8;
        const int d = row * AP + c8;
        cp16(Qs + d, Qhg + gk);
        cp16(Ks + d, Khg + gk);
        cp16(Vs + d, Vhg + gk);
        cp16(Ph + d, ph + pbase + (size_t)row * 64 + c8);
    }
    CP_COMMIT();
    CP_WAIT(0);
    __syncthreads();

    const int wq = warp * 16;
    const int g = lane >> 2, tg = lane & 3;
    const int vrr = (lane & 8) + (lane & 7);
    const int vcc = (lane >> 1) & 8;
    const int krr = (lane >> 1) & 8;
    const int kdd = lane & 8;

    // Q fragments (A-operand, row-major)
    unsigned qf[4][4];
#pragma unroll
    for (int dsi = 0; dsi < 4; dsi++)
        ldsm4(qf[dsi], Qs + (wq + (lane & 15)) * AP + dsi * 16 + ((lane & 16) >> 1));

    float oacc[8][4];
#pragma unroll
    for (int j = 0; j < 8; j++)
#pragma unroll
        for (int l = 0; l < 4; l++) oacc[j][l] = 0.f;

    // ---- O = Q * P_prev (hi-only) ----
#pragma unroll
    for (int dsi = 0; dsi < 4; dsi++) {
        const int ds = dsi * 16;
        unsigned phf[4][4];
#pragma unroll
        for (int np = 0; np < 4; np++)
            ldsm4t(phf[np], Ph + (ds + vrr) * AP + np * 16 + vcc);
#pragma unroll
        for (int nt = 0; nt < 8; nt++)
            mma16816(oacc[nt], qf[dsi][0], qf[dsi][1], qf[dsi][2], qf[dsi][3],
                     phf[nt >> 1][(nt & 1) * 2], phf[nt >> 1][(nt & 1) * 2 + 1]);
    }

    // ---- S = Q K^T (intra-chunk) ----
    float sacc[8][4];
#pragma unroll
    for (int j = 0; j < 8; j++)
#pragma unroll
        for (int l = 0; l < 4; l++) sacc[j][l] = 0.f;

#pragma unroll
    for (int dsi = 0; dsi < 4; dsi++) {
        const int ds = dsi * 16;
        unsigned kf[4][4];
#pragma unroll
        for (int np = 0; np < 4; np++)
            ldsm4(kf[np], Ks + (np * 16 + krr + (lane & 7)) * AP + ds + kdd);
#pragma unroll
        for (int nt = 0; nt < 8; nt++)
            mma16816(sacc[nt], qf[dsi][0], qf[dsi][1], qf[dsi][2], qf[dsi][3],
                     kf[nt >> 1][(nt & 1) * 2], kf[nt >> 1][(nt & 1) * 2 + 1]);
    }

    // mask (local tril) + pack to A-fragments
    const int qr0 = wq + g, qr8 = qr0 + 8;
    unsigned aS[4][4];
#pragma unroll
    for (int nt = 0; nt < 8; nt++) {
        const int kc = nt * 8 + tg * 2;
        float s0 = sacc[nt][0], s1 = sacc[nt][1];
        float s2 = sacc[nt][2], s3 = sacc[nt][3];
        if (kc     > qr0) s0 = 0.f;
        if (kc + 1 > qr0) s1 = 0.f;
        if (kc     > qr8) s2 = 0.f;
        if (kc + 1 > qr8) s3 = 0.f;
        aS[nt >> 1][(nt & 1) * 2 + 0] = hpack2(s0, s1);
        aS[nt >> 1][(nt & 1) * 2 + 1] = hpack2(s2, s3);
    }

    // ---- O += S V (intra) ----
#pragma unroll
    for (int kc4 = 0; kc4 < 4; kc4++) {
        const int ks = kc4 * 16;
        unsigned vf[4][4];
#pragma unroll
        for (int np = 0; np < 4; np++)
            ldsm4t(vf[np], Vs + (ks + vrr) * AP + np * 16 + vcc);
#pragma unroll
        for (int nt = 0; nt < 8; nt++)
            mma16816(oacc[nt], aS[kc4][0], aS[kc4][1], aS[kc4][2], aS[kc4][3],
                     vf[nt >> 1][(nt & 1) * 2], vf[nt >> 1][(nt & 1) * 2 + 1]);
    }

    // write O (fp16)
    const size_t t = (size_t)b * TT + q0 + wq + g;
#pragma unroll
    for (int nt = 0; nt < 8; nt++) {
        const int c = h * DH + nt * 8 + tg * 2;
        *reinterpret_cast<unsigned*>(&aoh[t * DD + c])       = hpack2(oacc[nt][0], oacc[nt][1]);
        *reinterpret_cast<unsigned*>(&aoh[(t + 8) * DD + c]) = hpack2(oacc[nt][2], oacc[nt][3]);
    }
}

// ---------------------------------------------------------------------------
extern "C" void kernel_launch(void* const* d_in, const int* in_sizes, int n_in,
                              void* d_out, int out_size)
{
    const float* x  = (const float*)d_in[0];
    const float* W1 = (const float*)d_in[1];
    const float* b1 = (const float*)d_in[2];
    const float* W2 = (const float*)d_in[3];
    const float* b2 = (const float*)d_in[4];
    float* out = (float*)d_out;

    __half *xh, *w1h, *w2h, *kqvh, *aoh, *ph;
    float* Cc;
    cudaGetSymbolAddress((void**)&xh,  g_xh);
    cudaGetSymbolAddress((void**)&w1h, g_w1h);
    cudaGetSymbolAddress((void**)&w2h, g_w2h);
    cudaGetSymbolAddress((void**)&kqvh, g_kqvh);
    cudaGetSymbolAddress((void**)&aoh, g_aoh);
    cudaGetSymbolAddress((void**)&Cc,  g_C);
    cudaGetSymbolAddress((void**)&ph,  g_ph);

    cudaFuncSetAttribute(gemm_h<1>,
                         cudaFuncAttributeMaxDynamicSharedMemorySize, GEMM_SMEM);
    cudaFuncSetAttribute(gemm_h<0>,
                         cudaFuncAttributeMaxDynamicSharedMemorySize, GEMM_SMEM);
    cudaFuncSetAttribute(attn_chunk,
                         cudaFuncAttributeMaxDynamicSharedMemorySize, ATTC_SMEM);

    // 0) x/W1/W2 -> fp16 (single fused launch)
    {
        const int total = NX4 + NW14 + NW24;
        prep_all<<<(total + 255) / 256, 256>>>(x, W1, W2, xh, w1h, w2h);
    }
    // 1) kqv = x @ W1 + b1  (fp16 output)
    {
        dim3 grid(3 * DD / 128, MROWS / 128);
        gemm_h<1><<<grid, 128, GEMM_SMEM>>>(xh, w1h, b1, nullptr, kqvh,
                                            MROWS, 3 * DD, DD);
    }
    // 2a) per-chunk outer products C_c = K_c^T V_c
    {
        dim3 grid(NCHUNK, HH, BB);
        kv_outer<<<grid, 128>>>(kqvh, Cc);
    }
    // 2b) exclusive prefix over chunks (MLP=4 pipelined, fp16 out)
    {
        dim3 grid(BB * HH, (DH * DH / 4) / 256);
        prefix_split<<<grid, 256>>>(Cc, ph);
    }
    // 2c) O_c = Q_c P_prev + tril(Q_c K_c^T) V_c
    {
        dim3 grid(NCHUNK, HH, BB);
        attn_chunk<<<grid, 128, ATTC_SMEM>>>(kqvh, ph, aoh);
    }
    // 3) out = ao @ W2 + b2  (fp32 output)
    {
        dim3 grid(DD / 128, MROWS / 128);
        gemm_h<0><<<grid, 128, GEMM_SMEM>>>(aoh, w2h, b2, out, nullptr,
                                            MROWS, DD, DD);
    }
}

// round 16
// speedup vs baseline: 10.1580x; 1.0002x over previous
#include <cuda_runtime.h>
#include <cuda_fp16.h>

#define BB 2
#define TT 2048
#define DD 1024
#define HH 16
#define DH 64
#define MROWS (BB*TT)
#define KQV_LD (3*DD)
#define NCHUNK 32          // 2048 / 64

// fp16 operands + scratch (device globals; allocation is forbidden)
__device__ __half g_xh [(size_t)MROWS*DD];
__device__ __half g_w1h[(size_t)DD*3*DD];   // natural [K][N]
__device__ __half g_w2h[(size_t)DD*DD];
__device__ __half g_kqvh[(size_t)MROWS*3*DD];
__device__ __half g_aoh[(size_t)MROWS*DD];
__device__ float  g_C  [(size_t)BB*HH*NCHUNK*DH*DH];   // per-chunk K^T V (fp32)
__device__ __half g_ph [(size_t)BB*HH*NCHUNK*DH*DH];   // exclusive prefix (fp16)

// ---------------------------------------------------------------------------
// helpers
// ---------------------------------------------------------------------------
__device__ __forceinline__ unsigned h2_pack(__half a, __half b) {
    __half2 t = __halves2half2(a, b);
    return *reinterpret_cast<unsigned*>(&t);
}
__device__ __forceinline__ unsigned hpack2(float x, float y) {
    return h2_pack(__float2half_rn(x), __float2half_rn(y));
}
__device__ __forceinline__ void mma16816(float* c,
    unsigned a0, unsigned a1, unsigned a2, unsigned a3,
    unsigned b0, unsigned b1)
{
    asm volatile(
        "mma.sync.aligned.m16n8k16.row.col.f32.f16.f16.f32 "
        "{%0,%1,%2,%3},{%4,%5,%6,%7},{%8,%9},{%0,%1,%2,%3};\n"
        : "+f"(c[0]), "+f"(c[1]), "+f"(c[2]), "+f"(c[3])
        : "r"(a0), "r"(a1), "r"(a2), "r"(a3), "r"(b0), "r"(b1));
}
__device__ __forceinline__ void ldsm4(unsigned* r, const void* p) {
    unsigned a = (unsigned)__cvta_generic_to_shared(p);
    asm volatile("ldmatrix.sync.aligned.m8n8.x4.shared.b16 {%0,%1,%2,%3}, [%4];\n"
        : "=r"(r[0]), "=r"(r[1]), "=r"(r[2]), "=r"(r[3]) : "r"(a));
}
__device__ __forceinline__ void ldsm4t(unsigned* r, const void* p) {
    unsigned a = (unsigned)__cvta_generic_to_shared(p);
    asm volatile("ldmatrix.sync.aligned.m8n8.x4.trans.shared.b16 {%0,%1,%2,%3}, [%4];\n"
        : "=r"(r[0]), "=r"(r[1]), "=r"(r[2]), "=r"(r[3]) : "r"(a));
}
__device__ __forceinline__ void cp16(void* sp, const void* gp) {
    unsigned s = (unsigned)__cvta_generic_to_shared(sp);
    asm volatile("cp.async.cg.shared.global [%0], [%1], 16;\n" :: "r"(s), "l"(gp));
}
#define CP_COMMIT() asm volatile("cp.async.commit_group;\n")
#define CP_WAIT(n)  asm volatile("cp.async.wait_group %0;\n" :: "n"(n))

// ---------------------------------------------------------------------------
// prep: one kernel converts x, W1, W2 -> fp16
// ---------------------------------------------------------------------------
#define NX4  (MROWS*DD/4)
#define NW14 (DD*3*DD/4)
#define NW24 (DD*DD/4)
__global__ void prep_all(const float* __restrict__ x,
                         const float* __restrict__ W1,
                         const float* __restrict__ W2,
                         __half* __restrict__ xh,
                         __half* __restrict__ w1h,
                         __half* __restrict__ w2h)
{
    int i = blockIdx.x * blockDim.x + threadIdx.x;
    const float* src; __half* dst; int off;
    if (i < NX4)                   { src = x;  dst = xh;  off = i; }
    else if (i < NX4 + NW14)       { src = W1; dst = w1h; off = i - NX4; }
    else if (i < NX4 + NW14 + NW24){ src = W2; dst = w2h; off = i - NX4 - NW14; }
    else return;
    float4 v = reinterpret_cast<const float4*>(src)[off];
    reinterpret_cast<uint2*>(dst)[off] = make_uint2(hpack2(v.x, v.y), hpack2(v.z, v.w));
}

// ---------------------------------------------------------------------------
// fp16 single-product GEMM (unchanged, proven R11/R12)
// ---------------------------------------------------------------------------
#define APG 72
#define BPG 136
#define SA_ST (128*APG)
#define SB_ST (64*BPG)
#define NSG 3
#define GEMM_SMEM ((NSG*SA_ST + NSG*SB_ST) * 2)

#define GEMM_LOAD(s, k0)                                                        \
    {                                                                           \
        _Pragma("unroll")                                                       \
        for (int j = 0; j < 8; j++) {                                           \
            const int id = tid + 128 * j;                                       \
            const int arow = id >> 3, ac = (id & 7) * 8;                        \
            const size_t ga = (size_t)(m0 + arow) * K + (k0) + ac;              \
            cp16(sA + (s)*SA_ST + arow*APG + ac, Ah_g + ga);                    \
            const int brow = id >> 4, bc = (id & 15) * 8;                       \
            const size_t gb = (size_t)((k0) + brow) * N + n0 + bc;              \
            cp16(sB + (s)*SB_ST + brow*BPG + bc, Bh_g + gb);                    \
        }                                                                       \
        CP_COMMIT();                                                            \
    }

template<int OMODE>
__global__ __launch_bounds__(128, 2) void gemm_h(
    const __half* __restrict__ Ah_g,
    const __half* __restrict__ Bh_g,
    const float* __restrict__ bias,
    float* __restrict__ C, __half* __restrict__ Ch,
    int M, int N, int K)
{
    extern __shared__ __half smg[];
    __half* sA = smg;
    __half* sB = smg + NSG*SA_ST;

    const int tid = threadIdx.x, warp = tid >> 5, lane = tid & 31;
    const int m0 = blockIdx.y * 128, n0 = blockIdx.x * 128;
    const int wm = (warp & 1) * 64, wn = (warp >> 1) * 64;

    float acc[4][8][4];
#pragma unroll
    for (int i = 0; i < 4; i++)
#pragma unroll
        for (int j = 0; j < 8; j++)
#pragma unroll
            for (int l = 0; l < 4; l++) acc[i][j][l] = 0.f;

    GEMM_LOAD(0, 0);
    GEMM_LOAD(1, 64);

    const int brr = (lane & 8) + (lane & 7);
    const int bcsel = (lane >> 1) & 8;
    const int arr = (lane & 15), akk = ((lane & 16) >> 1);

    const int ntiles = K / 64;
    for (int t = 0; t < ntiles; t++) {
        if (t + 1 < ntiles) { CP_WAIT(1); } else { CP_WAIT(0); }
        __syncthreads();
        if (t + 2 < ntiles) GEMM_LOAD((t + 2) % NSG, (t + 2) * 64);

        const int s = t % NSG;
        const __half* Ahs = sA + s*SA_ST;
        const __half* Bhs = sB + s*SB_ST;

        unsigned bb[2][4][4], aa[2][4];
#pragma unroll
        for (int np = 0; np < 4; np++)
            ldsm4t(bb[0][np], Bhs + brr * BPG + wn + np * 16 + bcsel);

#pragma unroll
        for (int ki = 0; ki < 4; ki++) {
            const int ks = ki * 16;
            if (ki < 3) {
#pragma unroll
                for (int np = 0; np < 4; np++)
                    ldsm4t(bb[(ki + 1) & 1][np], Bhs + (ks + 16 + brr) * BPG + wn + np * 16 + bcsel);
            }
            ldsm4(aa[0], Ahs + (wm + arr) * APG + ks + akk);
#pragma unroll
            for (int mt = 0; mt < 4; mt++) {
                if (mt < 3)
                    ldsm4(aa[(mt + 1) & 1], Ahs + (wm + (mt + 1) * 16 + arr) * APG + ks + akk);
                const unsigned* a = aa[mt & 1];
#pragma unroll
                for (int nt = 0; nt < 8; nt++) {
                    mma16816(acc[mt][nt], a[0], a[1], a[2], a[3],
                             bb[ki & 1][nt >> 1][(nt & 1) * 2],
                             bb[ki & 1][nt >> 1][(nt & 1) * 2 + 1]);
                }
            }
        }
    }

    const int g = lane >> 2, tg = lane & 3;
#pragma unroll
    for (int mt = 0; mt < 4; mt++) {
        const int r = m0 + wm + mt * 16 + g;
#pragma unroll
        for (int nt = 0; nt < 8; nt++) {
            const int c = n0 + wn + nt * 8 + tg * 2;
            const float bx = bias[c], by = bias[c + 1];
            const float v0 = acc[mt][nt][0] + bx, v1 = acc[mt][nt][1] + by;
            const float v2 = acc[mt][nt][2] + bx, v3 = acc[mt][nt][3] + by;
            if (OMODE == 1) {
                *reinterpret_cast<unsigned*>(&Ch[(size_t)r * N + c])       = hpack2(v0, v1);
                *reinterpret_cast<unsigned*>(&Ch[(size_t)(r + 8) * N + c]) = hpack2(v2, v3);
            } else {
                float2 o0 = {v0, v1}, o1 = {v2, v3};
                *reinterpret_cast<float2*>(&C[(size_t)r * N + c])       = o0;
                *reinterpret_cast<float2*>(&C[(size_t)(r + 8) * N + c]) = o1;
            }
        }
    }
}

// ---------------------------------------------------------------------------
// Kernel A: per-(b,h,chunk) outer-product sum  C_c = K_c^T V_c  (64x64 fp32)
// ---------------------------------------------------------------------------
#define AP 72
__global__ __launch_bounds__(128, 2) void kv_outer(
    const __half* __restrict__ kqvh, float* __restrict__ Cc)
{
    __shared__ __half Ks[64*AP], Vs[64*AP];

    const int tid = threadIdx.x, warp = tid >> 5, lane = tid & 31;
    const int chunk = blockIdx.x, h = blockIdx.y, b = blockIdx.z;
    const int k0 = chunk * 64;

    const size_t hoff = (size_t)b * TT * KQV_LD + h * DH;
    const __half *Khg = kqvh + hoff;
    const __half *Vhg = Khg + 2*DD;

#pragma unroll
    for (int j = 0; j < 4; j++) {
        const int id = tid + 128 * j;
        const int row = id >> 3, c8 = (id & 7) * 8;
        const size_t gk = (size_t)(k0 + row) * KQV_LD + c8;
        cp16(Ks + row * AP + c8, Khg + gk);
        cp16(Vs + row * AP + c8, Vhg + gk);
    }
    CP_COMMIT();
    CP_WAIT(0);
    __syncthreads();

    const int m = warp * 16;
    const int vrr = (lane & 8) + (lane & 7);
    const int vcc = (lane >> 1) & 8;
    const int arow = ((lane & 16) >> 1) + (lane & 7);
    const int acol = lane & 8;

    float cacc[8][4];
#pragma unroll
    for (int j = 0; j < 8; j++)
#pragma unroll
        for (int l = 0; l < 4; l++) cacc[j][l] = 0.f;

#pragma unroll
    for (int ks = 0; ks < 64; ks += 16) {
        unsigned af[4];
        ldsm4t(af, Ks + (ks + arow) * AP + m + acol);
        unsigned vf[4][4];
#pragma unroll
        for (int np = 0; np < 4; np++)
            ldsm4t(vf[np], Vs + (ks + vrr) * AP + np * 16 + vcc);
#pragma unroll
        for (int nt = 0; nt < 8; nt++)
            mma16816(cacc[nt], af[0], af[1], af[2], af[3],
                     vf[nt >> 1][(nt & 1) * 2], vf[nt >> 1][(nt & 1) * 2 + 1]);
    }

    const int g = lane >> 2, tg = lane & 3;
    const size_t cbase = ((size_t)(b * HH + h) * NCHUNK + chunk) * (DH * DH);
#pragma unroll
    for (int nt = 0; nt < 8; nt++) {
        const int col = nt * 8 + tg * 2;
        const int r0 = m + g;
        float2 o0 = {cacc[nt][0], cacc[nt][1]};
        float2 o1 = {cacc[nt][2], cacc[nt][3]};
        *reinterpret_cast<float2*>(&Cc[cbase + (size_t)r0 * 64 + col])       = o0;
        *reinterpret_cast<float2*>(&Cc[cbase + (size_t)(r0 + 8) * 64 + col]) = o1;
    }
}

// ---------------------------------------------------------------------------
// Kernel B: exclusive prefix over chunks -> fp16.
// SCALAR float per thread: 512 blocks x 256 thr = 131K threads (fills chip).
// MLP-2 prefetch inside each thread's 32-long chain.
// ---------------------------------------------------------------------------
#define EC (DH*DH)    // 4096 elements per chunk matrix
__global__ void prefix_split(const float* __restrict__ Cc,
                             __half* __restrict__ ph)
{
    const int bh = blockIdx.x;                            // 0..31
    const int e  = blockIdx.y * 256 + threadIdx.x;        // 0..4095
    const size_t base = (size_t)bh * NCHUNK * EC + e;

    float buf0 = Cc[base];
    float buf1 = Cc[base + EC];
    float run = 0.f;
#pragma unroll
    for (int c = 0; c < NCHUNK; c++) {
        const size_t idx = base + (size_t)c * EC;
        ph[idx] = __float2half_rn(run);
        const float v = (c & 1) ? buf1 : buf0;
        if (c + 2 < NCHUNK) {
            if (c & 1) buf1 = Cc[idx + 2 * EC];
            else       buf0 = Cc[idx + 2 * EC];
        }
        run += v;
    }
}

// ---------------------------------------------------------------------------
// Kernel C: per-(b,h,chunk)  O_c = Q_c P_prev + tril(Q_c K_c^T) V_c
// 4 warps, warp w owns q rows [16w, 16w+16) x all 64 d. P hi-only.
// ---------------------------------------------------------------------------
#define ATTC_SMEM (4 * 64 * AP * 2)   // Qs,Ks,Vs,Ph = 36864 B

__global__ __launch_bounds__(128, 2) void attn_chunk(
    const __half* __restrict__ kqvh,
    const __half* __restrict__ ph,
    __half* __restrict__ aoh)
{
    extern __shared__ __half smc[];
    __half *Qs = smc;
    __half *Ks = Qs + 64*AP;
    __half *Vs = Ks + 64*AP;
    __half *Ph = Vs + 64*AP;

    const int tid = threadIdx.x, warp = tid >> 5, lane = tid & 31;
    const int chunk = blockIdx.x, h = blockIdx.y, b = blockIdx.z;
    const int q0 = chunk * 64;
    const int bh = b * HH + h;

    const size_t hoff = (size_t)b * TT * KQV_LD + h * DH;
    const __half *Khg = kqvh + hoff;
    const __half *Qhg = Khg + DD;
    const __half *Vhg = Khg + 2*DD;
    const size_t pbase = ((size_t)bh * NCHUNK + chunk) * (DH*DH);

#pragma unroll
    for (int j = 0; j < 4; j++) {
        const int id = tid + 128 * j;
        const int row = id >> 3, c8 = (id & 7) * 8;
        const size_t gk = (size_t)(q0 + row) * KQV_LD + c8;
        const int d = row * AP + c8;
        cp16(Qs + d, Qhg + gk);
        cp16(Ks + d, Khg + gk);
        cp16(Vs + d, Vhg + gk);
        cp16(Ph + d, ph + pbase + (size_t)row * 64 + c8);
    }
    CP_COMMIT();
    CP_WAIT(0);
    __syncthreads();

    const int wq = warp * 16;
    const int g = lane >> 2, tg = lane & 3;
    const int vrr = (lane & 8) + (lane & 7);
    const int vcc = (lane >> 1) & 8;
    const int krr = (lane >> 1) & 8;
    const int kdd = lane & 8;

    // Q fragments (A-operand, row-major)
    unsigned qf[4][4];
#pragma unroll
    for (int dsi = 0; dsi < 4; dsi++)
        ldsm4(qf[dsi], Qs + (wq + (lane & 15)) * AP + dsi * 16 + ((lane & 16) >> 1));

    float oacc[8][4];
#pragma unroll
    for (int j = 0; j < 8; j++)
#pragma unroll
        for (int l = 0; l < 4; l++) oacc[j][l] = 0.f;

    // ---- O = Q * P_prev (hi-only) ----
#pragma unroll
    for (int dsi = 0; dsi < 4; dsi++) {
        const int ds = dsi * 16;
        unsigned phf[4][4];
#pragma unroll
        for (int np = 0; np < 4; np++)
            ldsm4t(phf[np], Ph + (ds + vrr) * AP + np * 16 + vcc);
#pragma unroll
        for (int nt = 0; nt < 8; nt++)
            mma16816(oacc[nt], qf[dsi][0], qf[dsi][1], qf[dsi][2], qf[dsi][3],
                     phf[nt >> 1][(nt & 1) * 2], phf[nt >> 1][(nt & 1) * 2 + 1]);
    }

    // ---- S = Q K^T (intra-chunk) ----
    float sacc[8][4];
#pragma unroll
    for (int j = 0; j < 8; j++)
#pragma unroll
        for (int l = 0; l < 4; l++) sacc[j][l] = 0.f;

#pragma unroll
    for (int dsi = 0; dsi < 4; dsi++) {
        const int ds = dsi * 16;
        unsigned kf[4][4];
#pragma unroll
        for (int np = 0; np < 4; np++)
            ldsm4(kf[np], Ks + (np * 16 + krr + (lane & 7)) * AP + ds + kdd);
#pragma unroll
        for (int nt = 0; nt < 8; nt++)
            mma16816(sacc[nt], qf[dsi][0], qf[dsi][1], qf[dsi][2], qf[dsi][3],
                     kf[nt >> 1][(nt & 1) * 2], kf[nt >> 1][(nt & 1) * 2 + 1]);
    }

    // mask (local tril) + pack to A-fragments
    const int qr0 = wq + g, qr8 = qr0 + 8;
    unsigned aS[4][4];
#pragma unroll
    for (int nt = 0; nt < 8; nt++) {
        const int kc = nt * 8 + tg * 2;
        float s0 = sacc[nt][0], s1 = sacc[nt][1];
        float s2 = sacc[nt][2], s3 = sacc[nt][3];
        if (kc     > qr0) s0 = 0.f;
        if (kc + 1 > qr0) s1 = 0.f;
        if (kc     > qr8) s2 = 0.f;
        if (kc + 1 > qr8) s3 = 0.f;
        aS[nt >> 1][(nt & 1) * 2 + 0] = hpack2(s0, s1);
        aS[nt >> 1][(nt & 1) * 2 + 1] = hpack2(s2, s3);
    }

    // ---- O += S V (intra) ----
#pragma unroll
    for (int kc4 = 0; kc4 < 4; kc4++) {
        const int ks = kc4 * 16;
        unsigned vf[4][4];
#pragma unroll
        for (int np = 0; np < 4; np++)
            ldsm4t(vf[np], Vs + (ks + vrr) * AP + np * 16 + vcc);
#pragma unroll
        for (int nt = 0; nt < 8; nt++)
            mma16816(oacc[nt], aS[kc4][0], aS[kc4][1], aS[kc4][2], aS[kc4][3],
                     vf[nt >> 1][(nt & 1) * 2], vf[nt >> 1][(nt & 1) * 2 + 1]);
    }

    // write O (fp16)
    const size_t t = (size_t)b * TT + q0 + wq + g;
#pragma unroll
    for (int nt = 0; nt < 8; nt++) {
        const int c = h * DH + nt * 8 + tg * 2;
        *reinterpret_cast<unsigned*>(&aoh[t * DD + c])       = hpack2(oacc[nt][0], oacc[nt][1]);
        *reinterpret_cast<unsigned*>(&aoh[(t + 8) * DD + c]) = hpack2(oacc[nt][2], oacc[nt][3]);
    }
}

// ---------------------------------------------------------------------------
extern "C" void kernel_launch(void* const* d_in, const int* in_sizes, int n_in,
                              void* d_out, int out_size)
{
    const float* x  = (const float*)d_in[0];
    const float* W1 = (const float*)d_in[1];
    const float* b1 = (const float*)d_in[2];
    const float* W2 = (const float*)d_in[3];
    const float* b2 = (const float*)d_in[4];
    float* out = (float*)d_out;

    __half *xh, *w1h, *w2h, *kqvh, *aoh, *ph;
    float* Cc;
    cudaGetSymbolAddress((void**)&xh,  g_xh);
    cudaGetSymbolAddress((void**)&w1h, g_w1h);
    cudaGetSymbolAddress((void**)&w2h, g_w2h);
    cudaGetSymbolAddress((void**)&kqvh, g_kqvh);
    cudaGetSymbolAddress((void**)&aoh, g_aoh);
    cudaGetSymbolAddress((void**)&Cc,  g_C);
    cudaGetSymbolAddress((void**)&ph,  g_ph);

    cudaFuncSetAttribute(gemm_h<1>,
                         cudaFuncAttributeMaxDynamicSharedMemorySize, GEMM_SMEM);
    cudaFuncSetAttribute(gemm_h<0>,
                         cudaFuncAttributeMaxDynamicSharedMemorySize, GEMM_SMEM);
    cudaFuncSetAttribute(attn_chunk,
                         cudaFuncAttributeMaxDynamicSharedMemorySize, ATTC_SMEM);

    // 0) x/W1/W2 -> fp16 (single fused launch)
    {
        const int total = NX4 + NW14 + NW24;
        prep_all<<<(total + 255) / 256, 256>>>(x, W1, W2, xh, w1h, w2h);
    }
    // 1) kqv = x @ W1 + b1  (fp16 output)
    {
        dim3 grid(3 * DD / 128, MROWS / 128);
        gemm_h<1><<<grid, 128, GEMM_SMEM>>>(xh, w1h, b1, nullptr, kqvh,
                                            MROWS, 3 * DD, DD);
    }
    // 2a) per-chunk outer products C_c = K_c^T V_c
    {
        dim3 grid(NCHUNK, HH, BB);
        kv_outer<<<grid, 128>>>(kqvh, Cc);
    }
    // 2b) exclusive prefix over chunks (scalar, chip-filling grid)
    {
        dim3 grid(BB * HH, (DH * DH) / 256);
        prefix_split<<<grid, 256>>>(Cc, ph);
    }
    // 2c) O_c = Q_c P_prev + tril(Q_c K_c^T) V_c
    {
        dim3 grid(NCHUNK, HH, BB);
        attn_chunk<<<grid, 128, ATTC_SMEM>>>(kqvh, ph, aoh);
    }
    // 3) out = ao @ W2 + b2  (fp32 output)
    {
        dim3 grid(DD / 128, MROWS / 128);
        gemm_h<0><<<grid, 128, GEMM_SMEM>>>(aoh, w2h, b2, out, nullptr,
                                            MROWS, DD, DD);
    }
}